// round 2
// baseline (speedup 1.0000x reference)
#include <cuda_runtime.h>
#include <math.h>

#define B_BATCH 4096
#define HID     512
#define G4      2048   // 4*HID

// ---------------- device scratch (no allocations allowed) ----------------
__device__ float g_E[9 * G4];                 // emb @ w_ih^T + b_ih + b_hh  [9, 2048]
__device__ float g_h[2][B_BATCH * HID];       // ping-pong hidden state
__device__ float g_c[B_BATCH * HID];          // cell state
__device__ int   g_tok[B_BATCH];              // current input token per row

typedef unsigned long long ull;

__device__ __forceinline__ ull pack2same(float x){
    ull r; asm("mov.b64 %0, {%1, %1};" : "=l"(r) : "f"(x)); return r;
}
__device__ __forceinline__ float2 unpack2(ull v){
    float2 r; asm("mov.b64 {%0, %1}, %2;" : "=f"(r.x), "=f"(r.y) : "l"(v)); return r;
}
__device__ __forceinline__ ull fma2(ull a, ull b, ull c){
    ull d; asm("fma.rn.f32x2 %0, %1, %2, %3;" : "=l"(d) : "l"(a), "l"(b), "l"(c)); return d;
}
__device__ __forceinline__ float sigmoidf_(float x){ return 1.0f / (1.0f + expf(-x)); }

// ---------------- init: zero h0, c, tokens ----------------
__global__ void init_kernel(){
    int idx = blockIdx.x * blockDim.x + threadIdx.x;
    int stride = gridDim.x * blockDim.x;
    for (int i = idx; i < B_BATCH * HID; i += stride){ g_h[0][i] = 0.0f; g_c[i] = 0.0f; }
    if (idx < B_BATCH) g_tok[idx] = 0;
}

// ---------------- E = emb @ w_ih^T + b_ih + b_hh ----------------
__global__ void precompute_E(const float* __restrict__ emb,
                             const float* __restrict__ w_ih,
                             const float* __restrict__ b_ih,
                             const float* __restrict__ b_hh){
    __shared__ float er[HID];
    int t = blockIdx.y;                          // token 0..8
    int j = blockIdx.x * blockDim.x + threadIdx.x; // gate col 0..2047
    for (int k = threadIdx.x; k < HID; k += blockDim.x) er[k] = emb[t * HID + k];
    __syncthreads();
    const float* w = w_ih + (size_t)j * HID;
    float s = 0.f;
    #pragma unroll 4
    for (int k = 0; k < HID; k += 4){
        float4 wv = *(const float4*)(w + k);
        s += er[k]*wv.x + er[k+1]*wv.y + er[k+2]*wv.z + er[k+3]*wv.w;
    }
    g_E[t * G4 + j] = s + b_ih[j] + b_hh[j];
}

// ---------------- fused GEMM (h @ w_hh^T) + embedding gather + LSTM pointwise ---------
// Block tile: 128 rows x 32 h-cols -> 128 gate-cols (all 4 gates of the 32 cols).
// Threads 256 = 16 (cx: h-col pairs) x 16 (ry: 8-row groups).
// Per-thread micro-tile: 8 rows x (2 h-cols x 4 gates) via packed f32x2 FMAs.
#define BM 128
#define BH 32
#define BN 128
#define BK 16
#define NCHUNK (HID / BK)

__global__ __launch_bounds__(256, 2)
void lstm_step_kernel(const float* __restrict__ w_hh, int phase){
    __shared__ __align__(16) float As[2][BK][BM];
    __shared__ __align__(16) float Bs[2][BK][BN];
    __shared__ float Es[9][BN];
    __shared__ int toks[BM];

    const float* __restrict__ hin  = g_h[phase];
    float*       __restrict__ hout = g_h[phase ^ 1];

    int tid = threadIdx.x;
    int cx  = tid & 15;     // 0..15 -> h-cols {2cx, 2cx+1}
    int ry  = tid >> 4;     // 0..15 -> rows ry*8..ry*8+7
    int H0  = blockIdx.x * BH;
    int R0  = blockIdx.y * BM;

    if (tid < BM) toks[tid] = g_tok[R0 + tid];
    for (int idx = tid; idx < 9 * BN; idx += 256){
        int t  = idx >> 7;
        int gc = idx & 127;
        Es[t][gc] = g_E[t * G4 + (gc >> 5) * HID + H0 + (gc & 31)];
    }

    // global -> smem loader mapping (each thread: 2x float4 for A, 2x float4 for B)
    int arow = tid >> 1;                // 0..127
    int kseg = (tid & 1) << 3;          // 0 or 8
    const float* Ag = hin + (size_t)(R0 + arow) * HID + kseg;
    int gc_l = tid >> 1;                // gate-col 0..127
    const float* Bg = w_hh + (size_t)((gc_l >> 5) * HID + H0 + (gc_l & 31)) * HID + kseg;

    float4 a0 = *(const float4*)(Ag);
    float4 a1 = *(const float4*)(Ag + 4);
    float4 b0 = *(const float4*)(Bg);
    float4 b1 = *(const float4*)(Bg + 4);
    #pragma unroll
    for (int q = 0; q < 4; ++q){
        As[0][kseg + q][arow]     = ((const float*)&a0)[q];
        As[0][kseg + 4 + q][arow] = ((const float*)&a1)[q];
        Bs[0][kseg + q][gc_l]     = ((const float*)&b0)[q];
        Bs[0][kseg + 4 + q][gc_l] = ((const float*)&b1)[q];
    }
    __syncthreads();

    ull acc[8][4];
    #pragma unroll
    for (int r = 0; r < 8; ++r)
        #pragma unroll
        for (int g = 0; g < 4; ++g) acc[r][g] = 0ULL;

    for (int c = 0; c < NCHUNK; ++c){
        int cur = c & 1;
        if (c + 1 < NCHUNK){
            const float* Agn = Ag + (c + 1) * BK;
            const float* Bgn = Bg + (c + 1) * BK;
            a0 = *(const float4*)(Agn);
            a1 = *(const float4*)(Agn + 4);
            b0 = *(const float4*)(Bgn);
            b1 = *(const float4*)(Bgn + 4);
        }
        const float (*Asc)[BM] = As[cur];
        const ull* Bsc = (const ull*)&Bs[cur][0][0];   // [BK][BN/2] as f32x2 pairs
        #pragma unroll
        for (int kk = 0; kk < BK; ++kk){
            ull bp[4];
            #pragma unroll
            for (int g = 0; g < 4; ++g) bp[g] = Bsc[kk * (BN/2) + g * 16 + cx];
            #pragma unroll
            for (int r = 0; r < 8; ++r){
                ull ap = pack2same(Asc[kk][ry * 8 + r]);
                #pragma unroll
                for (int g = 0; g < 4; ++g) acc[r][g] = fma2(ap, bp[g], acc[r][g]);
            }
        }
        if (c + 1 < NCHUNK){
            int nxt = cur ^ 1;
            #pragma unroll
            for (int q = 0; q < 4; ++q){
                As[nxt][kseg + q][arow]     = ((const float*)&a0)[q];
                As[nxt][kseg + 4 + q][arow] = ((const float*)&a1)[q];
                Bs[nxt][kseg + q][gc_l]     = ((const float*)&b0)[q];
                Bs[nxt][kseg + 4 + q][gc_l] = ((const float*)&b1)[q];
            }
            __syncthreads();
        }
    }

    // epilogue: add gathered E, LSTM pointwise, write h/c
    int hc = cx << 1;
    #pragma unroll
    for (int r = 0; r < 8; ++r){
        int lrow = ry * 8 + r;
        int t = toks[lrow];
        float2 iv = unpack2(acc[r][0]);
        float2 fv = unpack2(acc[r][1]);
        float2 gv = unpack2(acc[r][2]);
        float2 ov = unpack2(acc[r][3]);
        iv.x += Es[t][hc];      iv.y += Es[t][hc + 1];
        fv.x += Es[t][32 + hc]; fv.y += Es[t][32 + hc + 1];
        gv.x += Es[t][64 + hc]; gv.y += Es[t][64 + hc + 1];
        ov.x += Es[t][96 + hc]; ov.y += Es[t][96 + hc + 1];
        size_t base = (size_t)(R0 + lrow) * HID + H0 + hc;
        float2 cold = *(const float2*)&g_c[base];
        float ix = sigmoidf_(iv.x), iy = sigmoidf_(iv.y);
        float fx = sigmoidf_(fv.x), fy = sigmoidf_(fv.y);
        float gx = tanhf(gv.x),     gy = tanhf(gv.y);
        float ox = sigmoidf_(ov.x), oy = sigmoidf_(ov.y);
        float cnx = fx * cold.x + ix * gx;
        float cny = fy * cold.y + iy * gy;
        float2 cn; cn.x = cnx; cn.y = cny;
        float2 hn; hn.x = ox * tanhf(cnx); hn.y = oy * tanhf(cny);
        *(float2*)&g_c[base]  = cn;
        *(float2*)&hout[base] = hn;
    }
}

// ---------------- decision heads + gumbel-max sampling ----------------
// One warp per batch row. k node logits (tanh-squashed) + 8 op logits.
__global__ __launch_bounds__(256)
void decide_kernel(int phase_out,
                   const float* __restrict__ wn, const float* __restrict__ bn, int k,
                   const float* __restrict__ wop, const float* __restrict__ bop,
                   const float* __restrict__ gum, int s, float* __restrict__ out){
    __shared__ float wns[5 * HID];
    __shared__ float wos[8 * HID];
    __shared__ float bns[5];
    __shared__ float bos[8];
    const float* h = g_h[phase_out];
    int tid = threadIdx.x;
    for (int idx = tid; idx < 5 * HID; idx += 256) wns[idx] = (idx < k * HID) ? wn[idx] : 0.0f;
    for (int idx = tid; idx < 8 * HID; idx += 256) wos[idx] = wop[idx];
    if (tid < 5) bns[tid] = (tid < k) ? bn[tid] : 0.0f;
    if (tid < 8) bos[tid] = bop[tid];
    __syncthreads();

    int wid = tid >> 5, lane = tid & 31;
    int b = blockIdx.x * 8 + wid;
    const float* hr = h + (size_t)b * HID;
    float dn[5] = {0,0,0,0,0};
    float dq[8] = {0,0,0,0,0,0,0,0};
    #pragma unroll
    for (int j = 0; j < 16; ++j){
        int col = lane + (j << 5);
        float hv = hr[col];
        #pragma unroll
        for (int w = 0; w < 5; ++w) dn[w] += hv * wns[w * HID + col];
        #pragma unroll
        for (int w = 0; w < 8; ++w) dq[w] += hv * wos[w * HID + col];
    }
    #pragma unroll
    for (int off = 16; off > 0; off >>= 1){
        #pragma unroll
        for (int w = 0; w < 5; ++w) dn[w] += __shfl_xor_sync(0xffffffffu, dn[w], off);
        #pragma unroll
        for (int w = 0; w < 8; ++w) dq[w] += __shfl_xor_sync(0xffffffffu, dq[w], off);
    }
    if (lane == 0){
        float l[8];
        // ---- node decision -> output row 2s ----
        for (int w = 0; w < k; ++w) l[w] = 2.5f * tanhf((dn[w] + bns[w]) * 0.2f);
        {
            const float* g0 = gum + ((size_t)(2 * s) * B_BATCH + b) * 8;
            float m = l[0]; for (int w = 1; w < k; ++w) m = fmaxf(m, l[w]);
            float sum = 0.f; for (int w = 0; w < k; ++w) sum += expf(l[w] - m);
            float lse = m + logf(sum);
            float ent = 0.f;
            for (int w = 0; w < k; ++w){ float lp = l[w] - lse; ent -= lp * expf(lp); }
            int a = 0; float best = l[0] + g0[0];
            for (int w = 1; w < k; ++w){ float v = l[w] + g0[w]; if (v > best){ best = v; a = w; } }
            int row = 2 * s;
            out[(size_t)row * B_BATCH + b]        = (float)a;
            out[(size_t)(16 + row) * B_BATCH + b] = l[a] - lse;
            out[(size_t)(32 + row) * B_BATCH + b] = ent;
        }
        // ---- op decision -> output row 2s+1, feeds next token ----
        for (int w = 0; w < 8; ++w) l[w] = (dq[w] + bos[w]) * 0.2f;
        {
            const float* g1 = gum + ((size_t)(2 * s + 1) * B_BATCH + b) * 8;
            float m = l[0]; for (int w = 1; w < 8; ++w) m = fmaxf(m, l[w]);
            float sum = 0.f; for (int w = 0; w < 8; ++w) sum += expf(l[w] - m);
            float lse = m + logf(sum);
            float ent = 0.f;
            for (int w = 0; w < 8; ++w){ float lp = l[w] - lse; ent -= lp * expf(lp); }
            int a = 0; float best = l[0] + g1[0];
            for (int w = 1; w < 8; ++w){ float v = l[w] + g1[w]; if (v > best){ best = v; a = w; } }
            int row = 2 * s + 1;
            out[(size_t)row * B_BATCH + b]        = (float)a;
            out[(size_t)(16 + row) * B_BATCH + b] = l[a] - lse;
            out[(size_t)(32 + row) * B_BATCH + b] = ent;
            g_tok[b] = a;
        }
    }
}

// ---------------- launch ----------------
extern "C" void kernel_launch(void* const* d_in, const int* in_sizes, int n_in,
                              void* d_out, int out_size){
    const float* emb  = (const float*)d_in[0];
    const float* w_ih = (const float*)d_in[1];
    const float* w_hh = (const float*)d_in[2];
    const float* b_ih = (const float*)d_in[3];
    const float* b_hh = (const float*)d_in[4];
    const float* wn[4] = {(const float*)d_in[5], (const float*)d_in[7],
                          (const float*)d_in[9], (const float*)d_in[11]};
    const float* bn[4] = {(const float*)d_in[6], (const float*)d_in[8],
                          (const float*)d_in[10], (const float*)d_in[12]};
    const float* wop = (const float*)d_in[13];
    const float* bop = (const float*)d_in[14];
    const float* gum = (const float*)d_in[15];
    float* out = (float*)d_out;

    init_kernel<<<1024, 256>>>();
    precompute_E<<<dim3(G4 / 256, 9), 256>>>(emb, w_ih, b_ih, b_hh);
    for (int s = 0; s < 8; ++s){
        int i = s >> 1;
        lstm_step_kernel<<<dim3(HID / BH, B_BATCH / BM), 256>>>(w_hh, s & 1);
        decide_kernel<<<B_BATCH / 8, 256>>>((s + 1) & 1, wn[i], bn[i], i + 2,
                                            wop + (size_t)i * 8 * HID, bop + i * 8,
                                            gum, s, out);
    }
}

// round 5
// speedup vs baseline: 1.1147x; 1.1147x over previous
#include <cuda_runtime.h>
#include <cstdint>
#include <math.h>

#define B_BATCH 4096
#define HID     512
#define G4      2048
#define BM      128       // rows per CTA
#define BN      256       // gate-cols per CTA (4 gates x 64 hidden)
#define KC      32        // K floats per chunk (128B rows)
#define NCHUNK  48        // K' = 1536 = 3 x 512, 48 chunks of 32
#define NSTG    3

// smem layout
#define STG_BYTES  49152                  // A 16KB + B 32KB
#define STG_A(s)   ((s) * STG_BYTES)
#define STG_B(s)   ((s) * STG_BYTES + 16384)
#define OFF_ES     147456                 // 3 stages end
#define ES_PITCH   260
#define OFF_TOKS   (OFF_ES + 9 * ES_PITCH * 4)
#define SMEM_TOTAL (OFF_TOKS + 512)
#define D_PITCH    264                    // D tile overlaps stage region

// ---------------- device scratch ----------------
__device__ float g_E[9 * G4];
__device__ float g_h[B_BATCH * HID];
__device__ float g_c[B_BATCH * HID];
__device__ float g_Ah[2][B_BATCH * HID];   // tf32 hi of h (ping-pong)
__device__ float g_Al[2][B_BATCH * HID];   // tf32 lo of h
__device__ float g_Bh[G4 * HID];           // permuted tf32 hi of w_hh
__device__ float g_Bl[G4 * HID];
__device__ int   g_tok[B_BATCH];

// ---------------- helpers ----------------
__device__ __forceinline__ uint32_t smem_u32(const void* p){
    uint32_t a; asm("{ .reg .u64 t; cvta.to.shared.u64 t, %1; cvt.u32.u64 %0, t; }" : "=r"(a) : "l"(p));
    return a;
}
__device__ __forceinline__ float tf32_rna(float x){
    uint32_t t; asm("cvt.rna.tf32.f32 %0, %1;" : "=r"(t) : "f"(x));
    return __uint_as_float(t);
}
__device__ __forceinline__ float sigf(float x){ return __fdividef(1.0f, 1.0f + __expf(-x)); }
__device__ __forceinline__ float tanhfa(float x){ return 2.0f * __fdividef(1.0f, 1.0f + __expf(-2.0f * x)) - 1.0f; }

#define CP16(dst, src) asm volatile("cp.async.cg.shared.global [%0], [%1], 16;" :: "r"(dst), "l"(src) : "memory")
#define CP_COMMIT()    asm volatile("cp.async.commit_group;" ::: "memory")
#define CP_WAIT1()     asm volatile("cp.async.wait_group 1;" ::: "memory")
#define CP_WAIT0()     asm volatile("cp.async.wait_group 0;" ::: "memory")

#define LDSM4(r0, r1, r2, r3, addr) \
    asm volatile("ldmatrix.sync.aligned.m8n8.x4.shared.b16 {%0,%1,%2,%3}, [%4];" \
        : "=r"(r0), "=r"(r1), "=r"(r2), "=r"(r3) : "r"(addr))

#define MMA_TF32(d, a, b) \
    asm volatile("mma.sync.aligned.m16n8k8.row.col.f32.tf32.tf32.f32 " \
        "{%0,%1,%2,%3}, {%4,%5,%6,%7}, {%8,%9}, {%0,%1,%2,%3};" \
        : "+f"((d)[0]), "+f"((d)[1]), "+f"((d)[2]), "+f"((d)[3]) \
        : "r"((a)[0]), "r"((a)[1]), "r"((a)[2]), "r"((a)[3]), "r"((b)[0]), "r"((b)[1]))

// ---------------- init ----------------
__global__ void init_kernel(){
    int idx = blockIdx.x * blockDim.x + threadIdx.x;
    int stride = gridDim.x * blockDim.x;
    for (int i = idx; i < B_BATCH * HID; i += stride){
        g_Ah[0][i] = 0.0f; g_Al[0][i] = 0.0f; g_c[i] = 0.0f;
    }
    if (idx < B_BATCH) g_tok[idx] = 0;
}

// ---------------- E = emb @ w_ih^T + b_ih + b_hh ----------------
__global__ void precompute_E(const float* __restrict__ emb, const float* __restrict__ w_ih,
                             const float* __restrict__ b_ih, const float* __restrict__ b_hh){
    __shared__ float er[HID];
    int t = blockIdx.y;
    int j = blockIdx.x * blockDim.x + threadIdx.x;
    for (int k = threadIdx.x; k < HID; k += blockDim.x) er[k] = emb[t * HID + k];
    __syncthreads();
    const float* w = w_ih + (size_t)j * HID;
    float s = 0.f;
    #pragma unroll 4
    for (int k = 0; k < HID; k += 4){
        float4 wv = *(const float4*)(w + k);
        s += er[k]*wv.x + er[k+1]*wv.y + er[k+2]*wv.z + er[k+3]*wv.w;
    }
    g_E[t * G4 + j] = s + b_ih[j] + b_hh[j];
}

// ---------------- split + permute w_hh into tile-ordered tf32 hi/lo ----------------
// dest row r = tile*256 + n (n = gate*64 + j)  <-  w_hh row gate*512 + tile*64 + j
__global__ void split_B(const float* __restrict__ w_hh){
    int r = blockIdx.x;
    int t = r >> 8, n = r & 255;
    int srow = (n >> 6) * HID + t * 64 + (n & 63);
    const float* s = w_hh + (size_t)srow * HID;
    float* dh = g_Bh + (size_t)r * HID;
    float* dl = g_Bl + (size_t)r * HID;
    for (int k = threadIdx.x; k < HID; k += blockDim.x){
        float w = s[k];
        float hi = tf32_rna(w);
        dh[k] = hi;
        dl[k] = tf32_rna(w - hi);
    }
}

// ---------------- chunk loader: global -> swizzled smem via cp.async ----------------
// K' blocks: 0:(Ahi,Bhi) 1:(Alo,Bhi) 2:(Ahi,Blo)
__device__ __forceinline__ void load_chunk(uint32_t sb, int stage, int c,
        const float* Ahi, const float* Alo, int R0, int N0, int tid){
    int blk = c >> 4;
    int kof = (c & 15) * KC;
    const float* Ap = (blk == 1) ? Alo : Ahi;
    const float* Bp = (blk == 2) ? g_Bl : g_Bh;
    uint32_t ab = sb + STG_A(stage);
    uint32_t bb = sb + STG_B(stage);
    #pragma unroll
    for (int i = 0; i < 4; ++i){
        int idx = tid + (i << 8);
        int r = idx >> 3, u = idx & 7;
        CP16(ab + r * 128 + ((u ^ (r & 7)) << 4),
             Ap + ((size_t)(R0 + r) << 9) + kof + (u << 2));
    }
    #pragma unroll
    for (int i = 0; i < 8; ++i){
        int idx = tid + (i << 8);
        int r = idx >> 3, u = idx & 7;
        CP16(bb + r * 128 + ((u ^ (r & 7)) << 4),
             Bp + ((size_t)(N0 + r) << 9) + kof + (u << 2));
    }
    CP_COMMIT();
}

// ---------------- per-step: 3xTF32 mma.sync GEMM + fused LSTM epilogue ----------------
__global__ __launch_bounds__(256, 1)
void lstm_step_mma(int sIn){
    extern __shared__ __align__(1024) char smem[];
    uint32_t sb = smem_u32(smem);
    int tid = threadIdx.x, wid = tid >> 5, lane = tid & 31;
    int bx = blockIdx.x;
    int R0 = blockIdx.y * BM;
    int N0 = bx * BN;
    int c0 = bx * 64;

    float* Es   = (float*)(smem + OFF_ES);
    int*   toks = (int*)(smem + OFF_TOKS);

    if (tid < BM) toks[tid] = g_tok[R0 + tid];
    for (int idx = tid; idx < 9 * 256; idx += 256){
        int t = idx >> 8, n = idx & 255;
        Es[t * ES_PITCH + n] = g_E[t * G4 + (n >> 6) * HID + c0 + (n & 63)];
    }

    const float* Ahi = &g_Ah[sIn][0];
    const float* Alo = &g_Al[sIn][0];
    load_chunk(sb, 0, 0, Ahi, Alo, R0, N0, tid);
    load_chunk(sb, 1, 1, Ahi, Alo, R0, N0, tid);

    // fragment address components
    int wm = wid >> 2, wn = wid & 3;        // warp tile 64x64 at (wm*64, wn*64)
    int mat = lane >> 3, r8 = lane & 7;
    int rowA[4];
    #pragma unroll
    for (int f = 0; f < 4; ++f) rowA[f] = wm * 64 + f * 16 + ((mat & 1) << 3) + r8;
    int usA = mat >> 1;
    int rowB[4];
    #pragma unroll
    for (int p = 0; p < 4; ++p) rowB[p] = wn * 64 + (p * 2 + (mat >> 1)) * 8 + r8;
    int usB = mat & 1;

    float acc[4][8][4];
    #pragma unroll
    for (int f = 0; f < 4; ++f)
        #pragma unroll
        for (int j = 0; j < 8; ++j)
            #pragma unroll
            for (int e = 0; e < 4; ++e) acc[f][j][e] = 0.0f;

    #pragma unroll 1
    for (int c = 0; c < NCHUNK; ++c){
        int stage = c % 3;
        if (c < NCHUNK - 2) CP_WAIT1(); else CP_WAIT0();
        __syncthreads();
        if (c + 2 < NCHUNK) load_chunk(sb, (c + 2) % 3, c + 2, Ahi, Alo, R0, N0, tid);

        uint32_t ab = sb + STG_A(stage);
        uint32_t bb = sb + STG_B(stage);
        #pragma unroll
        for (int s = 0; s < 4; ++s){
            int ku = s * 2;
            uint32_t a[4][4], b[8][2];
            #pragma unroll
            for (int f = 0; f < 4; ++f){
                uint32_t ad = ab + rowA[f] * 128 + (((ku + usA) ^ r8) << 4);
                LDSM4(a[f][0], a[f][1], a[f][2], a[f][3], ad);
            }
            #pragma unroll
            for (int p = 0; p < 4; ++p){
                uint32_t bd = bb + rowB[p] * 128 + (((ku + usB) ^ r8) << 4);
                LDSM4(b[2*p][0], b[2*p][1], b[2*p+1][0], b[2*p+1][1], bd);
            }
            #pragma unroll
            for (int f = 0; f < 4; ++f)
                #pragma unroll
                for (int j = 0; j < 8; ++j)
                    MMA_TF32(acc[f][j], a[f], b[j]);
        }
    }

    // ---- epilogue: registers -> smem D tile (overlaps stage buffers) ----
    __syncthreads();
    float* Ds = (float*)smem;
    #pragma unroll
    for (int f = 0; f < 4; ++f){
        int r0 = wm * 64 + f * 16 + (lane >> 2);
        #pragma unroll
        for (int j = 0; j < 8; ++j){
            int cb = wn * 64 + j * 8 + 2 * (lane & 3);
            *(float2*)&Ds[r0 * D_PITCH + cb]       = make_float2(acc[f][j][0], acc[f][j][1]);
            *(float2*)&Ds[(r0 + 8) * D_PITCH + cb] = make_float2(acc[f][j][2], acc[f][j][3]);
        }
    }
    __syncthreads();

    // ---- LSTM pointwise: thread handles (row = tid>>1, 32 hidden cols) ----
    int row  = tid >> 1;
    int j0   = (tid & 1) * 32;
    int t    = toks[row];
    const float* Ep = &Es[t * ES_PITCH];
    const float* Dr = &Ds[row * D_PITCH];
    size_t gb = ((size_t)(R0 + row) << 9) + c0;
    float* Aho = &g_Ah[sIn ^ 1][0];
    float* Alo_o = &g_Al[sIn ^ 1][0];
    #pragma unroll
    for (int jj = 0; jj < 32; jj += 4){
        int j = j0 + jj;
        float4 iv = *(const float4*)&Dr[j];
        float4 fv = *(const float4*)&Dr[64 + j];
        float4 gv = *(const float4*)&Dr[128 + j];
        float4 ov = *(const float4*)&Dr[192 + j];
        float4 cv = *(const float4*)&g_c[gb + j];
        float4 cn, hn, ah, al;
        #pragma unroll
        for (int e = 0; e < 4; ++e){
            float i_ = sigf((&iv.x)[e] + Ep[j + e]);
            float f_ = sigf((&fv.x)[e] + Ep[64 + j + e]);
            float gg = tanhfa((&gv.x)[e] + Ep[128 + j + e]);
            float o_ = sigf((&ov.x)[e] + Ep[192 + j + e]);
            float cc = f_ * ((&cv.x)[e]) + i_ * gg;
            float hh = o_ * tanhfa(cc);
            float hi = tf32_rna(hh);
            (&cn.x)[e] = cc; (&hn.x)[e] = hh;
            (&ah.x)[e] = hi; (&al.x)[e] = tf32_rna(hh - hi);
        }
        *(float4*)&g_c[gb + j]   = cn;
        *(float4*)&g_h[gb + j]   = hn;
        *(float4*)&Aho[gb + j]   = ah;
        *(float4*)&Alo_o[gb + j] = al;
    }
}

// ---------------- decision heads + gumbel-max (float4 vectorized) ----------------
__global__ __launch_bounds__(256)
void decide_kernel(const float* __restrict__ wn, const float* __restrict__ bn, int k,
                   const float* __restrict__ wop, const float* __restrict__ bop,
                   const float* __restrict__ gum, int s, float* __restrict__ out){
    __shared__ float wns[5 * HID];
    __shared__ float wos[8 * HID];
    __shared__ float bns[5], bos[8];
    int tid = threadIdx.x;
    for (int i = tid; i < 5 * HID; i += 256) wns[i] = (i < k * HID) ? wn[i] : 0.0f;
    for (int i = tid; i < 8 * HID; i += 256) wos[i] = wop[i];
    if (tid < 5) bns[tid] = (tid < k) ? bn[tid] : 0.0f;
    if (tid < 8) bos[tid] = bop[tid];
    __syncthreads();

    int wid = tid >> 5, lane = tid & 31;
    int b = blockIdx.x * 8 + wid;
    const float4* hr  = (const float4*)(g_h + (size_t)b * HID);
    const float4* wn4 = (const float4*)wns;
    const float4* wo4 = (const float4*)wos;
    float dn[5] = {0,0,0,0,0};
    float dq[8] = {0,0,0,0,0,0,0,0};
    #pragma unroll
    for (int j = 0; j < 4; ++j){
        int c4 = lane + j * 32;
        float4 hv = hr[c4];
        #pragma unroll
        for (int w = 0; w < 5; ++w){
            float4 wv = wn4[w * 128 + c4];
            dn[w] += hv.x*wv.x + hv.y*wv.y + hv.z*wv.z + hv.w*wv.w;
        }
        #pragma unroll
        for (int w = 0; w < 8; ++w){
            float4 wv = wo4[w * 128 + c4];
            dq[w] += hv.x*wv.x + hv.y*wv.y + hv.z*wv.z + hv.w*wv.w;
        }
    }
    #pragma unroll
    for (int off = 16; off > 0; off >>= 1){
        #pragma unroll
        for (int w = 0; w < 5; ++w) dn[w] += __shfl_xor_sync(0xffffffffu, dn[w], off);
        #pragma unroll
        for (int w = 0; w < 8; ++w) dq[w] += __shfl_xor_sync(0xffffffffu, dq[w], off);
    }
    if (lane == 0){
        float l[8];
        for (int w = 0; w < k; ++w) l[w] = 2.5f * tanhf((dn[w] + bns[w]) * 0.2f);
        {
            const float* g0 = gum + ((size_t)(2 * s) * B_BATCH + b) * 8;
            float m = l[0]; for (int w = 1; w < k; ++w) m = fmaxf(m, l[w]);
            float sum = 0.f; for (int w = 0; w < k; ++w) sum += expf(l[w] - m);
            float lse = m + logf(sum);
            float ent = 0.f;
            for (int w = 0; w < k; ++w){ float lp = l[w] - lse; ent -= lp * expf(lp); }
            int a = 0; float best = l[0] + g0[0];
            for (int w = 1; w < k; ++w){ float v = l[w] + g0[w]; if (v > best){ best = v; a = w; } }
            int row = 2 * s;
            out[(size_t)row * B_BATCH + b]        = (float)a;
            out[(size_t)(16 + row) * B_BATCH + b] = l[a] - lse;
            out[(size_t)(32 + row) * B_BATCH + b] = ent;
        }
        for (int w = 0; w < 8; ++w) l[w] = (dq[w] + bos[w]) * 0.2f;
        {
            const float* g1 = gum + ((size_t)(2 * s + 1) * B_BATCH + b) * 8;
            float m = l[0]; for (int w = 1; w < 8; ++w) m = fmaxf(m, l[w]);
            float sum = 0.f; for (int w = 0; w < 8; ++w) sum += expf(l[w] - m);
            float lse = m + logf(sum);
            float ent = 0.f;
            for (int w = 0; w < 8; ++w){ float lp = l[w] - lse; ent -= lp * expf(lp); }
            int a = 0; float best = l[0] + g1[0];
            for (int w = 1; w < 8; ++w){ float v = l[w] + g1[w]; if (v > best){ best = v; a = w; } }
            int row = 2 * s + 1;
            out[(size_t)row * B_BATCH + b]        = (float)a;
            out[(size_t)(16 + row) * B_BATCH + b] = l[a] - lse;
            out[(size_t)(32 + row) * B_BATCH + b] = ent;
            g_tok[b] = a;
        }
    }
}

// ---------------- launch ----------------
extern "C" void kernel_launch(void* const* d_in, const int* in_sizes, int n_in,
                              void* d_out, int out_size){
    const float* emb  = (const float*)d_in[0];
    const float* w_ih = (const float*)d_in[1];
    const float* w_hh = (const float*)d_in[2];
    const float* b_ih = (const float*)d_in[3];
    const float* b_hh = (const float*)d_in[4];
    const float* wn[4] = {(const float*)d_in[5], (const float*)d_in[7],
                          (const float*)d_in[9], (const float*)d_in[11]};
    const float* bn[4] = {(const float*)d_in[6], (const float*)d_in[8],
                          (const float*)d_in[10], (const float*)d_in[12]};
    const float* wop = (const float*)d_in[13];
    const float* bop = (const float*)d_in[14];
    const float* gum = (const float*)d_in[15];
    float* out = (float*)d_out;

    cudaFuncSetAttribute(lstm_step_mma, cudaFuncAttributeMaxDynamicSharedMemorySize, SMEM_TOTAL);

    init_kernel<<<1024, 256>>>();
    precompute_E<<<dim3(G4 / 256, 9), 256>>>(emb, w_ih, b_ih, b_hh);
    split_B<<<G4, 256>>>(w_hh);
    for (int s = 0; s < 8; ++s){
        int i = s >> 1;
        lstm_step_mma<<<dim3(G4 / BN, B_BATCH / BM), 256, SMEM_TOTAL>>>(s & 1);
        decide_kernel<<<B_BATCH / 8, 256>>>(wn[i], bn[i], i + 2,
                                            wop + (size_t)i * 8 * HID, bop + i * 8,
                                            gum, s, out);
    }
}

// round 6
// speedup vs baseline: 1.3665x; 1.2259x over previous
#include <cuda_runtime.h>
#include <cuda.h>
#include <dlfcn.h>
#include <cstdint>
#include <math.h>

#define B_BATCH 4096
#define HID     512
#define G4      2048
#define BM      128       // rows per CTA
#define BN      256       // gate-cols per CTA (4 gates x 64 hidden)
#define KC      32        // K floats per chunk (128B rows)
#define NCHUNK  16        // 512/32; each chunk runs 3 MMA combos (3xTF32 fused)

// smem layout: per stage {Ahi 16K, Alo 16K, Bhi 32K, Blo 32K} = 96KB, 2 stages
#define STG_BYTES  98304
#define STG(s)     ((s) * STG_BYTES)
#define OFF_AHI    0
#define OFF_ALO    16384
#define OFF_BHI    32768
#define OFF_BLO    65536
#define OFF_MBAR   196608
#define OFF_ES     196672
#define ES_PITCH   260
#define OFF_TOKS   (OFF_ES + 9 * ES_PITCH * 4)     // 206032
#define SMEM_TOTAL (OFF_TOKS + 512)                // 206544
#define D_PITCH    264                             // epilogue D tile overlaps stages
#define CHUNK_BYTES 98304u

// ---------------- device scratch ----------------
__device__ __align__(1024) float g_E[9 * G4];
__device__ __align__(1024) float g_h[B_BATCH * HID];
__device__ __align__(1024) float g_c[B_BATCH * HID];
__device__ __align__(1024) float g_Ah[2][B_BATCH * HID];   // tf32 hi of h (ping-pong)
__device__ __align__(1024) float g_Al[2][B_BATCH * HID];   // tf32 lo of h
__device__ __align__(1024) float g_Bh[G4 * HID];           // permuted tf32 hi of w_hh
__device__ __align__(1024) float g_Bl[G4 * HID];
__device__ int g_tok[B_BATCH];

// ---------------- helpers ----------------
__device__ __forceinline__ uint32_t smem_u32(const void* p){
    uint32_t a; asm("{ .reg .u64 t; cvta.to.shared.u64 t, %1; cvt.u32.u64 %0, t; }" : "=r"(a) : "l"(p));
    return a;
}
__device__ __forceinline__ float tf32_rna(float x){
    uint32_t t; asm("cvt.rna.tf32.f32 %0, %1;" : "=r"(t) : "f"(x));
    return __uint_as_float(t);
}
__device__ __forceinline__ float sigf(float x){ return __fdividef(1.0f, 1.0f + __expf(-x)); }
__device__ __forceinline__ float tanhfa(float x){ return 2.0f * __fdividef(1.0f, 1.0f + __expf(-2.0f * x)) - 1.0f; }

#define LDSM4(r0, r1, r2, r3, addr) \
    asm volatile("ldmatrix.sync.aligned.m8n8.x4.shared.b16 {%0,%1,%2,%3}, [%4];" \
        : "=r"(r0), "=r"(r1), "=r"(r2), "=r"(r3) : "r"(addr))

#define MMA_TF32(d, a, b) \
    asm volatile("mma.sync.aligned.m16n8k8.row.col.f32.tf32.tf32.f32 " \
        "{%0,%1,%2,%3}, {%4,%5,%6,%7}, {%8,%9}, {%0,%1,%2,%3};" \
        : "+f"((d)[0]), "+f"((d)[1]), "+f"((d)[2]), "+f"((d)[3]) \
        : "r"((a)[0]), "r"((a)[1]), "r"((a)[2]), "r"((a)[3]), "r"((b)[0]), "r"((b)[1]))

#define MBAR_INIT(mb, n) asm volatile("mbarrier.init.shared.b64 [%0], %1;" :: "r"((uint32_t)(mb)), "r"((uint32_t)(n)) : "memory")
#define MBAR_EXPECT_TX(mb, bytes) asm volatile("mbarrier.arrive.expect_tx.shared.b64 _, [%0], %1;" :: "r"((uint32_t)(mb)), "r"((uint32_t)(bytes)) : "memory")
#define MBAR_WAIT(mb, par) do { \
    uint32_t _m = (uint32_t)(mb); uint32_t _p = (uint32_t)(par); uint32_t _d; \
    asm volatile("{\n\t.reg .pred p;\n\tmbarrier.try_wait.parity.acquire.cta.shared::cta.b64 p, [%1], %2;\n\tselp.b32 %0, 1, 0, p;\n\t}" \
        : "=r"(_d) : "r"(_m), "r"(_p) : "memory"); \
    if (!_d) { \
        asm volatile("{\n\t.reg .pred P1;\n\tWL_%=:\n\tmbarrier.try_wait.parity.acquire.cta.shared::cta.b64 P1, [%0], %1, 0x989680;\n\t@P1 bra.uni WD_%=;\n\tbra.uni WL_%=;\n\tWD_%=:\n\t}" \
            :: "r"(_m), "r"(_p) : "memory"); \
    } } while (0)

#define TMA_2D(dst, map, cx, cy, mb) \
    asm volatile("cp.async.bulk.tensor.2d.shared::cta.global.tile.mbarrier::complete_tx::bytes " \
        "[%0], [%1, {%2, %3}], [%4];" \
        :: "r"((uint32_t)(dst)), "l"(map), "r"((int32_t)(cx)), "r"((int32_t)(cy)), "r"((uint32_t)(mb)) : "memory")

// ---------------- init ----------------
__global__ void init_kernel(){
    int idx = blockIdx.x * blockDim.x + threadIdx.x;
    int stride = gridDim.x * blockDim.x;
    for (int i = idx; i < B_BATCH * HID; i += stride){
        g_Ah[0][i] = 0.0f; g_Al[0][i] = 0.0f; g_c[i] = 0.0f;
    }
    if (idx < B_BATCH) g_tok[idx] = 0;
}

// ---------------- E = emb @ w_ih^T + b_ih + b_hh ----------------
__global__ void precompute_E(const float* __restrict__ emb, const float* __restrict__ w_ih,
                             const float* __restrict__ b_ih, const float* __restrict__ b_hh){
    __shared__ float er[HID];
    int t = blockIdx.y;
    int j = blockIdx.x * blockDim.x + threadIdx.x;
    for (int k = threadIdx.x; k < HID; k += blockDim.x) er[k] = emb[t * HID + k];
    __syncthreads();
    const float* w = w_ih + (size_t)j * HID;
    float s = 0.f;
    #pragma unroll 4
    for (int k = 0; k < HID; k += 4){
        float4 wv = *(const float4*)(w + k);
        s += er[k]*wv.x + er[k+1]*wv.y + er[k+2]*wv.z + er[k+3]*wv.w;
    }
    g_E[t * G4 + j] = s + b_ih[j] + b_hh[j];
}

// ---------------- split + permute w_hh into tile-ordered tf32 hi/lo ----------------
// dest row r = tile*256 + n (n = gate*64 + j)  <-  w_hh row gate*512 + tile*64 + j
__global__ void split_B(const float* __restrict__ w_hh){
    int r = blockIdx.x;
    int t = r >> 8, n = r & 255;
    int srow = (n >> 6) * HID + t * 64 + (n & 63);
    const float* s = w_hh + (size_t)srow * HID;
    float* dh = g_Bh + (size_t)r * HID;
    float* dl = g_Bl + (size_t)r * HID;
    for (int k = threadIdx.x; k < HID; k += blockDim.x){
        float w = s[k];
        float hi = tf32_rna(w);
        dh[k] = hi;
        dl[k] = tf32_rna(w - hi);
    }
}

// ---------------- per-step: fused 3xTF32 mma.sync GEMM via TMA pipeline ----------------
__global__ __launch_bounds__(256, 1)
void lstm_step_tma(int sIn,
                   const __grid_constant__ CUtensorMap mAh,
                   const __grid_constant__ CUtensorMap mAl,
                   const __grid_constant__ CUtensorMap mBh,
                   const __grid_constant__ CUtensorMap mBl){
    extern __shared__ __align__(1024) char smem[];
    uint32_t sb = smem_u32(smem);
    int tid = threadIdx.x, wid = tid >> 5, lane = tid & 31;
    int bx = blockIdx.x;
    int R0 = blockIdx.y * BM;
    int N0 = bx * BN;
    int c0 = bx * 64;

    float* Es   = (float*)(smem + OFF_ES);
    int*   toks = (int*)(smem + OFF_TOKS);

    if (tid < BM) toks[tid] = g_tok[R0 + tid];
    for (int idx = tid; idx < 9 * 256; idx += 256){
        int t = idx >> 8, n = idx & 255;
        Es[t * ES_PITCH + n] = g_E[t * G4 + (n >> 6) * HID + c0 + (n & 63)];
    }

    if (tid == 0){
        MBAR_INIT(sb + OFF_MBAR, 1);
        MBAR_INIT(sb + OFF_MBAR + 8, 1);
    }
    __syncthreads();

    // issue chunks 0 and 1
    if (tid == 0){
        #pragma unroll
        for (int c = 0; c < 2; ++c){
            uint32_t mb = sb + OFF_MBAR + c * 8;
            uint32_t st = sb + STG(c);
            MBAR_EXPECT_TX(mb, CHUNK_BYTES);
            TMA_2D(st + OFF_AHI, &mAh, c * KC, R0, mb);
            TMA_2D(st + OFF_ALO, &mAl, c * KC, R0, mb);
            TMA_2D(st + OFF_BHI, &mBh, c * KC, N0, mb);
            TMA_2D(st + OFF_BLO, &mBl, c * KC, N0, mb);
        }
    }

    // fragment address components (64x64 warp tiles, verified layout)
    int wm = wid >> 2, wn = wid & 3;
    int mat = lane >> 3, r8 = lane & 7;
    int rowA[4];
    #pragma unroll
    for (int f = 0; f < 4; ++f) rowA[f] = wm * 64 + f * 16 + ((mat & 1) << 3) + r8;
    int usA = mat >> 1;
    int rowB[4];
    #pragma unroll
    for (int p = 0; p < 4; ++p) rowB[p] = wn * 64 + (p * 2 + (mat >> 1)) * 8 + r8;
    int usB = mat & 1;

    float acc[4][8][4];
    #pragma unroll
    for (int f = 0; f < 4; ++f)
        #pragma unroll
        for (int j = 0; j < 8; ++j)
            #pragma unroll
            for (int e = 0; e < 4; ++e) acc[f][j][e] = 0.0f;

    #pragma unroll 1
    for (int c = 0; c < NCHUNK; ++c){
        int stg = c & 1;
        MBAR_WAIT(sb + OFF_MBAR + stg * 8, (c >> 1) & 1);

        uint32_t ahi_b = sb + STG(stg) + OFF_AHI;
        uint32_t alo_b = sb + STG(stg) + OFF_ALO;
        uint32_t bhi_b = sb + STG(stg) + OFF_BHI;
        uint32_t blo_b = sb + STG(stg) + OFF_BLO;

        #pragma unroll
        for (int s = 0; s < 4; ++s){
            int ku = s * 2;
            uint32_t ah[4][4], bh[8][2];
            #pragma unroll
            for (int f = 0; f < 4; ++f){
                uint32_t ad = ahi_b + rowA[f] * 128 + (((ku + usA) ^ r8) << 4);
                LDSM4(ah[f][0], ah[f][1], ah[f][2], ah[f][3], ad);
            }
            #pragma unroll
            for (int p = 0; p < 4; ++p){
                uint32_t bd = bhi_b + rowB[p] * 128 + (((ku + usB) ^ r8) << 4);
                LDSM4(bh[2*p][0], bh[2*p][1], bh[2*p+1][0], bh[2*p+1][1], bd);
            }
            #pragma unroll
            for (int f = 0; f < 4; ++f)
                #pragma unroll
                for (int j = 0; j < 8; ++j)
                    MMA_TF32(acc[f][j], ah[f], bh[j]);

            // Alo x Bhi (reuse bh, load al into fresh regs)
            {
                uint32_t al[4][4];
                #pragma unroll
                for (int f = 0; f < 4; ++f){
                    uint32_t ad = alo_b + rowA[f] * 128 + (((ku + usA) ^ r8) << 4);
                    LDSM4(al[f][0], al[f][1], al[f][2], al[f][3], ad);
                }
                #pragma unroll
                for (int f = 0; f < 4; ++f)
                    #pragma unroll
                    for (int j = 0; j < 8; ++j)
                        MMA_TF32(acc[f][j], al[f], bh[j]);
            }
            // Ahi x Blo (reuse ah, load bl over bh's registers)
            {
                uint32_t bl[8][2];
                #pragma unroll
                for (int p = 0; p < 4; ++p){
                    uint32_t bd = blo_b + rowB[p] * 128 + (((ku + usB) ^ r8) << 4);
                    LDSM4(bl[2*p][0], bl[2*p][1], bl[2*p+1][0], bl[2*p+1][1], bd);
                }
                #pragma unroll
                for (int f = 0; f < 4; ++f)
                    #pragma unroll
                    for (int j = 0; j < 8; ++j)
                        MMA_TF32(acc[f][j], ah[f], bl[j]);
            }
        }

        __syncthreads();
        if (tid == 0 && c + 2 < NCHUNK){
            int cn = c + 2;
            uint32_t mb = sb + OFF_MBAR + stg * 8;
            uint32_t st = sb + STG(stg);
            MBAR_EXPECT_TX(mb, CHUNK_BYTES);
            TMA_2D(st + OFF_AHI, &mAh, cn * KC, R0, mb);
            TMA_2D(st + OFF_ALO, &mAl, cn * KC, R0, mb);
            TMA_2D(st + OFF_BHI, &mBh, cn * KC, N0, mb);
            TMA_2D(st + OFF_BLO, &mBl, cn * KC, N0, mb);
        }
    }

    // ---- epilogue: registers -> smem D tile (overlaps stage buffers) ----
    __syncthreads();
    float* Ds = (float*)smem;
    #pragma unroll
    for (int f = 0; f < 4; ++f){
        int r0 = wm * 64 + f * 16 + (lane >> 2);
        #pragma unroll
        for (int j = 0; j < 8; ++j){
            int cb = wn * 64 + j * 8 + 2 * (lane & 3);
            *(float2*)&Ds[r0 * D_PITCH + cb]       = make_float2(acc[f][j][0], acc[f][j][1]);
            *(float2*)&Ds[(r0 + 8) * D_PITCH + cb] = make_float2(acc[f][j][2], acc[f][j][3]);
        }
    }
    __syncthreads();

    // ---- LSTM pointwise ----
    int row  = tid >> 1;
    int j0   = (tid & 1) * 32;
    int t    = toks[row];
    const float* Ep = &Es[t * ES_PITCH];
    const float* Dr = &Ds[row * D_PITCH];
    size_t gb = ((size_t)(R0 + row) << 9) + c0;
    float* Aho = &g_Ah[sIn ^ 1][0];
    float* Alo_o = &g_Al[sIn ^ 1][0];
    #pragma unroll
    for (int jj = 0; jj < 32; jj += 4){
        int j = j0 + jj;
        float4 iv = *(const float4*)&Dr[j];
        float4 fv = *(const float4*)&Dr[64 + j];
        float4 gv = *(const float4*)&Dr[128 + j];
        float4 ov = *(const float4*)&Dr[192 + j];
        float4 cv = *(const float4*)&g_c[gb + j];
        float4 cn, hn, ah, al;
        #pragma unroll
        for (int e = 0; e < 4; ++e){
            float i_ = sigf((&iv.x)[e] + Ep[j + e]);
            float f_ = sigf((&fv.x)[e] + Ep[64 + j + e]);
            float gg = tanhfa((&gv.x)[e] + Ep[128 + j + e]);
            float o_ = sigf((&ov.x)[e] + Ep[192 + j + e]);
            float cc = f_ * ((&cv.x)[e]) + i_ * gg;
            float hh = o_ * tanhfa(cc);
            float hi = tf32_rna(hh);
            (&cn.x)[e] = cc; (&hn.x)[e] = hh;
            (&ah.x)[e] = hi; (&al.x)[e] = tf32_rna(hh - hi);
        }
        *(float4*)&g_c[gb + j]   = cn;
        *(float4*)&g_h[gb + j]   = hn;
        *(float4*)&Aho[gb + j]   = ah;
        *(float4*)&Alo_o[gb + j] = al;
    }
}

// ---------------- decision heads + gumbel-max (float4 vectorized) ----------------
__global__ __launch_bounds__(256)
void decide_kernel(const float* __restrict__ wn, const float* __restrict__ bn, int k,
                   const float* __restrict__ wop, const float* __restrict__ bop,
                   const float* __restrict__ gum, int s, float* __restrict__ out){
    __shared__ float wns[5 * HID];
    __shared__ float wos[8 * HID];
    __shared__ float bns[5], bos[8];
    int tid = threadIdx.x;
    for (int i = tid; i < 5 * HID; i += 256) wns[i] = (i < k * HID) ? wn[i] : 0.0f;
    for (int i = tid; i < 8 * HID; i += 256) wos[i] = wop[i];
    if (tid < 5) bns[tid] = (tid < k) ? bn[tid] : 0.0f;
    if (tid < 8) bos[tid] = bop[tid];
    __syncthreads();

    int wid = tid >> 5, lane = tid & 31;
    int b = blockIdx.x * 8 + wid;
    const float4* hr  = (const float4*)(g_h + (size_t)b * HID);
    const float4* wn4 = (const float4*)wns;
    const float4* wo4 = (const float4*)wos;
    float dn[5] = {0,0,0,0,0};
    float dq[8] = {0,0,0,0,0,0,0,0};
    #pragma unroll
    for (int j = 0; j < 4; ++j){
        int c4 = lane + j * 32;
        float4 hv = hr[c4];
        #pragma unroll
        for (int w = 0; w < 5; ++w){
            float4 wv = wn4[w * 128 + c4];
            dn[w] += hv.x*wv.x + hv.y*wv.y + hv.z*wv.z + hv.w*wv.w;
        }
        #pragma unroll
        for (int w = 0; w < 8; ++w){
            float4 wv = wo4[w * 128 + c4];
            dq[w] += hv.x*wv.x + hv.y*wv.y + hv.z*wv.z + hv.w*wv.w;
        }
    }
    #pragma unroll
    for (int off = 16; off > 0; off >>= 1){
        #pragma unroll
        for (int w = 0; w < 5; ++w) dn[w] += __shfl_xor_sync(0xffffffffu, dn[w], off);
        #pragma unroll
        for (int w = 0; w < 8; ++w) dq[w] += __shfl_xor_sync(0xffffffffu, dq[w], off);
    }
    if (lane == 0){
        float l[8];
        for (int w = 0; w < k; ++w) l[w] = 2.5f * tanhf((dn[w] + bns[w]) * 0.2f);
        {
            const float* g0 = gum + ((size_t)(2 * s) * B_BATCH + b) * 8;
            float m = l[0]; for (int w = 1; w < k; ++w) m = fmaxf(m, l[w]);
            float sum = 0.f; for (int w = 0; w < k; ++w) sum += expf(l[w] - m);
            float lse = m + logf(sum);
            float ent = 0.f;
            for (int w = 0; w < k; ++w){ float lp = l[w] - lse; ent -= lp * expf(lp); }
            int a = 0; float best = l[0] + g0[0];
            for (int w = 1; w < k; ++w){ float v = l[w] + g0[w]; if (v > best){ best = v; a = w; } }
            int row = 2 * s;
            out[(size_t)row * B_BATCH + b]        = (float)a;
            out[(size_t)(16 + row) * B_BATCH + b] = l[a] - lse;
            out[(size_t)(32 + row) * B_BATCH + b] = ent;
        }
        for (int w = 0; w < 8; ++w) l[w] = (dq[w] + bos[w]) * 0.2f;
        {
            const float* g1 = gum + ((size_t)(2 * s + 1) * B_BATCH + b) * 8;
            float m = l[0]; for (int w = 1; w < 8; ++w) m = fmaxf(m, l[w]);
            float sum = 0.f; for (int w = 0; w < 8; ++w) sum += expf(l[w] - m);
            float lse = m + logf(sum);
            float ent = 0.f;
            for (int w = 0; w < 8; ++w){ float lp = l[w] - lse; ent -= lp * expf(lp); }
            int a = 0; float best = l[0] + g1[0];
            for (int w = 1; w < 8; ++w){ float v = l[w] + g1[w]; if (v > best){ best = v; a = w; } }
            int row = 2 * s + 1;
            out[(size_t)row * B_BATCH + b]        = (float)a;
            out[(size_t)(16 + row) * B_BATCH + b] = l[a] - lse;
            out[(size_t)(32 + row) * B_BATCH + b] = ent;
            g_tok[b] = a;
        }
    }
}

// ---------------- host: tensormap construction via dlopen(libcuda) ----------------
typedef CUresult (*EncodeTiledFn)(CUtensorMap*, CUtensorMapDataType, cuuint32_t, void*,
                                  const cuuint64_t*, const cuuint64_t*, const cuuint32_t*,
                                  const cuuint32_t*, CUtensorMapInterleave, CUtensorMapSwizzle,
                                  CUtensorMapL2promotion, CUtensorMapFloatOOBfill);

static EncodeTiledFn get_encoder(){
    void* h = dlopen("libcuda.so.1", RTLD_LAZY | RTLD_GLOBAL);
    if (!h) h = dlopen("libcuda.so", RTLD_LAZY | RTLD_GLOBAL);
    if (!h) return nullptr;
    return (EncodeTiledFn)dlsym(h, "cuTensorMapEncodeTiled");
}

static void make_map(EncodeTiledFn enc, CUtensorMap* m, void* base,
                     uint64_t rows, uint32_t box_rows){
    cuuint64_t dims[2]    = {(cuuint64_t)HID, (cuuint64_t)rows};
    cuuint64_t strides[1] = {(cuuint64_t)HID * 4};
    cuuint32_t box[2]     = {KC, box_rows};
    cuuint32_t es[2]      = {1, 1};
    enc(m, CU_TENSOR_MAP_DATA_TYPE_FLOAT32, 2, base, dims, strides, box, es,
        CU_TENSOR_MAP_INTERLEAVE_NONE, CU_TENSOR_MAP_SWIZZLE_128B,
        CU_TENSOR_MAP_L2_PROMOTION_L2_128B, CU_TENSOR_MAP_FLOAT_OOB_FILL_NONE);
}

// ---------------- launch ----------------
extern "C" void kernel_launch(void* const* d_in, const int* in_sizes, int n_in,
                              void* d_out, int out_size){
    const float* emb  = (const float*)d_in[0];
    const float* w_ih = (const float*)d_in[1];
    const float* w_hh = (const float*)d_in[2];
    const float* b_ih = (const float*)d_in[3];
    const float* b_hh = (const float*)d_in[4];
    const float* wn[4] = {(const float*)d_in[5], (const float*)d_in[7],
                          (const float*)d_in[9], (const float*)d_in[11]};
    const float* bn[4] = {(const float*)d_in[6], (const float*)d_in[8],
                          (const float*)d_in[10], (const float*)d_in[12]};
    const float* wop = (const float*)d_in[13];
    const float* bop = (const float*)d_in[14];
    const float* gum = (const float*)d_in[15];
    float* out = (float*)d_out;

    // tensormaps (host-side, no stream ops; rebuilt every call, deterministic)
    EncodeTiledFn enc = get_encoder();
    void *pAh, *pAl, *pBh, *pBl;
    cudaGetSymbolAddress(&pAh, g_Ah);
    cudaGetSymbolAddress(&pAl, g_Al);
    cudaGetSymbolAddress(&pBh, g_Bh);
    cudaGetSymbolAddress(&pBl, g_Bl);
    CUtensorMap mAh[2], mAl[2], mBh, mBl;
    size_t buf = (size_t)B_BATCH * HID * 4;
    make_map(enc, &mAh[0], (char*)pAh,       B_BATCH, BM);
    make_map(enc, &mAh[1], (char*)pAh + buf, B_BATCH, BM);
    make_map(enc, &mAl[0], (char*)pAl,       B_BATCH, BM);
    make_map(enc, &mAl[1], (char*)pAl + buf, B_BATCH, BM);
    make_map(enc, &mBh, pBh, G4, BN);
    make_map(enc, &mBl, pBl, G4, BN);

    cudaFuncSetAttribute(lstm_step_tma, cudaFuncAttributeMaxDynamicSharedMemorySize, SMEM_TOTAL);

    init_kernel<<<1024, 256>>>();
    precompute_E<<<dim3(G4 / 256, 9), 256>>>(emb, w_ih, b_ih, b_hh);
    split_B<<<G4, 256>>>(w_hh);
    for (int s = 0; s < 8; ++s){
        int i = s >> 1;
        int ping = s & 1;
        lstm_step_tma<<<dim3(G4 / BN, B_BATCH / BM), 256, SMEM_TOTAL>>>(
            ping, mAh[ping], mAl[ping], mBh, mBl);
        decide_kernel<<<B_BATCH / 8, 256>>>(wn[i], bn[i], i + 2,
                                            wop + (size_t)i * 8 * HID, bop + i * 8,
                                            gum, s, out);
    }
}

// round 7
// speedup vs baseline: 1.5671x; 1.1468x over previous
#include <cuda_runtime.h>
#include <cuda.h>
#include <dlfcn.h>
#include <cstdint>
#include <math.h>

#define B_BATCH 4096
#define HID     512
#define G4      2048
#define BM      128       // rows per CTA
#define BN      256       // gate-cols per CTA (4 gates x 64 hidden)
#define KC      32        // K floats per chunk (128B rows)
#define NCHUNK  16        // 512/32; each chunk runs 3 MMA combos (3xTF32 fused)

// smem layout: per stage {Ahi 16K, Alo 16K, Bhi 32K, Blo 32K} = 96KB, 2 stages
#define STG_BYTES  98304
#define STG(s)     ((s) * STG_BYTES)
#define OFF_AHI    0
#define OFF_ALO    16384
#define OFF_BHI    32768
#define OFF_BLO    65536
#define OFF_MBAR   196608                          // full0, full1, empty0, empty1 (8B each)
#define OFF_ES     196672
#define ES_PITCH   260
#define OFF_TOKS   (OFF_ES + 9 * ES_PITCH * 4)     // 206032
#define SMEM_TOTAL (OFF_TOKS + 512)                // 206544
#define D_PITCH    264                             // epilogue D tile overlaps stages
#define CHUNK_BYTES 98304u

// ---------------- device scratch ----------------
__device__ __align__(1024) float g_E[9 * G4];
__device__ __align__(1024) float g_h[B_BATCH * HID];
__device__ __align__(1024) float g_c[B_BATCH * HID];
__device__ __align__(1024) float g_Ah[2][B_BATCH * HID];   // tf32 hi of h (ping-pong)
__device__ __align__(1024) float g_Al[2][B_BATCH * HID];   // tf32 lo of h
__device__ __align__(1024) float g_Bh[G4 * HID];           // permuted tf32 hi of w_hh
__device__ __align__(1024) float g_Bl[G4 * HID];
__device__ float g_r0[4 * HID];                            // step0: h, c, ah, al (one row)
__device__ int g_tok[B_BATCH];

// ---------------- helpers ----------------
__device__ __forceinline__ uint32_t smem_u32(const void* p){
    uint32_t a; asm("{ .reg .u64 t; cvta.to.shared.u64 t, %1; cvt.u32.u64 %0, t; }" : "=r"(a) : "l"(p));
    return a;
}
__device__ __forceinline__ float tf32_rna(float x){
    uint32_t t; asm("cvt.rna.tf32.f32 %0, %1;" : "=r"(t) : "f"(x));
    return __uint_as_float(t);
}
__device__ __forceinline__ float sigf(float x){ return __fdividef(1.0f, 1.0f + __expf(-x)); }
__device__ __forceinline__ float tanhfa(float x){ return 2.0f * __fdividef(1.0f, 1.0f + __expf(-2.0f * x)) - 1.0f; }

#define LDSM4(r0, r1, r2, r3, addr) \
    asm volatile("ldmatrix.sync.aligned.m8n8.x4.shared.b16 {%0,%1,%2,%3}, [%4];" \
        : "=r"(r0), "=r"(r1), "=r"(r2), "=r"(r3) : "r"(addr))

#define MMA_TF32(d, a, b) \
    asm volatile("mma.sync.aligned.m16n8k8.row.col.f32.tf32.tf32.f32 " \
        "{%0,%1,%2,%3}, {%4,%5,%6,%7}, {%8,%9}, {%0,%1,%2,%3};" \
        : "+f"((d)[0]), "+f"((d)[1]), "+f"((d)[2]), "+f"((d)[3]) \
        : "r"((a)[0]), "r"((a)[1]), "r"((a)[2]), "r"((a)[3]), "r"((b)[0]), "r"((b)[1]))

#define MBAR_INIT(mb, n) asm volatile("mbarrier.init.shared.b64 [%0], %1;" :: "r"((uint32_t)(mb)), "r"((uint32_t)(n)) : "memory")
#define MBAR_EXPECT_TX(mb, bytes) asm volatile("mbarrier.arrive.expect_tx.shared.b64 _, [%0], %1;" :: "r"((uint32_t)(mb)), "r"((uint32_t)(bytes)) : "memory")
#define MBAR_ARRIVE(mb) asm volatile("mbarrier.arrive.shared.b64 _, [%0];" :: "r"((uint32_t)(mb)) : "memory")
#define MBAR_WAIT(mb, par) do { \
    uint32_t _m = (uint32_t)(mb); uint32_t _p = (uint32_t)(par); uint32_t _d; \
    asm volatile("{\n\t.reg .pred p;\n\tmbarrier.try_wait.parity.acquire.cta.shared::cta.b64 p, [%1], %2;\n\tselp.b32 %0, 1, 0, p;\n\t}" \
        : "=r"(_d) : "r"(_m), "r"(_p) : "memory"); \
    if (!_d) { \
        asm volatile("{\n\t.reg .pred P1;\n\tWL_%=:\n\tmbarrier.try_wait.parity.acquire.cta.shared::cta.b64 P1, [%0], %1, 0x989680;\n\t@P1 bra.uni WD_%=;\n\tbra.uni WL_%=;\n\tWD_%=:\n\t}" \
            :: "r"(_m), "r"(_p) : "memory"); \
    } } while (0)

#define TMA_2D(dst, map, cx, cy, mb) \
    asm volatile("cp.async.bulk.tensor.2d.shared::cta.global.tile.mbarrier::complete_tx::bytes " \
        "[%0], [%1, {%2, %3}], [%4];" \
        :: "r"((uint32_t)(dst)), "l"(map), "r"((int32_t)(cx)), "r"((int32_t)(cy)), "r"((uint32_t)(mb)) : "memory")

// ---------------- E = emb @ w_ih^T + b_ih + b_hh ----------------
__global__ void precompute_E(const float* __restrict__ emb, const float* __restrict__ w_ih,
                             const float* __restrict__ b_ih, const float* __restrict__ b_hh){
    __shared__ float er[HID];
    int t = blockIdx.y;
    int j = blockIdx.x * blockDim.x + threadIdx.x;
    for (int k = threadIdx.x; k < HID; k += blockDim.x) er[k] = emb[t * HID + k];
    __syncthreads();
    const float* w = w_ih + (size_t)j * HID;
    float s = 0.f;
    #pragma unroll 4
    for (int k = 0; k < HID; k += 4){
        float4 wv = *(const float4*)(w + k);
        s += er[k]*wv.x + er[k+1]*wv.y + er[k+2]*wv.z + er[k+3]*wv.w;
    }
    g_E[t * G4 + j] = s + b_ih[j] + b_hh[j];
}

// ---------------- split + permute w_hh into tile-ordered tf32 hi/lo ----------------
__global__ void split_B(const float* __restrict__ w_hh){
    int r = blockIdx.x;
    int t = r >> 8, n = r & 255;
    int srow = (n >> 6) * HID + t * 64 + (n & 63);
    const float* s = w_hh + (size_t)srow * HID;
    float* dh = g_Bh + (size_t)r * HID;
    float* dl = g_Bl + (size_t)r * HID;
    for (int k = threadIdx.x; k < HID; k += blockDim.x){
        float w = s[k];
        float hi = tf32_rna(w);
        dh[k] = hi;
        dl[k] = tf32_rna(w - hi);
    }
}

// ---------------- step 0: h0=c0=0, token=0 for ALL rows -> one shared row ----------------
__global__ void step0_compute(){
    int k = threadIdx.x;                 // 512 threads
    float i_ = sigf(g_E[k]);
    float gg = tanhfa(g_E[1024 + k]);
    float o_ = sigf(g_E[1536 + k]);
    float cc = i_ * gg;                  // f*c0 + i*g with c0=0
    float hh = o_ * tanhfa(cc);
    float hi = tf32_rna(hh);
    g_r0[k]          = hh;
    g_r0[512 + k]    = cc;
    g_r0[1024 + k]   = hi;
    g_r0[1536 + k]   = tf32_rna(hh - hi);
}

__global__ void step0_bcast(){
    int idx = blockIdx.x * blockDim.x + threadIdx.x;   // 524288 threads
    int r  = idx >> 7;
    int k4 = (idx & 127) << 2;
    size_t gb = ((size_t)r << 9) + k4;
    float4 h4 = *(const float4*)&g_r0[k4];
    float4 c4 = *(const float4*)&g_r0[512 + k4];
    float4 a4 = *(const float4*)&g_r0[1024 + k4];
    float4 l4 = *(const float4*)&g_r0[1536 + k4];
    *(float4*)&g_h[gb]     = h4;
    *(float4*)&g_c[gb]     = c4;
    *(float4*)&g_Ah[1][gb] = a4;
    *(float4*)&g_Al[1][gb] = l4;
}

// ---------------- per-step: fused 3xTF32 mma.sync GEMM via TMA pipeline ----------------
__global__ __launch_bounds__(256, 1)
void lstm_step_tma(int sIn,
                   const __grid_constant__ CUtensorMap mAh,
                   const __grid_constant__ CUtensorMap mAl,
                   const __grid_constant__ CUtensorMap mBh,
                   const __grid_constant__ CUtensorMap mBl){
    extern __shared__ __align__(1024) char smem[];
    uint32_t sb = smem_u32(smem);
    int tid = threadIdx.x, wid = tid >> 5, lane = tid & 31;
    int bx = blockIdx.x;
    int R0 = blockIdx.y * BM;
    int N0 = bx * BN;
    int c0 = bx * 64;

    float* Es   = (float*)(smem + OFF_ES);
    int*   toks = (int*)(smem + OFF_TOKS);

    if (tid < BM) toks[tid] = g_tok[R0 + tid];
    for (int idx = tid; idx < 9 * 256; idx += 256){
        int t = idx >> 8, n = idx & 255;
        Es[t * ES_PITCH + n] = g_E[t * G4 + (n >> 6) * HID + c0 + (n & 63)];
    }

    uint32_t fullb  = sb + OFF_MBAR;        // full[0], full[1]
    uint32_t emptyb = sb + OFF_MBAR + 16;   // empty[0], empty[1]
    if (tid == 0){
        MBAR_INIT(fullb, 1);
        MBAR_INIT(fullb + 8, 1);
        MBAR_INIT(emptyb, 8);
        MBAR_INIT(emptyb + 8, 8);
    }
    __syncthreads();

    // prologue: issue chunks 0 and 1
    if (tid == 0){
        #pragma unroll
        for (int c = 0; c < 2; ++c){
            uint32_t mb = fullb + c * 8;
            uint32_t st = sb + STG(c);
            MBAR_EXPECT_TX(mb, CHUNK_BYTES);
            TMA_2D(st + OFF_AHI, &mAh, c * KC, R0, mb);
            TMA_2D(st + OFF_ALO, &mAl, c * KC, R0, mb);
            TMA_2D(st + OFF_BHI, &mBh, c * KC, N0, mb);
            TMA_2D(st + OFF_BLO, &mBl, c * KC, N0, mb);
        }
    }

    // fragment address components (64x64 warp tiles, verified layout)
    int wm = wid >> 2, wn = wid & 3;
    int mat = lane >> 3, r8 = lane & 7;
    int rowA[4];
    #pragma unroll
    for (int f = 0; f < 4; ++f) rowA[f] = wm * 64 + f * 16 + ((mat & 1) << 3) + r8;
    int usA = mat >> 1;
    int rowB[4];
    #pragma unroll
    for (int p = 0; p < 4; ++p) rowB[p] = wn * 64 + (p * 2 + (mat >> 1)) * 8 + r8;
    int usB = mat & 1;

    float acc[4][8][4];
    #pragma unroll
    for (int f = 0; f < 4; ++f)
        #pragma unroll
        for (int j = 0; j < 8; ++j)
            #pragma unroll
            for (int e = 0; e < 4; ++e) acc[f][j][e] = 0.0f;

    #pragma unroll 1
    for (int c = 0; c < NCHUNK; ++c){
        int stg = c & 1;
        int par = (c >> 1) & 1;
        MBAR_WAIT(fullb + stg * 8, par);

        uint32_t ahi_b = sb + STG(stg) + OFF_AHI;
        uint32_t alo_b = sb + STG(stg) + OFF_ALO;
        uint32_t bhi_b = sb + STG(stg) + OFF_BHI;
        uint32_t blo_b = sb + STG(stg) + OFF_BLO;

        #pragma unroll
        for (int s = 0; s < 4; ++s){
            int ku = s * 2;
            uint32_t ah[4][4], bh[8][2];
            #pragma unroll
            for (int f = 0; f < 4; ++f){
                uint32_t ad = ahi_b + rowA[f] * 128 + (((ku + usA) ^ r8) << 4);
                LDSM4(ah[f][0], ah[f][1], ah[f][2], ah[f][3], ad);
            }
            #pragma unroll
            for (int p = 0; p < 4; ++p){
                uint32_t bd = bhi_b + rowB[p] * 128 + (((ku + usB) ^ r8) << 4);
                LDSM4(bh[2*p][0], bh[2*p][1], bh[2*p+1][0], bh[2*p+1][1], bd);
            }
            #pragma unroll
            for (int f = 0; f < 4; ++f)
                #pragma unroll
                for (int j = 0; j < 8; ++j)
                    MMA_TF32(acc[f][j], ah[f], bh[j]);

            {   // Alo x Bhi
                uint32_t al[4][4];
                #pragma unroll
                for (int f = 0; f < 4; ++f){
                    uint32_t ad = alo_b + rowA[f] * 128 + (((ku + usA) ^ r8) << 4);
                    LDSM4(al[f][0], al[f][1], al[f][2], al[f][3], ad);
                }
                #pragma unroll
                for (int f = 0; f < 4; ++f)
                    #pragma unroll
                    for (int j = 0; j < 8; ++j)
                        MMA_TF32(acc[f][j], al[f], bh[j]);
            }
            {   // Ahi x Blo
                uint32_t bl[8][2];
                #pragma unroll
                for (int p = 0; p < 4; ++p){
                    uint32_t bd = blo_b + rowB[p] * 128 + (((ku + usB) ^ r8) << 4);
                    LDSM4(bl[2*p][0], bl[2*p][1], bl[2*p+1][0], bl[2*p+1][1], bd);
                }
                #pragma unroll
                for (int f = 0; f < 4; ++f)
                    #pragma unroll
                    for (int j = 0; j < 8; ++j)
                        MMA_TF32(acc[f][j], ah[f], bl[j]);
            }
        }

        // this warp is done reading stage stg for chunk c
        if (lane == 0) MBAR_ARRIVE(emptyb + stg * 8);
        // producer lane: once all 8 warps are done, refill stage with chunk c+2
        if (tid == 0 && c + 2 < NCHUNK){
            MBAR_WAIT(emptyb + stg * 8, par);
            int cn = c + 2;
            uint32_t mb = fullb + stg * 8;
            uint32_t st = sb + STG(stg);
            MBAR_EXPECT_TX(mb, CHUNK_BYTES);
            TMA_2D(st + OFF_AHI, &mAh, cn * KC, R0, mb);
            TMA_2D(st + OFF_ALO, &mAl, cn * KC, R0, mb);
            TMA_2D(st + OFF_BHI, &mBh, cn * KC, N0, mb);
            TMA_2D(st + OFF_BLO, &mBl, cn * KC, N0, mb);
        }
    }

    // ---- epilogue: registers -> smem D tile (overlaps stage buffers) ----
    __syncthreads();
    float* Ds = (float*)smem;
    #pragma unroll
    for (int f = 0; f < 4; ++f){
        int r0 = wm * 64 + f * 16 + (lane >> 2);
        #pragma unroll
        for (int j = 0; j < 8; ++j){
            int cb = wn * 64 + j * 8 + 2 * (lane & 3);
            *(float2*)&Ds[r0 * D_PITCH + cb]       = make_float2(acc[f][j][0], acc[f][j][1]);
            *(float2*)&Ds[(r0 + 8) * D_PITCH + cb] = make_float2(acc[f][j][2], acc[f][j][3]);
        }
    }
    __syncthreads();

    // ---- LSTM pointwise ----
    int row  = tid >> 1;
    int j0   = (tid & 1) * 32;
    int t    = toks[row];
    const float* Ep = &Es[t * ES_PITCH];
    const float* Dr = &Ds[row * D_PITCH];
    size_t gb = ((size_t)(R0 + row) << 9) + c0;
    float* Aho = &g_Ah[sIn ^ 1][0];
    float* Alo_o = &g_Al[sIn ^ 1][0];
    #pragma unroll
    for (int jj = 0; jj < 32; jj += 4){
        int j = j0 + jj;
        float4 iv = *(const float4*)&Dr[j];
        float4 fv = *(const float4*)&Dr[64 + j];
        float4 gv = *(const float4*)&Dr[128 + j];
        float4 ov = *(const float4*)&Dr[192 + j];
        float4 cv = *(const float4*)&g_c[gb + j];
        float4 cn, hn, ah, al;
        #pragma unroll
        for (int e = 0; e < 4; ++e){
            float i_ = sigf((&iv.x)[e] + Ep[j + e]);
            float f_ = sigf((&fv.x)[e] + Ep[64 + j + e]);
            float gg = tanhfa((&gv.x)[e] + Ep[128 + j + e]);
            float o_ = sigf((&ov.x)[e] + Ep[192 + j + e]);
            float cc = f_ * ((&cv.x)[e]) + i_ * gg;
            float hh = o_ * tanhfa(cc);
            float hi = tf32_rna(hh);
            (&cn.x)[e] = cc; (&hn.x)[e] = hh;
            (&ah.x)[e] = hi; (&al.x)[e] = tf32_rna(hh - hi);
        }
        *(float4*)&g_c[gb + j]   = cn;
        *(float4*)&g_h[gb + j]   = hn;
        *(float4*)&Aho[gb + j]   = ah;
        *(float4*)&Alo_o[gb + j] = al;
    }
}

// ---------------- decision heads + gumbel-max (float4 vectorized) ----------------
__global__ __launch_bounds__(256)
void decide_kernel(const float* __restrict__ wn, const float* __restrict__ bn, int k,
                   const float* __restrict__ wop, const float* __restrict__ bop,
                   const float* __restrict__ gum, int s, float* __restrict__ out){
    __shared__ float wns[5 * HID];
    __shared__ float wos[8 * HID];
    __shared__ float bns[5], bos[8];
    int tid = threadIdx.x;
    for (int i = tid; i < 5 * HID; i += 256) wns[i] = (i < k * HID) ? wn[i] : 0.0f;
    for (int i = tid; i < 8 * HID; i += 256) wos[i] = wop[i];
    if (tid < 5) bns[tid] = (tid < k) ? bn[tid] : 0.0f;
    if (tid < 8) bos[tid] = bop[tid];
    __syncthreads();

    int wid = tid >> 5, lane = tid & 31;
    int b = blockIdx.x * 8 + wid;
    const float4* hr  = (const float4*)(g_h + (size_t)b * HID);
    const float4* wn4 = (const float4*)wns;
    const float4* wo4 = (const float4*)wos;
    float dn[5] = {0,0,0,0,0};
    float dq[8] = {0,0,0,0,0,0,0,0};
    #pragma unroll
    for (int j = 0; j < 4; ++j){
        int c4 = lane + j * 32;
        float4 hv = hr[c4];
        #pragma unroll
        for (int w = 0; w < 5; ++w){
            float4 wv = wn4[w * 128 + c4];
            dn[w] += hv.x*wv.x + hv.y*wv.y + hv.z*wv.z + hv.w*wv.w;
        }
        #pragma unroll
        for (int w = 0; w < 8; ++w){
            float4 wv = wo4[w * 128 + c4];
            dq[w] += hv.x*wv.x + hv.y*wv.y + hv.z*wv.z + hv.w*wv.w;
        }
    }
    #pragma unroll
    for (int off = 16; off > 0; off >>= 1){
        #pragma unroll
        for (int w = 0; w < 5; ++w) dn[w] += __shfl_xor_sync(0xffffffffu, dn[w], off);
        #pragma unroll
        for (int w = 0; w < 8; ++w) dq[w] += __shfl_xor_sync(0xffffffffu, dq[w], off);
    }
    if (lane == 0){
        float l[8];
        for (int w = 0; w < k; ++w) l[w] = 2.5f * tanhf((dn[w] + bns[w]) * 0.2f);
        {
            const float* g0 = gum + ((size_t)(2 * s) * B_BATCH + b) * 8;
            float m = l[0]; for (int w = 1; w < k; ++w) m = fmaxf(m, l[w]);
            float sum = 0.f; for (int w = 0; w < k; ++w) sum += expf(l[w] - m);
            float lse = m + logf(sum);
            float ent = 0.f;
            for (int w = 0; w < k; ++w){ float lp = l[w] - lse; ent -= lp * expf(lp); }
            int a = 0; float best = l[0] + g0[0];
            for (int w = 1; w < k; ++w){ float v = l[w] + g0[w]; if (v > best){ best = v; a = w; } }
            int row = 2 * s;
            out[(size_t)row * B_BATCH + b]        = (float)a;
            out[(size_t)(16 + row) * B_BATCH + b] = l[a] - lse;
            out[(size_t)(32 + row) * B_BATCH + b] = ent;
        }
        for (int w = 0; w < 8; ++w) l[w] = (dq[w] + bos[w]) * 0.2f;
        {
            const float* g1 = gum + ((size_t)(2 * s + 1) * B_BATCH + b) * 8;
            float m = l[0]; for (int w = 1; w < 8; ++w) m = fmaxf(m, l[w]);
            float sum = 0.f; for (int w = 0; w < 8; ++w) sum += expf(l[w] - m);
            float lse = m + logf(sum);
            float ent = 0.f;
            for (int w = 0; w < 8; ++w){ float lp = l[w] - lse; ent -= lp * expf(lp); }
            int a = 0; float best = l[0] + g1[0];
            for (int w = 1; w < 8; ++w){ float v = l[w] + g1[w]; if (v > best){ best = v; a = w; } }
            int row = 2 * s + 1;
            out[(size_t)row * B_BATCH + b]        = (float)a;
            out[(size_t)(16 + row) * B_BATCH + b] = l[a] - lse;
            out[(size_t)(32 + row) * B_BATCH + b] = ent;
            g_tok[b] = a;
        }
    }
}

// ---------------- host: tensormap construction via dlopen(libcuda) ----------------
typedef CUresult (*EncodeTiledFn)(CUtensorMap*, CUtensorMapDataType, cuuint32_t, void*,
                                  const cuuint64_t*, const cuuint64_t*, const cuuint32_t*,
                                  const cuuint32_t*, CUtensorMapInterleave, CUtensorMapSwizzle,
                                  CUtensorMapL2promotion, CUtensorMapFloatOOBfill);

static EncodeTiledFn get_encoder(){
    void* h = dlopen("libcuda.so.1", RTLD_LAZY | RTLD_GLOBAL);
    if (!h) h = dlopen("libcuda.so", RTLD_LAZY | RTLD_GLOBAL);
    if (!h) return nullptr;
    return (EncodeTiledFn)dlsym(h, "cuTensorMapEncodeTiled");
}

static void make_map(EncodeTiledFn enc, CUtensorMap* m, void* base,
                     uint64_t rows, uint32_t box_rows){
    cuuint64_t dims[2]    = {(cuuint64_t)HID, (cuuint64_t)rows};
    cuuint64_t strides[1] = {(cuuint64_t)HID * 4};
    cuuint32_t box[2]     = {KC, box_rows};
    cuuint32_t es[2]      = {1, 1};
    enc(m, CU_TENSOR_MAP_DATA_TYPE_FLOAT32, 2, base, dims, strides, box, es,
        CU_TENSOR_MAP_INTERLEAVE_NONE, CU_TENSOR_MAP_SWIZZLE_128B,
        CU_TENSOR_MAP_L2_PROMOTION_L2_128B, CU_TENSOR_MAP_FLOAT_OOB_FILL_NONE);
}

// ---------------- launch ----------------
extern "C" void kernel_launch(void* const* d_in, const int* in_sizes, int n_in,
                              void* d_out, int out_size){
    const float* emb  = (const float*)d_in[0];
    const float* w_ih = (const float*)d_in[1];
    const float* w_hh = (const float*)d_in[2];
    const float* b_ih = (const float*)d_in[3];
    const float* b_hh = (const float*)d_in[4];
    const float* wn[4] = {(const float*)d_in[5], (const float*)d_in[7],
                          (const float*)d_in[9], (const float*)d_in[11]};
    const float* bn[4] = {(const float*)d_in[6], (const float*)d_in[8],
                          (const float*)d_in[10], (const float*)d_in[12]};
    const float* wop = (const float*)d_in[13];
    const float* bop = (const float*)d_in[14];
    const float* gum = (const float*)d_in[15];
    float* out = (float*)d_out;

    // tensormaps (host-side, no stream ops; rebuilt every call, deterministic)
    EncodeTiledFn enc = get_encoder();
    void *pAh, *pAl, *pBh, *pBl;
    cudaGetSymbolAddress(&pAh, g_Ah);
    cudaGetSymbolAddress(&pAl, g_Al);
    cudaGetSymbolAddress(&pBh, g_Bh);
    cudaGetSymbolAddress(&pBl, g_Bl);
    CUtensorMap mAh[2], mAl[2], mBh, mBl;
    size_t buf = (size_t)B_BATCH * HID * 4;
    make_map(enc, &mAh[0], (char*)pAh,       B_BATCH, BM);
    make_map(enc, &mAh[1], (char*)pAh + buf, B_BATCH, BM);
    make_map(enc, &mAl[0], (char*)pAl,       B_BATCH, BM);
    make_map(enc, &mAl[1], (char*)pAl + buf, B_BATCH, BM);
    make_map(enc, &mBh, pBh, G4, BN);
    make_map(enc, &mBl, pBl, G4, BN);

    cudaFuncSetAttribute(lstm_step_tma, cudaFuncAttributeMaxDynamicSharedMemorySize, SMEM_TOTAL);

    precompute_E<<<dim3(G4 / 256, 9), 256>>>(emb, w_ih, b_ih, b_hh);
    split_B<<<G4, 256>>>(w_hh);

    // step 0: all rows share token 0 and h0=c0=0 -> one row computed, broadcast
    step0_compute<<<1, 512>>>();
    step0_bcast<<<2048, 256>>>();
    decide_kernel<<<B_BATCH / 8, 256>>>(wn[0], bn[0], 2,
                                        wop, bop, gum, 0, out);

    for (int s = 1; s < 8; ++s){
        int i = s >> 1;
        int ping = s & 1;
        lstm_step_tma<<<dim3(G4 / BN, B_BATCH / BM), 256, SMEM_TOTAL>>>(
            ping, mAh[ping], mAl[ping], mBh, mBl);
        decide_kernel<<<B_BATCH / 8, 256>>>(wn[i], bn[i], i + 2,
                                            wop + (size_t)i * 8 * HID, bop + i * 8,
                                            gum, s, out);
    }
}

// round 8
// speedup vs baseline: 1.6568x; 1.0573x over previous
#include <cuda_runtime.h>
#include <cuda.h>
#include <dlfcn.h>
#include <cstdint>
#include <math.h>

#define B_BATCH 4096
#define HID     512
#define G4      2048
#define BM      128       // rows per CTA
#define BN      256       // gate-cols per CTA (4 gates x 64 hidden)
#define KC      32        // K floats per chunk (128B rows)
#define NCHUNK  16        // 512/32; each chunk runs 3 MMA combos (3xTF32 fused)

// smem layout: per stage {Ahi 16K, Alo 16K, Bhi 32K, Blo 32K} = 96KB, 2 stages
#define STG_BYTES  98304
#define STG(s)     ((s) * STG_BYTES)
#define OFF_AHI    0
#define OFF_ALO    16384
#define OFF_BHI    32768
#define OFF_BLO    65536
#define OFF_MBAR   196608                          // full0, full1, empty0, empty1 (8B each)
#define OFF_ES     196672
#define ES_PITCH   260
#define OFF_TOKS   (OFF_ES + 9 * ES_PITCH * 4)     // 206032
#define OFF_DWS    (OFF_TOKS + 512)                // 206544: decoder slice [13][64]
#define SMEM_TOTAL (OFF_DWS + 13 * 64 * 4)         // 209872
#define D_PITCH    264                             // epilogue D tile overlaps stages
#define CHUNK_BYTES 98304u

// ---------------- device scratch ----------------
__device__ __align__(1024) float g_E[9 * G4];
__device__ __align__(1024) float g_c[B_BATCH * HID];
__device__ __align__(1024) float g_Ah[2][B_BATCH * HID];   // tf32 hi of h (ping-pong)
__device__ __align__(1024) float g_Al[2][B_BATCH * HID];   // tf32 lo of h
__device__ __align__(1024) float g_Bh[G4 * HID];           // permuted tf32 hi of w_hh
__device__ __align__(1024) float g_Bl[G4 * HID];
__device__ __align__(1024) float g_part[8 * B_BATCH * 16]; // decision partials per col-tile
__device__ float g_r0[3 * HID];                            // step0: c, ah, al (one row)
__device__ float g_dec0[16];                               // step0 logits/lse/ent
__device__ int g_tok[B_BATCH];

// ---------------- helpers ----------------
__device__ __forceinline__ uint32_t smem_u32(const void* p){
    uint32_t a; asm("{ .reg .u64 t; cvta.to.shared.u64 t, %1; cvt.u32.u64 %0, t; }" : "=r"(a) : "l"(p));
    return a;
}
__device__ __forceinline__ float tf32_rna(float x){
    uint32_t t; asm("cvt.rna.tf32.f32 %0, %1;" : "=r"(t) : "f"(x));
    return __uint_as_float(t);
}
__device__ __forceinline__ float sigf(float x){ return __fdividef(1.0f, 1.0f + __expf(-x)); }
__device__ __forceinline__ float tanhfa(float x){ return 2.0f * __fdividef(1.0f, 1.0f + __expf(-2.0f * x)) - 1.0f; }

#define LDSM4(r0, r1, r2, r3, addr) \
    asm volatile("ldmatrix.sync.aligned.m8n8.x4.shared.b16 {%0,%1,%2,%3}, [%4];" \
        : "=r"(r0), "=r"(r1), "=r"(r2), "=r"(r3) : "r"(addr))

#define MMA_TF32(d, a, b) \
    asm volatile("mma.sync.aligned.m16n8k8.row.col.f32.tf32.tf32.f32 " \
        "{%0,%1,%2,%3}, {%4,%5,%6,%7}, {%8,%9}, {%0,%1,%2,%3};" \
        : "+f"((d)[0]), "+f"((d)[1]), "+f"((d)[2]), "+f"((d)[3]) \
        : "r"((a)[0]), "r"((a)[1]), "r"((a)[2]), "r"((a)[3]), "r"((b)[0]), "r"((b)[1]))

#define MBAR_INIT(mb, n) asm volatile("mbarrier.init.shared.b64 [%0], %1;" :: "r"((uint32_t)(mb)), "r"((uint32_t)(n)) : "memory")
#define MBAR_EXPECT_TX(mb, bytes) asm volatile("mbarrier.arrive.expect_tx.shared.b64 _, [%0], %1;" :: "r"((uint32_t)(mb)), "r"((uint32_t)(bytes)) : "memory")
#define MBAR_ARRIVE(mb) asm volatile("mbarrier.arrive.shared.b64 _, [%0];" :: "r"((uint32_t)(mb)) : "memory")
#define MBAR_WAIT(mb, par) do { \
    uint32_t _m = (uint32_t)(mb); uint32_t _p = (uint32_t)(par); uint32_t _d; \
    asm volatile("{\n\t.reg .pred p;\n\tmbarrier.try_wait.parity.acquire.cta.shared::cta.b64 p, [%1], %2;\n\tselp.b32 %0, 1, 0, p;\n\t}" \
        : "=r"(_d) : "r"(_m), "r"(_p) : "memory"); \
    if (!_d) { \
        asm volatile("{\n\t.reg .pred P1;\n\tWL_%=:\n\tmbarrier.try_wait.parity.acquire.cta.shared::cta.b64 P1, [%0], %1, 0x989680;\n\t@P1 bra.uni WD_%=;\n\tbra.uni WL_%=;\n\tWD_%=:\n\t}" \
            :: "r"(_m), "r"(_p) : "memory"); \
    } } while (0)

#define TMA_2D(dst, map, cx, cy, mb) \
    asm volatile("cp.async.bulk.tensor.2d.shared::cta.global.tile.mbarrier::complete_tx::bytes " \
        "[%0], [%1, {%2, %3}], [%4];" \
        :: "r"((uint32_t)(dst)), "l"(map), "r"((int32_t)(cx)), "r"((int32_t)(cy)), "r"((uint32_t)(mb)) : "memory")

// ---------------- E = emb @ w_ih^T + b_ih + b_hh ----------------
__global__ void precompute_E(const float* __restrict__ emb, const float* __restrict__ w_ih,
                             const float* __restrict__ b_ih, const float* __restrict__ b_hh){
    __shared__ float er[HID];
    int t = blockIdx.y;
    int j = blockIdx.x * blockDim.x + threadIdx.x;
    for (int k = threadIdx.x; k < HID; k += blockDim.x) er[k] = emb[t * HID + k];
    __syncthreads();
    const float* w = w_ih + (size_t)j * HID;
    float s = 0.f;
    #pragma unroll 4
    for (int k = 0; k < HID; k += 4){
        float4 wv = *(const float4*)(w + k);
        s += er[k]*wv.x + er[k+1]*wv.y + er[k+2]*wv.z + er[k+3]*wv.w;
    }
    g_E[t * G4 + j] = s + b_ih[j] + b_hh[j];
}

// ---------------- split + permute w_hh into tile-ordered tf32 hi/lo ----------------
__global__ void split_B(const float* __restrict__ w_hh){
    int r = blockIdx.x;
    int t = r >> 8, n = r & 255;
    int srow = (n >> 6) * HID + t * 64 + (n & 63);
    const float* s = w_hh + (size_t)srow * HID;
    float* dh = g_Bh + (size_t)r * HID;
    float* dl = g_Bl + (size_t)r * HID;
    for (int k = threadIdx.x; k < HID; k += blockDim.x){
        float w = s[k];
        float hi = tf32_rna(w);
        dh[k] = hi;
        dl[k] = tf32_rna(w - hi);
    }
}

// ---------------- step 0: one shared row + rank-1 decisions ----------------
__global__ void step0_compute(const float* __restrict__ wn2, const float* __restrict__ bn2,
                              const float* __restrict__ wop0, const float* __restrict__ bop0){
    __shared__ float sh[HID];
    __shared__ float lg[10];
    int k = threadIdx.x;                 // 512 threads
    float i_ = sigf(g_E[k]);
    float gg = tanhfa(g_E[1024 + k]);
    float o_ = sigf(g_E[1536 + k]);
    float cc = i_ * gg;                  // f*c0 + i*g with c0=0
    float hh = o_ * tanhfa(cc);
    float hi = tf32_rna(hh);
    sh[k] = hh;
    g_r0[k]          = cc;
    g_r0[512 + k]    = hi;
    g_r0[1024 + k]   = tf32_rna(hh - hi);
    __syncthreads();
    int wid = k >> 5, lane = k & 31;
    if (wid < 10){
        const float* wr = (wid < 2) ? wn2 + wid * HID : wop0 + (wid - 2) * HID;
        float s = 0.f;
        #pragma unroll
        for (int j = 0; j < 16; ++j){
            int col = lane + (j << 5);
            s += sh[col] * wr[col];
        }
        #pragma unroll
        for (int off = 16; off > 0; off >>= 1) s += __shfl_xor_sync(0xffffffffu, s, off);
        if (lane == 0) lg[wid] = s;
    }
    __syncthreads();
    if (k == 0){
        float l0[2], l1[8];
        for (int w = 0; w < 2; ++w) l0[w] = 2.5f * tanhf((lg[w] + bn2[w]) * 0.2f);
        for (int w = 0; w < 8; ++w) l1[w] = (lg[2 + w] + bop0[w]) * 0.2f;
        float m0 = fmaxf(l0[0], l0[1]);
        float s0 = expf(l0[0] - m0) + expf(l0[1] - m0);
        float lse0 = m0 + logf(s0);
        float e0 = 0.f;
        for (int w = 0; w < 2; ++w){ float lp = l0[w] - lse0; e0 -= lp * expf(lp); }
        float m1 = l1[0]; for (int w = 1; w < 8; ++w) m1 = fmaxf(m1, l1[w]);
        float s1 = 0.f; for (int w = 0; w < 8; ++w) s1 += expf(l1[w] - m1);
        float lse1 = m1 + logf(s1);
        float e1 = 0.f;
        for (int w = 0; w < 8; ++w){ float lp = l1[w] - lse1; e1 -= lp * expf(lp); }
        g_dec0[0] = l0[0]; g_dec0[1] = l0[1];
        for (int w = 0; w < 8; ++w) g_dec0[2 + w] = l1[w];
        g_dec0[10] = lse0; g_dec0[11] = lse1;
        g_dec0[12] = e0;   g_dec0[13] = e1;
    }
}

__global__ void step0_sample(const float* __restrict__ gum, float* __restrict__ out){
    int b = blockIdx.x * 256 + threadIdx.x;
    float l0[2], l1[8];
    l0[0] = g_dec0[0]; l0[1] = g_dec0[1];
    #pragma unroll
    for (int w = 0; w < 8; ++w) l1[w] = g_dec0[2 + w];
    float lse0 = g_dec0[10], lse1 = g_dec0[11];
    float e0 = g_dec0[12], e1 = g_dec0[13];
    const float* g0 = gum + (size_t)b * 8;
    const float* g1 = gum + ((size_t)B_BATCH + b) * 8;
    int a0 = (l0[1] + g0[1] > l0[0] + g0[0]) ? 1 : 0;
    out[b]                         = (float)a0;
    out[(size_t)16 * B_BATCH + b]  = l0[a0] - lse0;
    out[(size_t)32 * B_BATCH + b]  = e0;
    int a1 = 0; float best = l1[0] + g1[0];
    #pragma unroll
    for (int w = 1; w < 8; ++w){ float v = l1[w] + g1[w]; if (v > best){ best = v; a1 = w; } }
    out[(size_t)1 * B_BATCH + b]   = (float)a1;
    out[(size_t)17 * B_BATCH + b]  = l1[a1] - lse1;
    out[(size_t)33 * B_BATCH + b]  = e1;
    g_tok[b] = a1;
}

__global__ void step0_bcast(){
    int idx = blockIdx.x * blockDim.x + threadIdx.x;   // 524288 threads
    int r  = idx >> 7;
    int k4 = (idx & 127) << 2;
    size_t gb = ((size_t)r << 9) + k4;
    float4 c4 = *(const float4*)&g_r0[k4];
    float4 a4 = *(const float4*)&g_r0[512 + k4];
    float4 l4 = *(const float4*)&g_r0[1024 + k4];
    *(float4*)&g_c[gb]     = c4;
    *(float4*)&g_Ah[1][gb] = a4;
    *(float4*)&g_Al[1][gb] = l4;
}

// ---------------- per-step: fused 3xTF32 mma.sync GEMM + LSTM + decision partials ----------------
__global__ __launch_bounds__(256, 1)
void lstm_step_tma(int sIn, int kd,
                   const float* __restrict__ wnp, const float* __restrict__ wopp,
                   const __grid_constant__ CUtensorMap mAh,
                   const __grid_constant__ CUtensorMap mAl,
                   const __grid_constant__ CUtensorMap mBh,
                   const __grid_constant__ CUtensorMap mBl){
    extern __shared__ __align__(1024) char smem[];
    uint32_t sb = smem_u32(smem);
    int tid = threadIdx.x, wid = tid >> 5, lane = tid & 31;
    int bx = blockIdx.x;
    int R0 = blockIdx.y * BM;
    int N0 = bx * BN;
    int c0 = bx * 64;

    float* Es   = (float*)(smem + OFF_ES);
    int*   toks = (int*)(smem + OFF_TOKS);
    float* dws  = (float*)(smem + OFF_DWS);    // [13][64] decoder slice

    if (tid < BM) toks[tid] = g_tok[R0 + tid];
    for (int idx = tid; idx < 9 * 256; idx += 256){
        int t = idx >> 8, n = idx & 255;
        Es[t * ES_PITCH + n] = g_E[t * G4 + (n >> 6) * HID + c0 + (n & 31) + ((n >> 5) & 1) * 32];
    }
    // decoder weight slice: rows 0..4 node (pad beyond kd with 0), rows 5..12 op
    for (int idx = tid; idx < 13 * 64; idx += 256){
        int w = idx >> 6, j = idx & 63;
        float v;
        if (w < 5) v = (w < kd) ? wnp[w * HID + c0 + j] : 0.0f;
        else       v = wopp[(w - 5) * HID + c0 + j];
        dws[idx] = v;
    }

    uint32_t fullb  = sb + OFF_MBAR;        // full[0], full[1]
    uint32_t emptyb = sb + OFF_MBAR + 16;   // empty[0], empty[1]
    if (tid == 0){
        MBAR_INIT(fullb, 1);
        MBAR_INIT(fullb + 8, 1);
        MBAR_INIT(emptyb, 8);
        MBAR_INIT(emptyb + 8, 8);
    }
    __syncthreads();

    // prologue: issue chunks 0 and 1
    if (tid == 0){
        #pragma unroll
        for (int c = 0; c < 2; ++c){
            uint32_t mb = fullb + c * 8;
            uint32_t st = sb + STG(c);
            MBAR_EXPECT_TX(mb, CHUNK_BYTES);
            TMA_2D(st + OFF_AHI, &mAh, c * KC, R0, mb);
            TMA_2D(st + OFF_ALO, &mAl, c * KC, R0, mb);
            TMA_2D(st + OFF_BHI, &mBh, c * KC, N0, mb);
            TMA_2D(st + OFF_BLO, &mBl, c * KC, N0, mb);
        }
    }

    // fragment address components (64x64 warp tiles, verified layout)
    int wm = wid >> 2, wn = wid & 3;
    int mat = lane >> 3, r8 = lane & 7;
    int rowA[4];
    #pragma unroll
    for (int f = 0; f < 4; ++f) rowA[f] = wm * 64 + f * 16 + ((mat & 1) << 3) + r8;
    int usA = mat >> 1;
    int rowB[4];
    #pragma unroll
    for (int p = 0; p < 4; ++p) rowB[p] = wn * 64 + (p * 2 + (mat >> 1)) * 8 + r8;
    int usB = mat & 1;

    float acc[4][8][4];
    #pragma unroll
    for (int f = 0; f < 4; ++f)
        #pragma unroll
        for (int j = 0; j < 8; ++j)
            #pragma unroll
            for (int e = 0; e < 4; ++e) acc[f][j][e] = 0.0f;

    #pragma unroll 1
    for (int c = 0; c < NCHUNK; ++c){
        int stg = c & 1;
        int par = (c >> 1) & 1;
        MBAR_WAIT(fullb + stg * 8, par);

        uint32_t ahi_b = sb + STG(stg) + OFF_AHI;
        uint32_t alo_b = sb + STG(stg) + OFF_ALO;
        uint32_t bhi_b = sb + STG(stg) + OFF_BHI;
        uint32_t blo_b = sb + STG(stg) + OFF_BLO;

        #pragma unroll
        for (int s = 0; s < 4; ++s){
            int ku = s * 2;
            uint32_t ah[4][4], bh[8][2];
            #pragma unroll
            for (int f = 0; f < 4; ++f){
                uint32_t ad = ahi_b + rowA[f] * 128 + (((ku + usA) ^ r8) << 4);
                LDSM4(ah[f][0], ah[f][1], ah[f][2], ah[f][3], ad);
            }
            #pragma unroll
            for (int p = 0; p < 4; ++p){
                uint32_t bd = bhi_b + rowB[p] * 128 + (((ku + usB) ^ r8) << 4);
                LDSM4(bh[2*p][0], bh[2*p][1], bh[2*p+1][0], bh[2*p+1][1], bd);
            }
            #pragma unroll
            for (int f = 0; f < 4; ++f)
                #pragma unroll
                for (int j = 0; j < 8; ++j)
                    MMA_TF32(acc[f][j], ah[f], bh[j]);

            {   // Alo x Bhi
                uint32_t al[4][4];
                #pragma unroll
                for (int f = 0; f < 4; ++f){
                    uint32_t ad = alo_b + rowA[f] * 128 + (((ku + usA) ^ r8) << 4);
                    LDSM4(al[f][0], al[f][1], al[f][2], al[f][3], ad);
                }
                #pragma unroll
                for (int f = 0; f < 4; ++f)
                    #pragma unroll
                    for (int j = 0; j < 8; ++j)
                        MMA_TF32(acc[f][j], al[f], bh[j]);
            }
            {   // Ahi x Blo
                uint32_t bl[8][2];
                #pragma unroll
                for (int p = 0; p < 4; ++p){
                    uint32_t bd = blo_b + rowB[p] * 128 + (((ku + usB) ^ r8) << 4);
                    LDSM4(bl[2*p][0], bl[2*p][1], bl[2*p+1][0], bl[2*p+1][1], bd);
                }
                #pragma unroll
                for (int f = 0; f < 4; ++f)
                    #pragma unroll
                    for (int j = 0; j < 8; ++j)
                        MMA_TF32(acc[f][j], ah[f], bl[j]);
            }
        }

        // this warp is done reading stage stg for chunk c
        if (lane == 0) MBAR_ARRIVE(emptyb + stg * 8);
        // producer lane: once all 8 warps are done, refill stage with chunk c+2
        if (tid == 0 && c + 2 < NCHUNK){
            MBAR_WAIT(emptyb + stg * 8, par);
            int cn = c + 2;
            uint32_t mb = fullb + stg * 8;
            uint32_t st = sb + STG(stg);
            MBAR_EXPECT_TX(mb, CHUNK_BYTES);
            TMA_2D(st + OFF_AHI, &mAh, cn * KC, R0, mb);
            TMA_2D(st + OFF_ALO, &mAl, cn * KC, R0, mb);
            TMA_2D(st + OFF_BHI, &mBh, cn * KC, N0, mb);
            TMA_2D(st + OFF_BLO, &mBl, cn * KC, N0, mb);
        }
    }

    // ---- epilogue: registers -> smem D tile (overlaps stage buffers) ----
    __syncthreads();
    float* Ds = (float*)smem;
    #pragma unroll
    for (int f = 0; f < 4; ++f){
        int r0 = wm * 64 + f * 16 + (lane >> 2);
        #pragma unroll
        for (int j = 0; j < 8; ++j){
            int cb = wn * 64 + j * 8 + 2 * (lane & 3);
            *(float2*)&Ds[r0 * D_PITCH + cb]       = make_float2(acc[f][j][0], acc[f][j][1]);
            *(float2*)&Ds[(r0 + 8) * D_PITCH + cb] = make_float2(acc[f][j][2], acc[f][j][3]);
        }
    }
    __syncthreads();

    // ---- LSTM pointwise + decision-head partial dots ----
    int row  = tid >> 1;
    int j0   = (tid & 1) * 32;
    int t    = toks[row];
    const float* Ep = &Es[t * ES_PITCH];
    const float* Dr = &Ds[row * D_PITCH];
    size_t gb = ((size_t)(R0 + row) << 9) + c0;
    float* Aho = &g_Ah[sIn ^ 1][0];
    float* Alo_o = &g_Al[sIn ^ 1][0];
    float hbuf[32];
    #pragma unroll
    for (int jj = 0; jj < 32; jj += 4){
        int j = j0 + jj;
        float4 iv = *(const float4*)&Dr[j];
        float4 fv = *(const float4*)&Dr[64 + j];
        float4 gv = *(const float4*)&Dr[128 + j];
        float4 ov = *(const float4*)&Dr[192 + j];
        float4 cv = *(const float4*)&g_c[gb + j];
        float4 cn, ah, al;
        #pragma unroll
        for (int e = 0; e < 4; ++e){
            float i_ = sigf((&iv.x)[e] + Ep[j + e]);
            float f_ = sigf((&fv.x)[e] + Ep[64 + j + e]);
            float gg = tanhfa((&gv.x)[e] + Ep[128 + j + e]);
            float o_ = sigf((&ov.x)[e] + Ep[192 + j + e]);
            float cc = f_ * ((&cv.x)[e]) + i_ * gg;
            float hh = o_ * tanhfa(cc);
            float hi = tf32_rna(hh);
            hbuf[jj + e] = hh;
            (&cn.x)[e] = cc;
            (&ah.x)[e] = hi; (&al.x)[e] = tf32_rna(hh - hi);
        }
        *(float4*)&g_c[gb + j]   = cn;
        *(float4*)&Aho[gb + j]   = ah;
        *(float4*)&Alo_o[gb + j] = al;
    }

    // partial dots over this thread's 32 cols for 13 heads
    float pd[13];
    #pragma unroll
    for (int w = 0; w < 13; ++w) pd[w] = 0.0f;
    #pragma unroll
    for (int jj = 0; jj < 32; ++jj){
        float hv = hbuf[jj];
        const float* dc = &dws[j0 + jj];
        #pragma unroll
        for (int w = 0; w < 13; ++w) pd[w] += hv * dc[w * 64];
    }
    // combine the two half-row threads (tid, tid^1) — same warp
    #pragma unroll
    for (int w = 0; w < 13; ++w) pd[w] += __shfl_xor_sync(0xffffffffu, pd[w], 1);
    if ((tid & 1) == 0){
        float4* dst = (float4*)&g_part[((size_t)bx * B_BATCH + R0 + row) * 16];
        dst[0] = make_float4(pd[0], pd[1], pd[2], pd[3]);
        dst[1] = make_float4(pd[4], pd[5], pd[6], pd[7]);
        dst[2] = make_float4(pd[8], pd[9], pd[10], pd[11]);
        dst[3] = make_float4(pd[12], 0.f, 0.f, 0.f);
    }
}

// ---------------- finalize: sum 8 col-tile partials, softmax + gumbel-max ----------------
__global__ __launch_bounds__(256)
void finalize_kernel(const float* __restrict__ bn, int k,
                     const float* __restrict__ bop,
                     const float* __restrict__ gum, int s, float* __restrict__ out){
    int b = blockIdx.x * 256 + threadIdx.x;
    float dn[5] = {0,0,0,0,0};
    float dq[8] = {0,0,0,0,0,0,0,0};
    #pragma unroll
    for (int bx = 0; bx < 8; ++bx){
        const float4* p = (const float4*)&g_part[((size_t)bx * B_BATCH + b) * 16];
        float4 p0 = p[0], p1 = p[1], p2 = p[2], p3 = p[3];
        dn[0] += p0.x; dn[1] += p0.y; dn[2] += p0.z; dn[3] += p0.w;
        dn[4] += p1.x;
        dq[0] += p1.y; dq[1] += p1.z; dq[2] += p1.w;
        dq[3] += p2.x; dq[4] += p2.y; dq[5] += p2.z; dq[6] += p2.w;
        dq[7] += p3.x;
    }
    float l[8];
    for (int w = 0; w < k; ++w) l[w] = 2.5f * tanhf((dn[w] + bn[w]) * 0.2f);
    {
        const float* g0 = gum + ((size_t)(2 * s) * B_BATCH + b) * 8;
        float m = l[0]; for (int w = 1; w < k; ++w) m = fmaxf(m, l[w]);
        float sum = 0.f; for (int w = 0; w < k; ++w) sum += expf(l[w] - m);
        float lse = m + logf(sum);
        float ent = 0.f;
        for (int w = 0; w < k; ++w){ float lp = l[w] - lse; ent -= lp * expf(lp); }
        int a = 0; float best = l[0] + g0[0];
        for (int w = 1; w < k; ++w){ float v = l[w] + g0[w]; if (v > best){ best = v; a = w; } }
        int row = 2 * s;
        out[(size_t)row * B_BATCH + b]        = (float)a;
        out[(size_t)(16 + row) * B_BATCH + b] = l[a] - lse;
        out[(size_t)(32 + row) * B_BATCH + b] = ent;
    }
    for (int w = 0; w < 8; ++w) l[w] = (dq[w] + bop[w]) * 0.2f;
    {
        const float* g1 = gum + ((size_t)(2 * s + 1) * B_BATCH + b) * 8;
        float m = l[0]; for (int w = 1; w < 8; ++w) m = fmaxf(m, l[w]);
        float sum = 0.f; for (int w = 0; w < 8; ++w) sum += expf(l[w] - m);
        float lse = m + logf(sum);
        float ent = 0.f;
        for (int w = 0; w < 8; ++w){ float lp = l[w] - lse; ent -= lp * expf(lp); }
        int a = 0; float best = l[0] + g1[0];
        for (int w = 1; w < 8; ++w){ float v = l[w] + g1[w]; if (v > best){ best = v; a = w; } }
        int row = 2 * s + 1;
        out[(size_t)row * B_BATCH + b]        = (float)a;
        out[(size_t)(16 + row) * B_BATCH + b] = l[a] - lse;
        out[(size_t)(32 + row) * B_BATCH + b] = ent;
        g_tok[b] = a;
    }
}

// ---------------- host: tensormap construction via dlopen(libcuda) ----------------
typedef CUresult (*EncodeTiledFn)(CUtensorMap*, CUtensorMapDataType, cuuint32_t, void*,
                                  const cuuint64_t*, const cuuint64_t*, const cuuint32_t*,
                                  const cuuint32_t*, CUtensorMapInterleave, CUtensorMapSwizzle,
                                  CUtensorMapL2promotion, CUtensorMapFloatOOBfill);

static EncodeTiledFn get_encoder(){
    void* h = dlopen("libcuda.so.1", RTLD_LAZY | RTLD_GLOBAL);
    if (!h) h = dlopen("libcuda.so", RTLD_LAZY | RTLD_GLOBAL);
    if (!h) return nullptr;
    return (EncodeTiledFn)dlsym(h, "cuTensorMapEncodeTiled");
}

static void make_map(EncodeTiledFn enc, CUtensorMap* m, void* base,
                     uint64_t rows, uint32_t box_rows){
    cuuint64_t dims[2]    = {(cuuint64_t)HID, (cuuint64_t)rows};
    cuuint64_t strides[1] = {(cuuint64_t)HID * 4};
    cuuint32_t box[2]     = {KC, box_rows};
    cuuint32_t es[2]      = {1, 1};
    enc(m, CU_TENSOR_MAP_DATA_TYPE_FLOAT32, 2, base, dims, strides, box, es,
        CU_TENSOR_MAP_INTERLEAVE_NONE, CU_TENSOR_MAP_SWIZZLE_128B,
        CU_TENSOR_MAP_L2_PROMOTION_L2_128B, CU_TENSOR_MAP_FLOAT_OOB_FILL_NONE);
}

// ---------------- launch ----------------
extern "C" void kernel_launch(void* const* d_in, const int* in_sizes, int n_in,
                              void* d_out, int out_size){
    const float* emb  = (const float*)d_in[0];
    const float* w_ih = (const float*)d_in[1];
    const float* w_hh = (const float*)d_in[2];
    const float* b_ih = (const float*)d_in[3];
    const float* b_hh = (const float*)d_in[4];
    const float* wn[4] = {(const float*)d_in[5], (const float*)d_in[7],
                          (const float*)d_in[9], (const float*)d_in[11]};
    const float* bn[4] = {(const float*)d_in[6], (const float*)d_in[8],
                          (const float*)d_in[10], (const float*)d_in[12]};
    const float* wop = (const float*)d_in[13];
    const float* bop = (const float*)d_in[14];
    const float* gum = (const float*)d_in[15];
    float* out = (float*)d_out;

    // tensormaps (host-side, no stream ops; rebuilt every call, deterministic)
    EncodeTiledFn enc = get_encoder();
    void *pAh, *pAl, *pBh, *pBl;
    cudaGetSymbolAddress(&pAh, g_Ah);
    cudaGetSymbolAddress(&pAl, g_Al);
    cudaGetSymbolAddress(&pBh, g_Bh);
    cudaGetSymbolAddress(&pBl, g_Bl);
    CUtensorMap mAh[2], mAl[2], mBh, mBl;
    size_t buf = (size_t)B_BATCH * HID * 4;
    make_map(enc, &mAh[0], (char*)pAh,       B_BATCH, BM);
    make_map(enc, &mAh[1], (char*)pAh + buf, B_BATCH, BM);
    make_map(enc, &mAl[0], (char*)pAl,       B_BATCH, BM);
    make_map(enc, &mAl[1], (char*)pAl + buf, B_BATCH, BM);
    make_map(enc, &mBh, pBh, G4, BN);
    make_map(enc, &mBl, pBl, G4, BN);

    cudaFuncSetAttribute(lstm_step_tma, cudaFuncAttributeMaxDynamicSharedMemorySize, SMEM_TOTAL);

    precompute_E<<<dim3(G4 / 256, 9), 256>>>(emb, w_ih, b_ih, b_hh);
    split_B<<<G4, 256>>>(w_hh);

    // step 0: all rows share token 0 and h0=c0=0 -> one row computed, rank-1 decisions
    step0_compute<<<1, 512>>>(wn[0], bn[0], wop, bop);
    step0_sample<<<B_BATCH / 256, 256>>>(gum, out);
    step0_bcast<<<2048, 256>>>();

    for (int s = 1; s < 8; ++s){
        int i = s >> 1;
        int ping = s & 1;
        lstm_step_tma<<<dim3(G4 / BN, B_BATCH / BM), 256, SMEM_TOTAL>>>(
            ping, i + 2, wn[i], wop + (size_t)i * 8 * HID,
            mAh[ping], mAl[ping], mBh, mBl);
        finalize_kernel<<<B_BATCH / 256, 256>>>(bn[i], i + 2, bop + i * 8,
                                                gum, s, out);
    }
}

// round 10
// speedup vs baseline: 2.2036x; 1.3300x over previous
#include <cuda_runtime.h>
#include <cuda.h>
#include <dlfcn.h>
#include <cstdint>
#include <math.h>

#define B_BATCH 4096
#define HID     512
#define G4      2048
#define BM      128
#define BN      256
#define KC      32
#define NCHUNK  16

#define STG_BYTES  98304
#define STG(s)     ((s) * STG_BYTES)
#define OFF_AHI    0
#define OFF_ALO    16384
#define OFF_BHI    32768
#define OFF_BLO    65536
#define OFF_MBAR   196608
#define OFF_ES     196672
#define ES_PITCH   260
#define OFF_TOKS   (OFF_ES + 9 * ES_PITCH * 4)
#define OFF_DWS    (OFF_TOKS + 512)
#define SMEM_TOTAL (OFF_DWS + 13 * 64 * 4)
#define D_PITCH    264
#define CHUNK_BYTES 98304u

// ---------------- device scratch ----------------
__device__ __align__(1024) float g_E[9 * G4];
__device__ __align__(1024) float g_c[B_BATCH * HID];
__device__ __align__(1024) float g_Ah[2][B_BATCH * HID];
__device__ __align__(1024) float g_Al[2][B_BATCH * HID];
__device__ __align__(1024) float g_Bh[G4 * HID];
__device__ __align__(1024) float g_Bl[G4 * HID];
__device__ __align__(1024) float g_part[8 * B_BATCH * 16];
__device__ __align__(1024) float g_Hd[2][512 * HID];    // distinct h (steps 0-3)
__device__ __align__(1024) float g_Cd[2][512 * HID];    // distinct c
__device__ __align__(1024) float g_G[64 * G4];          // distinct gates pre-activation
__device__ float g_dlog[512 * 20];                      // per-key logits/lse/ent
__device__ float g_dec0[16];
__device__ int g_tok[B_BATCH];
__device__ int g_key[B_BATCH];

// ---------------- helpers ----------------
__device__ __forceinline__ uint32_t smem_u32(const void* p){
    uint32_t a; asm("{ .reg .u64 t; cvta.to.shared.u64 t, %1; cvt.u32.u64 %0, t; }" : "=r"(a) : "l"(p));
    return a;
}
__device__ __forceinline__ float tf32_rna(float x){
    uint32_t t; asm("cvt.rna.tf32.f32 %0, %1;" : "=r"(t) : "f"(x));
    return __uint_as_float(t);
}
__device__ __forceinline__ float sigf(float x){ return __fdividef(1.0f, 1.0f + __expf(-x)); }
__device__ __forceinline__ float tanhfa(float x){ return 2.0f * __fdividef(1.0f, 1.0f + __expf(-2.0f * x)) - 1.0f; }

#define LDSM4(r0, r1, r2, r3, addr) \
    asm volatile("ldmatrix.sync.aligned.m8n8.x4.shared.b16 {%0,%1,%2,%3}, [%4];" \
        : "=r"(r0), "=r"(r1), "=r"(r2), "=r"(r3) : "r"(addr))

#define MMA_TF32(d, a, b) \
    asm volatile("mma.sync.aligned.m16n8k8.row.col.f32.tf32.tf32.f32 " \
        "{%0,%1,%2,%3}, {%4,%5,%6,%7}, {%8,%9}, {%0,%1,%2,%3};" \
        : "+f"((d)[0]), "+f"((d)[1]), "+f"((d)[2]), "+f"((d)[3]) \
        : "r"((a)[0]), "r"((a)[1]), "r"((a)[2]), "r"((a)[3]), "r"((b)[0]), "r"((b)[1]))

#define MBAR_INIT(mb, n) asm volatile("mbarrier.init.shared.b64 [%0], %1;" :: "r"((uint32_t)(mb)), "r"((uint32_t)(n)) : "memory")
#define MBAR_EXPECT_TX(mb, bytes) asm volatile("mbarrier.arrive.expect_tx.shared.b64 _, [%0], %1;" :: "r"((uint32_t)(mb)), "r"((uint32_t)(bytes)) : "memory")
#define MBAR_ARRIVE(mb) asm volatile("mbarrier.arrive.shared.b64 _, [%0];" :: "r"((uint32_t)(mb)) : "memory")
#define MBAR_WAIT(mb, par) do { \
    uint32_t _m = (uint32_t)(mb); uint32_t _p = (uint32_t)(par); uint32_t _d; \
    asm volatile("{\n\t.reg .pred p;\n\tmbarrier.try_wait.parity.acquire.cta.shared::cta.b64 p, [%1], %2;\n\tselp.b32 %0, 1, 0, p;\n\t}" \
        : "=r"(_d) : "r"(_m), "r"(_p) : "memory"); \
    if (!_d) { \
        asm volatile("{\n\t.reg .pred P1;\n\tWL_%=:\n\tmbarrier.try_wait.parity.acquire.cta.shared::cta.b64 P1, [%0], %1, 0x989680;\n\t@P1 bra.uni WD_%=;\n\tbra.uni WL_%=;\n\tWD_%=:\n\t}" \
            :: "r"(_m), "r"(_p) : "memory"); \
    } } while (0)

#define TMA_2D(dst, map, cx, cy, mb) \
    asm volatile("cp.async.bulk.tensor.2d.shared::cta.global.tile.mbarrier::complete_tx::bytes " \
        "[%0], [%1, {%2, %3}], [%4];" \
        :: "r"((uint32_t)(dst)), "l"(map), "r"((int32_t)(cx)), "r"((int32_t)(cy)), "r"((uint32_t)(mb)) : "memory")

// ---------------- E = emb @ w_ih^T + b_ih + b_hh ----------------
__global__ void precompute_E(const float* __restrict__ emb, const float* __restrict__ w_ih,
                             const float* __restrict__ b_ih, const float* __restrict__ b_hh){
    __shared__ float er[HID];
    int t = blockIdx.y;
    int j = blockIdx.x * blockDim.x + threadIdx.x;
    for (int k = threadIdx.x; k < HID; k += blockDim.x) er[k] = emb[t * HID + k];
    __syncthreads();
    const float* w = w_ih + (size_t)j * HID;
    float s = 0.f;
    #pragma unroll 4
    for (int k = 0; k < HID; k += 4){
        float4 wv = *(const float4*)(w + k);
        s += er[k]*wv.x + er[k+1]*wv.y + er[k+2]*wv.z + er[k+3]*wv.w;
    }
    g_E[t * G4 + j] = s + b_ih[j] + b_hh[j];
}

// ---------------- split + permute w_hh ----------------
__global__ void split_B(const float* __restrict__ w_hh){
    int r = blockIdx.x;
    int t = r >> 8, n = r & 255;
    int srow = (n >> 6) * HID + t * 64 + (n & 63);
    const float* s = w_hh + (size_t)srow * HID;
    float* dh = g_Bh + (size_t)r * HID;
    float* dl = g_Bl + (size_t)r * HID;
    for (int k = threadIdx.x; k < HID; k += blockDim.x){
        float w = s[k];
        float hi = tf32_rna(w);
        dh[k] = hi;
        dl[k] = tf32_rna(w - hi);
    }
}

// ---------------- step 0: one shared row + rank-1 decisions ----------------
__global__ void step0_compute(const float* __restrict__ wn2, const float* __restrict__ bn2,
                              const float* __restrict__ wop0, const float* __restrict__ bop0){
    __shared__ float sh[HID];
    __shared__ float lg[10];
    int k = threadIdx.x;                 // 512 threads
    float i_ = sigf(g_E[k]);
    float gg = tanhfa(g_E[1024 + k]);
    float o_ = sigf(g_E[1536 + k]);
    float cc = i_ * gg;
    float hh = o_ * tanhfa(cc);
    sh[k] = hh;
    g_Hd[0][k] = hh;
    g_Cd[0][k] = cc;
    __syncthreads();
    int wid = k >> 5, lane = k & 31;
    if (wid < 10){
        const float* wr = (wid < 2) ? wn2 + wid * HID : wop0 + (wid - 2) * HID;
        float s = 0.f;
        #pragma unroll
        for (int j = 0; j < 16; ++j){
            int col = lane + (j << 5);
            s += sh[col] * wr[col];
        }
        #pragma unroll
        for (int off = 16; off > 0; off >>= 1) s += __shfl_xor_sync(0xffffffffu, s, off);
        if (lane == 0) lg[wid] = s;
    }
    __syncthreads();
    if (k == 0){
        float l0[2], l1[8];
        for (int w = 0; w < 2; ++w) l0[w] = 2.5f * tanhf((lg[w] + bn2[w]) * 0.2f);
        for (int w = 0; w < 8; ++w) l1[w] = (lg[2 + w] + bop0[w]) * 0.2f;
        float m0 = fmaxf(l0[0], l0[1]);
        float s0 = expf(l0[0] - m0) + expf(l0[1] - m0);
        float lse0 = m0 + logf(s0);
        float e0 = 0.f;
        for (int w = 0; w < 2; ++w){ float lp = l0[w] - lse0; e0 -= lp * expf(lp); }
        float m1 = l1[0]; for (int w = 1; w < 8; ++w) m1 = fmaxf(m1, l1[w]);
        float s1 = 0.f; for (int w = 0; w < 8; ++w) s1 += expf(l1[w] - m1);
        float lse1 = m1 + logf(s1);
        float e1 = 0.f;
        for (int w = 0; w < 8; ++w){ float lp = l1[w] - lse1; e1 -= lp * expf(lp); }
        g_dec0[0] = l0[0]; g_dec0[1] = l0[1];
        for (int w = 0; w < 8; ++w) g_dec0[2 + w] = l1[w];
        g_dec0[10] = lse0; g_dec0[11] = lse1;
        g_dec0[12] = e0;   g_dec0[13] = e1;
    }
}

__global__ void step0_sample(const float* __restrict__ gum, float* __restrict__ out){
    int b = blockIdx.x * 256 + threadIdx.x;
    float l0[2], l1[8];
    l0[0] = g_dec0[0]; l0[1] = g_dec0[1];
    #pragma unroll
    for (int w = 0; w < 8; ++w) l1[w] = g_dec0[2 + w];
    float lse0 = g_dec0[10], lse1 = g_dec0[11];
    float e0 = g_dec0[12], e1 = g_dec0[13];
    const float* g0 = gum + (size_t)b * 8;
    const float* g1 = gum + ((size_t)B_BATCH + b) * 8;
    int a0 = (l0[1] + g0[1] > l0[0] + g0[0]) ? 1 : 0;
    out[b]                         = (float)a0;
    out[(size_t)16 * B_BATCH + b]  = l0[a0] - lse0;
    out[(size_t)32 * B_BATCH + b]  = e0;
    int a1 = 0; float best = l1[0] + g1[0];
    #pragma unroll
    for (int w = 1; w < 8; ++w){ float v = l1[w] + g1[w]; if (v > best){ best = v; a1 = w; } }
    out[(size_t)1 * B_BATCH + b]   = (float)a1;
    out[(size_t)17 * B_BATCH + b]  = l1[a1] - lse1;
    out[(size_t)33 * B_BATCH + b]  = e1;
    g_key[b] = a1;
}

// ---------------- distinct-state steps 1..3 ----------------
// G[k][j] = dot(Hd[k], w_hh[j]) for Kin keys
__global__ __launch_bounds__(256)
void dstep_gemm(const float* __restrict__ w_hh, const float* __restrict__ Hd, int Kin){
    __shared__ float hs[8][HID];
    __shared__ float ws[256][17];
    int tid = threadIdx.x;
    int j0 = blockIdx.x * 256;
    int kb = blockIdx.y * 8;
    int nk = Kin - kb; if (nk > 8) nk = 8;
    for (int idx = tid; idx < nk * HID; idx += 256)
        hs[idx >> 9][idx & 511] = Hd[(size_t)(kb + (idx >> 9)) * HID + (idx & 511)];
    float acc[8] = {0,0,0,0,0,0,0,0};
    for (int kc = 0; kc < HID; kc += 16){
        __syncthreads();
        #pragma unroll
        for (int i = 0; i < 16; ++i){
            int e = tid + 256 * i;
            ws[e >> 4][e & 15] = w_hh[(size_t)(j0 + (e >> 4)) * HID + kc + (e & 15)];
        }
        __syncthreads();
        #pragma unroll
        for (int kl = 0; kl < 16; ++kl){
            float w = ws[tid][kl];
            #pragma unroll
            for (int q = 0; q < 8; ++q) acc[q] += w * hs[q][kc + kl];
        }
    }
    for (int q = 0; q < nk; ++q) g_G[(size_t)(kb + q) * G4 + j0 + tid] = acc[q];
}

// per out-key: pointwise LSTM + decision logits/lse/ent
__global__ __launch_bounds__(128)
void dstep_point(int Kin, int kd,
                 const float* __restrict__ wn, const float* __restrict__ bn,
                 const float* __restrict__ wop, const float* __restrict__ bop,
                 float* __restrict__ Hdo, float* __restrict__ Cdo,
                 const float* __restrict__ Cdi){
    __shared__ float sh[HID];
    __shared__ float hd[13];
    int kp = blockIdx.x;
    int k = kp % Kin, t = kp / Kin;
    int tid = threadIdx.x;
    const float* Gr = &g_G[(size_t)k * G4];
    const float* Er = &g_E[(size_t)t * G4];
    const float* Cr = &Cdi[(size_t)k * HID];
    #pragma unroll
    for (int e = 0; e < 4; ++e){
        int col = tid * 4 + e;
        float gi = Gr[col]        + Er[col];
        float gf = Gr[512 + col]  + Er[512 + col];
        float gg = Gr[1024 + col] + Er[1024 + col];
        float go = Gr[1536 + col] + Er[1536 + col];
        float i_ = sigf(gi), f_ = sigf(gf);
        float g_ = tanhfa(gg), o_ = sigf(go);
        float cc = f_ * Cr[col] + i_ * g_;
        float hh = o_ * tanhfa(cc);
        sh[col] = hh;
        Hdo[(size_t)kp * HID + col] = hh;
        Cdo[(size_t)kp * HID + col] = cc;
    }
    __syncthreads();
    int wid = tid >> 5, lane = tid & 31;
    for (int hx = wid; hx < 13; hx += 4){
        if (hx < 5 && hx >= kd) continue;
        const float* wr = (hx < 5) ? wn + hx * HID : wop + (hx - 5) * HID;
        float s = 0.f;
        #pragma unroll
        for (int j = 0; j < 16; ++j){
            int col = lane + (j << 5);
            s += sh[col] * wr[col];
        }
        #pragma unroll
        for (int off = 16; off > 0; off >>= 1) s += __shfl_xor_sync(0xffffffffu, s, off);
        if (lane == 0) hd[hx] = s;
    }
    __syncthreads();
    if (tid == 0){
        float* dl = &g_dlog[kp * 20];
        float ln[5], lo[8];
        for (int w = 0; w < kd; ++w) ln[w] = 2.5f * tanhf((hd[w] + bn[w]) * 0.2f);
        for (int w = 0; w < 8; ++w)  lo[w] = (hd[5 + w] + bop[w]) * 0.2f;
        float m = ln[0]; for (int w = 1; w < kd; ++w) m = fmaxf(m, ln[w]);
        float sum = 0.f; for (int w = 0; w < kd; ++w) sum += expf(ln[w] - m);
        float lse_n = m + logf(sum);
        float ent_n = 0.f;
        for (int w = 0; w < kd; ++w){ float lp = ln[w] - lse_n; ent_n -= lp * expf(lp); }
        m = lo[0]; for (int w = 1; w < 8; ++w) m = fmaxf(m, lo[w]);
        sum = 0.f; for (int w = 0; w < 8; ++w) sum += expf(lo[w] - m);
        float lse_o = m + logf(sum);
        float ent_o = 0.f;
        for (int w = 0; w < 8; ++w){ float lp = lo[w] - lse_o; ent_o -= lp * expf(lp); }
        for (int w = 0; w < kd; ++w) dl[w] = ln[w];
        for (int w = 0; w < 8; ++w)  dl[5 + w] = lo[w];
        dl[13] = lse_n; dl[14] = lse_o; dl[15] = ent_n; dl[16] = ent_o;
    }
}

// per-row sampling from distinct logits
__global__ void dsample(int s, int K, int kd, const float* __restrict__ gum, float* __restrict__ out){
    int b = blockIdx.x * 256 + threadIdx.x;
    int k = g_key[b];
    const float* dl = &g_dlog[k * 20];
    const float* g0 = gum + ((size_t)(2 * s) * B_BATCH + b) * 8;
    int a = 0; float best = dl[0] + g0[0];
    for (int w = 1; w < kd; ++w){ float v = dl[w] + g0[w]; if (v > best){ best = v; a = w; } }
    int row = 2 * s;
    out[(size_t)row * B_BATCH + b]        = (float)a;
    out[(size_t)(16 + row) * B_BATCH + b] = dl[a] - dl[13];
    out[(size_t)(32 + row) * B_BATCH + b] = dl[15];
    const float* g1 = gum + ((size_t)(2 * s + 1) * B_BATCH + b) * 8;
    a = 0; best = dl[5] + g1[0];
    #pragma unroll
    for (int w = 1; w < 8; ++w){ float v = dl[5 + w] + g1[w]; if (v > best){ best = v; a = w; } }
    row = 2 * s + 1;
    out[(size_t)row * B_BATCH + b]        = (float)a;
    out[(size_t)(16 + row) * B_BATCH + b] = dl[5 + a] - dl[14];
    out[(size_t)(32 + row) * B_BATCH + b] = dl[16];
    g_key[b] = k + K * a;
    g_tok[b] = a;
}

// materialize per-row state from distinct h4/c4 (keys 0..511 in ping 1)
__global__ void materialize(){
    int idx = blockIdx.x * blockDim.x + threadIdx.x;
    int r  = idx >> 7;
    int c4 = (idx & 127) << 2;
    int k = g_key[r] & 511;
    float4 h4 = *(const float4*)&g_Hd[1][(size_t)k * HID + c4];
    float4 cv = *(const float4*)&g_Cd[1][(size_t)k * HID + c4];
    float4 ah, al;
    #pragma unroll
    for (int e = 0; e < 4; ++e){
        float hh = (&h4.x)[e];
        float hi = tf32_rna(hh);
        (&ah.x)[e] = hi;
        (&al.x)[e] = tf32_rna(hh - hi);
    }
    size_t gb = ((size_t)r << 9) + c4;
    *(float4*)&g_c[gb]     = cv;
    *(float4*)&g_Ah[0][gb] = ah;
    *(float4*)&g_Al[0][gb] = al;
}

// ---------------- full per-row step (s=4..7): 3xTF32 MMA + LSTM + decision partials ----------------
__global__ __launch_bounds__(256, 1)
void lstm_step_tma(int sIn, int kd,
                   const float* __restrict__ wnp, const float* __restrict__ wopp,
                   const __grid_constant__ CUtensorMap mAh,
                   const __grid_constant__ CUtensorMap mAl,
                   const __grid_constant__ CUtensorMap mBh,
                   const __grid_constant__ CUtensorMap mBl){
    extern __shared__ __align__(1024) char smem[];
    uint32_t sb = smem_u32(smem);
    int tid = threadIdx.x, wid = tid >> 5, lane = tid & 31;
    int bx = blockIdx.x;
    int R0 = blockIdx.y * BM;
    int N0 = bx * BN;
    int c0 = bx * 64;

    float* Es   = (float*)(smem + OFF_ES);
    int*   toks = (int*)(smem + OFF_TOKS);
    float* dws  = (float*)(smem + OFF_DWS);

    if (tid < BM) toks[tid] = g_tok[R0 + tid];
    for (int idx = tid; idx < 9 * 256; idx += 256){
        int t = idx >> 8, n = idx & 255;
        Es[t * ES_PITCH + n] = g_E[t * G4 + (n >> 6) * HID + c0 + (n & 63)];
    }
    for (int idx = tid; idx < 13 * 64; idx += 256){
        int w = idx >> 6, j = idx & 63;
        float v;
        if (w < 5) v = (w < kd) ? wnp[w * HID + c0 + j] : 0.0f;
        else       v = wopp[(w - 5) * HID + c0 + j];
        dws[idx] = v;
    }

    uint32_t fullb  = sb + OFF_MBAR;
    uint32_t emptyb = sb + OFF_MBAR + 16;
    if (tid == 0){
        MBAR_INIT(fullb, 1);
        MBAR_INIT(fullb + 8, 1);
        MBAR_INIT(emptyb, 8);
        MBAR_INIT(emptyb + 8, 8);
    }
    __syncthreads();

    if (tid == 0){
        #pragma unroll
        for (int c = 0; c < 2; ++c){
            uint32_t mb = fullb + c * 8;
            uint32_t st = sb + STG(c);
            MBAR_EXPECT_TX(mb, CHUNK_BYTES);
            TMA_2D(st + OFF_AHI, &mAh, c * KC, R0, mb);
            TMA_2D(st + OFF_ALO, &mAl, c * KC, R0, mb);
            TMA_2D(st + OFF_BHI, &mBh, c * KC, N0, mb);
            TMA_2D(st + OFF_BLO, &mBl, c * KC, N0, mb);
        }
    }

    int wm = wid >> 2, wn = wid & 3;
    int mat = lane >> 3, r8 = lane & 7;
    int rowA[4];
    #pragma unroll
    for (int f = 0; f < 4; ++f) rowA[f] = wm * 64 + f * 16 + ((mat & 1) << 3) + r8;
    int usA = mat >> 1;
    int rowB[4];
    #pragma unroll
    for (int p = 0; p < 4; ++p) rowB[p] = wn * 64 + (p * 2 + (mat >> 1)) * 8 + r8;
    int usB = mat & 1;

    float acc[4][8][4];
    #pragma unroll
    for (int f = 0; f < 4; ++f)
        #pragma unroll
        for (int j = 0; j < 8; ++j)
            #pragma unroll
            for (int e = 0; e < 4; ++e) acc[f][j][e] = 0.0f;

    #pragma unroll 1
    for (int c = 0; c < NCHUNK; ++c){
        int stg = c & 1;
        int par = (c >> 1) & 1;
        MBAR_WAIT(fullb + stg * 8, par);

        uint32_t ahi_b = sb + STG(stg) + OFF_AHI;
        uint32_t alo_b = sb + STG(stg) + OFF_ALO;
        uint32_t bhi_b = sb + STG(stg) + OFF_BHI;
        uint32_t blo_b = sb + STG(stg) + OFF_BLO;

        #pragma unroll
        for (int s = 0; s < 4; ++s){
            int ku = s * 2;
            uint32_t ah[4][4], bh[8][2];
            #pragma unroll
            for (int f = 0; f < 4; ++f){
                uint32_t ad = ahi_b + rowA[f] * 128 + (((ku + usA) ^ r8) << 4);
                LDSM4(ah[f][0], ah[f][1], ah[f][2], ah[f][3], ad);
            }
            #pragma unroll
            for (int p = 0; p < 4; ++p){
                uint32_t bd = bhi_b + rowB[p] * 128 + (((ku + usB) ^ r8) << 4);
                LDSM4(bh[2*p][0], bh[2*p][1], bh[2*p+1][0], bh[2*p+1][1], bd);
            }
            #pragma unroll
            for (int f = 0; f < 4; ++f)
                #pragma unroll
                for (int j = 0; j < 8; ++j)
                    MMA_TF32(acc[f][j], ah[f], bh[j]);

            {
                uint32_t al[4][4];
                #pragma unroll
                for (int f = 0; f < 4; ++f){
                    uint32_t ad = alo_b + rowA[f] * 128 + (((ku + usA) ^ r8) << 4);
                    LDSM4(al[f][0], al[f][1], al[f][2], al[f][3], ad);
                }
                #pragma unroll
                for (int f = 0; f < 4; ++f)
                    #pragma unroll
                    for (int j = 0; j < 8; ++j)
                        MMA_TF32(acc[f][j], al[f], bh[j]);
            }
            {
                uint32_t bl[8][2];
                #pragma unroll
                for (int p = 0; p < 4; ++p){
                    uint32_t bd = blo_b + rowB[p] * 128 + (((ku + usB) ^ r8) << 4);
                    LDSM4(bl[2*p][0], bl[2*p][1], bl[2*p+1][0], bl[2*p+1][1], bd);
                }
                #pragma unroll
                for (int f = 0; f < 4; ++f)
                    #pragma unroll
                    for (int j = 0; j < 8; ++j)
                        MMA_TF32(acc[f][j], ah[f], bl[j]);
            }
        }

        if (lane == 0) MBAR_ARRIVE(emptyb + stg * 8);
        if (tid == 0 && c + 2 < NCHUNK){
            MBAR_WAIT(emptyb + stg * 8, par);
            int cn = c + 2;
            uint32_t mb = fullb + stg * 8;
            uint32_t st = sb + STG(stg);
            MBAR_EXPECT_TX(mb, CHUNK_BYTES);
            TMA_2D(st + OFF_AHI, &mAh, cn * KC, R0, mb);
            TMA_2D(st + OFF_ALO, &mAl, cn * KC, R0, mb);
            TMA_2D(st + OFF_BHI, &mBh, cn * KC, N0, mb);
            TMA_2D(st + OFF_BLO, &mBl, cn * KC, N0, mb);
        }
    }

    __syncthreads();
    float* Ds = (float*)smem;
    #pragma unroll
    for (int f = 0; f < 4; ++f){
        int r0 = wm * 64 + f * 16 + (lane >> 2);
        #pragma unroll
        for (int j = 0; j < 8; ++j){
            int cb = wn * 64 + j * 8 + 2 * (lane & 3);
            *(float2*)&Ds[r0 * D_PITCH + cb]       = make_float2(acc[f][j][0], acc[f][j][1]);
            *(float2*)&Ds[(r0 + 8) * D_PITCH + cb] = make_float2(acc[f][j][2], acc[f][j][3]);
        }
    }
    __syncthreads();

    int row  = tid >> 1;
    int j0   = (tid & 1) * 32;
    int t    = toks[row];
    const float* Ep = &Es[t * ES_PITCH];
    const float* Dr = &Ds[row * D_PITCH];
    size_t gb = ((size_t)(R0 + row) << 9) + c0;
    float* Aho = &g_Ah[sIn ^ 1][0];
    float* Alo_o = &g_Al[sIn ^ 1][0];
    float hbuf[32];
    #pragma unroll
    for (int jj = 0; jj < 32; jj += 4){
        int j = j0 + jj;
        float4 iv = *(const float4*)&Dr[j];
        float4 fv = *(const float4*)&Dr[64 + j];
        float4 gv = *(const float4*)&Dr[128 + j];
        float4 ov = *(const float4*)&Dr[192 + j];
        float4 cv = *(const float4*)&g_c[gb + j];
        float4 cn, ah, al;
        #pragma unroll
        for (int e = 0; e < 4; ++e){
            float i_ = sigf((&iv.x)[e] + Ep[j + e]);
            float f_ = sigf((&fv.x)[e] + Ep[64 + j + e]);
            float gg = tanhfa((&gv.x)[e] + Ep[128 + j + e]);
            float o_ = sigf((&ov.x)[e] + Ep[192 + j + e]);
            float cc = f_ * ((&cv.x)[e]) + i_ * gg;
            float hh = o_ * tanhfa(cc);
            float hi = tf32_rna(hh);
            hbuf[jj + e] = hh;
            (&cn.x)[e] = cc;
            (&ah.x)[e] = hi; (&al.x)[e] = tf32_rna(hh - hi);
        }
        *(float4*)&g_c[gb + j]   = cn;
        *(float4*)&Aho[gb + j]   = ah;
        *(float4*)&Alo_o[gb + j] = al;
    }

    float pd[13];
    #pragma unroll
    for (int w = 0; w < 13; ++w) pd[w] = 0.0f;
    #pragma unroll
    for (int jj = 0; jj < 32; ++jj){
        float hv = hbuf[jj];
        const float* dc = &dws[j0 + jj];
        #pragma unroll
        for (int w = 0; w < 13; ++w) pd[w] += hv * dc[w * 64];
    }
    #pragma unroll
    for (int w = 0; w < 13; ++w) pd[w] += __shfl_xor_sync(0xffffffffu, pd[w], 1);
    if ((tid & 1) == 0){
        float4* dst = (float4*)&g_part[((size_t)bx * B_BATCH + R0 + row) * 16];
        dst[0] = make_float4(pd[0], pd[1], pd[2], pd[3]);
        dst[1] = make_float4(pd[4], pd[5], pd[6], pd[7]);
        dst[2] = make_float4(pd[8], pd[9], pd[10], pd[11]);
        dst[3] = make_float4(pd[12], 0.f, 0.f, 0.f);
    }
}

// ---------------- finalize: sum 8 col-tile partials, softmax + gumbel-max ----------------
__global__ __launch_bounds__(256)
void finalize_kernel(const float* __restrict__ bn, int k,
                     const float* __restrict__ bop,
                     const float* __restrict__ gum, int s, float* __restrict__ out){
    int b = blockIdx.x * 256 + threadIdx.x;
    float dn[5] = {0,0,0,0,0};
    float dq[8] = {0,0,0,0,0,0,0,0};
    #pragma unroll
    for (int bx = 0; bx < 8; ++bx){
        const float4* p = (const float4*)&g_part[((size_t)bx * B_BATCH + b) * 16];
        float4 p0 = p[0], p1 = p[1], p2 = p[2], p3 = p[3];
        dn[0] += p0.x; dn[1] += p0.y; dn[2] += p0.z; dn[3] += p0.w;
        dn[4] += p1.x;
        dq[0] += p1.y; dq[1] += p1.z; dq[2] += p1.w;
        dq[3] += p2.x; dq[4] += p2.y; dq[5] += p2.z; dq[6] += p2.w;
        dq[7] += p3.x;
    }
    float l[8];
    for (int w = 0; w < k; ++w) l[w] = 2.5f * tanhf((dn[w] + bn[w]) * 0.2f);
    {
        const float* g0 = gum + ((size_t)(2 * s) * B_BATCH + b) * 8;
        float m = l[0]; for (int w = 1; w < k; ++w) m = fmaxf(m, l[w]);
        float sum = 0.f; for (int w = 0; w < k; ++w) sum += expf(l[w] - m);
        float lse = m + logf(sum);
        float ent = 0.f;
        for (int w = 0; w < k; ++w){ float lp = l[w] - lse; ent -= lp * expf(lp); }
        int a = 0; float best = l[0] + g0[0];
        for (int w = 1; w < k; ++w){ float v = l[w] + g0[w]; if (v > best){ best = v; a = w; } }
        int row = 2 * s;
        out[(size_t)row * B_BATCH + b]        = (float)a;
        out[(size_t)(16 + row) * B_BATCH + b] = l[a] - lse;
        out[(size_t)(32 + row) * B_BATCH + b] = ent;
    }
    for (int w = 0; w < 8; ++w) l[w] = (dq[w] + bop[w]) * 0.2f;
    {
        const float* g1 = gum + ((size_t)(2 * s + 1) * B_BATCH + b) * 8;
        float m = l[0]; for (int w = 1; w < 8; ++w) m = fmaxf(m, l[w]);
        float sum = 0.f; for (int w = 0; w < 8; ++w) sum += expf(l[w] - m);
        float lse = m + logf(sum);
        float ent = 0.f;
        for (int w = 0; w < 8; ++w){ float lp = l[w] - lse; ent -= lp * expf(lp); }
        int a = 0; float best = l[0] + g1[0];
        for (int w = 1; w < 8; ++w){ float v = l[w] + g1[w]; if (v > best){ best = v; a = w; } }
        int row = 2 * s + 1;
        out[(size_t)row * B_BATCH + b]        = (float)a;
        out[(size_t)(16 + row) * B_BATCH + b] = l[a] - lse;
        out[(size_t)(32 + row) * B_BATCH + b] = ent;
        g_tok[b] = a;
    }
}

// ---------------- host: tensormap construction via dlopen(libcuda) ----------------
typedef CUresult (*EncodeTiledFn)(CUtensorMap*, CUtensorMapDataType, cuuint32_t, void*,
                                  const cuuint64_t*, const cuuint64_t*, const cuuint32_t*,
                                  const cuuint32_t*, CUtensorMapInterleave, CUtensorMapSwizzle,
                                  CUtensorMapL2promotion, CUtensorMapFloatOOBfill);

static EncodeTiledFn get_encoder(){
    void* h = dlopen("libcuda.so.1", RTLD_LAZY | RTLD_GLOBAL);
    if (!h) h = dlopen("libcuda.so", RTLD_LAZY | RTLD_GLOBAL);
    if (!h) return nullptr;
    return (EncodeTiledFn)dlsym(h, "cuTensorMapEncodeTiled");
}

static void make_map(EncodeTiledFn enc, CUtensorMap* m, void* base,
                     uint64_t rows, uint32_t box_rows){
    cuuint64_t dims[2]    = {(cuuint64_t)HID, (cuuint64_t)rows};
    cuuint64_t strides[1] = {(cuuint64_t)HID * 4};
    cuuint32_t box[2]     = {KC, box_rows};
    cuuint32_t es[2]      = {1, 1};
    enc(m, CU_TENSOR_MAP_DATA_TYPE_FLOAT32, 2, base, dims, strides, box, es,
        CU_TENSOR_MAP_INTERLEAVE_NONE, CU_TENSOR_MAP_SWIZZLE_128B,
        CU_TENSOR_MAP_L2_PROMOTION_L2_128B, CU_TENSOR_MAP_FLOAT_OOB_FILL_NONE);
}

// ---------------- launch ----------------
extern "C" void kernel_launch(void* const* d_in, const int* in_sizes, int n_in,
                              void* d_out, int out_size){
    const float* emb  = (const float*)d_in[0];
    const float* w_ih = (const float*)d_in[1];
    const float* w_hh = (const float*)d_in[2];
    const float* b_ih = (const float*)d_in[3];
    const float* b_hh = (const float*)d_in[4];
    const float* wn[4] = {(const float*)d_in[5], (const float*)d_in[7],
                          (const float*)d_in[9], (const float*)d_in[11]};
    const float* bn[4] = {(const float*)d_in[6], (const float*)d_in[8],
                          (const float*)d_in[10], (const float*)d_in[12]};
    const float* wop = (const float*)d_in[13];
    const float* bop = (const float*)d_in[14];
    const float* gum = (const float*)d_in[15];
    float* out = (float*)d_out;

    EncodeTiledFn enc = get_encoder();
    void *pAh, *pAl, *pBh, *pBl, *pHd, *pCd;
    cudaGetSymbolAddress(&pAh, g_Ah);
    cudaGetSymbolAddress(&pAl, g_Al);
    cudaGetSymbolAddress(&pBh, g_Bh);
    cudaGetSymbolAddress(&pBl, g_Bl);
    cudaGetSymbolAddress(&pHd, g_Hd);
    cudaGetSymbolAddress(&pCd, g_Cd);
    CUtensorMap mAh[2], mAl[2], mBh, mBl;
    size_t buf = (size_t)B_BATCH * HID * 4;
    make_map(enc, &mAh[0], (char*)pAh,       B_BATCH, BM);
    make_map(enc, &mAh[1], (char*)pAh + buf, B_BATCH, BM);
    make_map(enc, &mAl[0], (char*)pAl,       B_BATCH, BM);
    make_map(enc, &mAl[1], (char*)pAl + buf, B_BATCH, BM);
    make_map(enc, &mBh, pBh, G4, BN);
    make_map(enc, &mBl, pBl, G4, BN);

    float* Hd0 = (float*)pHd;
    float* Hd1 = (float*)pHd + 512 * HID;
    float* Cd0 = (float*)pCd;
    float* Cd1 = (float*)pCd + 512 * HID;

    cudaFuncSetAttribute(lstm_step_tma, cudaFuncAttributeMaxDynamicSharedMemorySize, SMEM_TOTAL);

    precompute_E<<<dim3(G4 / 256, 9), 256>>>(emb, w_ih, b_ih, b_hh);
    split_B<<<G4, 256>>>(w_hh);

    // step 0: rank-1
    step0_compute<<<1, 512>>>(wn[0], bn[0], wop, bop);
    step0_sample<<<B_BATCH / 256, 256>>>(gum, out);

    // step 1: 1 -> 8 distinct keys (heads i=0)
    dstep_gemm<<<dim3(8, 1), 256>>>(w_hh, Hd0, 1);
    dstep_point<<<8, 128>>>(1, 2, wn[0], bn[0], wop, bop, Hd1, Cd1, Cd0);
    dsample<<<B_BATCH / 256, 256>>>(1, 8, 2, gum, out);

    // step 2: 8 -> 64 (heads i=1)
    dstep_gemm<<<dim3(8, 1), 256>>>(w_hh, Hd1, 8);
    dstep_point<<<64, 128>>>(8, 3, wn[1], bn[1], wop + 8 * HID, bop + 8, Hd0, Cd0, Cd1);
    dsample<<<B_BATCH / 256, 256>>>(2, 64, 3, gum, out);

    // step 3: 64 -> 512 (heads i=1)
    dstep_gemm<<<dim3(8, 8), 256>>>(w_hh, Hd0, 64);
    dstep_point<<<512, 128>>>(64, 3, wn[1], bn[1], wop + 8 * HID, bop + 8, Hd1, Cd1, Cd0);
    dsample<<<B_BATCH / 256, 256>>>(3, 512, 3, gum, out);

    // materialize per-row state for step 4 (reads ping 0)
    materialize<<<2048, 256>>>();

    for (int s = 4; s < 8; ++s){
        int i = s >> 1;
        int ping = s & 1;
        lstm_step_tma<<<dim3(G4 / BN, B_BATCH / BM), 256, SMEM_TOTAL>>>(
            ping, i + 2, wn[i], wop + (size_t)i * 8 * HID,
            mAh[ping], mAl[ping], mBh, mBl);
        finalize_kernel<<<B_BATCH / 256, 256>>>(bn[i], i + 2, bop + i * 8,
                                                gum, s, out);
    }
}

// round 12
// speedup vs baseline: 2.2087x; 1.0023x over previous
#include <cuda_runtime.h>
#include <cuda.h>
#include <dlfcn.h>
#include <cstdint>
#include <math.h>

#define B_BATCH 4096
#define HID     512
#define G4      2048
#define BM      128
#define BN      256
#define KC      32
#define NCHUNK  16

#define STG_BYTES  98304
#define STG(s)     ((s) * STG_BYTES)
#define OFF_AHI    0
#define OFF_ALO    16384
#define OFF_BHI    32768
#define OFF_BLO    65536
#define OFF_MBAR   196608
#define OFF_ES     196672
#define ES_PITCH   260
#define OFF_DWS    (OFF_ES + 9 * ES_PITCH * 4)
#define SMEM_TOTAL (OFF_DWS + 13 * 64 * 4)
#define D_PITCH    264
#define CHUNK_BYTES 98304u

// ---------------- device scratch ----------------
__device__ __align__(1024) float g_E[9 * G4];
__device__ __align__(1024) float g_c[B_BATCH * HID];
__device__ __align__(1024) float g_Ah[2][B_BATCH * HID];
__device__ __align__(1024) float g_Al[2][B_BATCH * HID];
__device__ __align__(1024) float g_Bh[G4 * HID];
__device__ __align__(1024) float g_Bl[G4 * HID];
__device__ __align__(1024) float g_part[8 * B_BATCH * 16];
__device__ __align__(1024) float g_Hd[2][512 * HID];
__device__ __align__(1024) float g_Cd[2][512 * HID];
__device__ __align__(1024) float g_G[64 * G4];
__device__ float g_dlog[512 * 20];
__device__ float g_dec0[16];
__device__ int g_tok[B_BATCH];
__device__ int g_key[B_BATCH];
__device__ int g_done[32];

// ---------------- helpers ----------------
__device__ __forceinline__ uint32_t smem_u32(const void* p){
    uint32_t a; asm("{ .reg .u64 t; cvta.to.shared.u64 t, %1; cvt.u32.u64 %0, t; }" : "=r"(a) : "l"(p));
    return a;
}
__device__ __forceinline__ float tf32_rna(float x){
    uint32_t t; asm("cvt.rna.tf32.f32 %0, %1;" : "=r"(t) : "f"(x));
    return __uint_as_float(t);
}
__device__ __forceinline__ float sigf(float x){ return __fdividef(1.0f, 1.0f + __expf(-x)); }
__device__ __forceinline__ float tanhfa(float x){ return 2.0f * __fdividef(1.0f, 1.0f + __expf(-2.0f * x)) - 1.0f; }

#define LDSM4(r0, r1, r2, r3, addr) \
    asm volatile("ldmatrix.sync.aligned.m8n8.x4.shared.b16 {%0,%1,%2,%3}, [%4];" \
        : "=r"(r0), "=r"(r1), "=r"(r2), "=r"(r3) : "r"(addr))

#define MMA_TF32(d, a, b) \
    asm volatile("mma.sync.aligned.m16n8k8.row.col.f32.tf32.tf32.f32 " \
        "{%0,%1,%2,%3}, {%4,%5,%6,%7}, {%8,%9}, {%0,%1,%2,%3};" \
        : "+f"((d)[0]), "+f"((d)[1]), "+f"((d)[2]), "+f"((d)[3]) \
        : "r"((a)[0]), "r"((a)[1]), "r"((a)[2]), "r"((a)[3]), "r"((b)[0]), "r"((b)[1]))

#define MBAR_INIT(mb, n) asm volatile("mbarrier.init.shared.b64 [%0], %1;" :: "r"((uint32_t)(mb)), "r"((uint32_t)(n)) : "memory")
#define MBAR_EXPECT_TX(mb, bytes) asm volatile("mbarrier.arrive.expect_tx.shared.b64 _, [%0], %1;" :: "r"((uint32_t)(mb)), "r"((uint32_t)(bytes)) : "memory")
#define MBAR_ARRIVE(mb) asm volatile("mbarrier.arrive.shared.b64 _, [%0];" :: "r"((uint32_t)(mb)) : "memory")
#define MBAR_WAIT(mb, par) do { \
    uint32_t _m = (uint32_t)(mb); uint32_t _p = (uint32_t)(par); uint32_t _d; \
    asm volatile("{\n\t.reg .pred p;\n\tmbarrier.try_wait.parity.acquire.cta.shared::cta.b64 p, [%1], %2;\n\tselp.b32 %0, 1, 0, p;\n\t}" \
        : "=r"(_d) : "r"(_m), "r"(_p) : "memory"); \
    if (!_d) { \
        asm volatile("{\n\t.reg .pred P1;\n\tWL_%=:\n\tmbarrier.try_wait.parity.acquire.cta.shared::cta.b64 P1, [%0], %1, 0x989680;\n\t@P1 bra.uni WD_%=;\n\tbra.uni WL_%=;\n\tWD_%=:\n\t}" \
            :: "r"(_m), "r"(_p) : "memory"); \
    } } while (0)

#define TMA_2D(dst, map, cx, cy, mb) \
    asm volatile("cp.async.bulk.tensor.2d.shared::cta.global.tile.mbarrier::complete_tx::bytes " \
        "[%0], [%1, {%2, %3}], [%4];" \
        :: "r"((uint32_t)(dst)), "l"(map), "r"((int32_t)(cx)), "r"((int32_t)(cy)), "r"((uint32_t)(mb)) : "memory")

// ---------------- E = emb @ w_ih^T + b_ih + b_hh ----------------
__global__ void precompute_E(const float* __restrict__ emb, const float* __restrict__ w_ih,
                             const float* __restrict__ b_ih, const float* __restrict__ b_hh){
    __shared__ float er[HID];
    int t = blockIdx.y;
    int j = blockIdx.x * blockDim.x + threadIdx.x;
    for (int k = threadIdx.x; k < HID; k += blockDim.x) er[k] = emb[t * HID + k];
    __syncthreads();
    const float* w = w_ih + (size_t)j * HID;
    float s = 0.f;
    #pragma unroll 4
    for (int k = 0; k < HID; k += 4){
        float4 wv = *(const float4*)(w + k);
        s += er[k]*wv.x + er[k+1]*wv.y + er[k+2]*wv.z + er[k+3]*wv.w;
    }
    g_E[t * G4 + j] = s + b_ih[j] + b_hh[j];
}

// ---------------- split + permute w_hh ----------------
__global__ void split_B(const float* __restrict__ w_hh){
    int r = blockIdx.x;
    int t = r >> 8, n = r & 255;
    int srow = (n >> 6) * HID + t * 64 + (n & 63);
    const float* s = w_hh + (size_t)srow * HID;
    float* dh = g_Bh + (size_t)r * HID;
    float* dl = g_Bl + (size_t)r * HID;
    for (int k = threadIdx.x; k < HID; k += blockDim.x){
        float w = s[k];
        float hi = tf32_rna(w);
        dh[k] = hi;
        dl[k] = tf32_rna(w - hi);
    }
}

// ---------------- step 0: one shared row + rank-1 decisions ----------------
__global__ void step0_compute(const float* __restrict__ wn2, const float* __restrict__ bn2,
                              const float* __restrict__ wop0, const float* __restrict__ bop0){
    __shared__ float sh[HID];
    __shared__ float lg[10];
    int k = threadIdx.x;
    float i_ = sigf(g_E[k]);
    float gg = tanhfa(g_E[1024 + k]);
    float o_ = sigf(g_E[1536 + k]);
    float cc = i_ * gg;
    float hh = o_ * tanhfa(cc);
    sh[k] = hh;
    g_Hd[0][k] = hh;
    g_Cd[0][k] = cc;
    __syncthreads();
    int wid = k >> 5, lane = k & 31;
    if (wid < 10){
        const float* wr = (wid < 2) ? wn2 + wid * HID : wop0 + (wid - 2) * HID;
        float s = 0.f;
        #pragma unroll
        for (int j = 0; j < 16; ++j){
            int col = lane + (j << 5);
            s += sh[col] * wr[col];
        }
        #pragma unroll
        for (int off = 16; off > 0; off >>= 1) s += __shfl_xor_sync(0xffffffffu, s, off);
        if (lane == 0) lg[wid] = s;
    }
    __syncthreads();
    if (k == 0){
        float l0[2], l1[8];
        for (int w = 0; w < 2; ++w) l0[w] = 2.5f * tanhf((lg[w] + bn2[w]) * 0.2f);
        for (int w = 0; w < 8; ++w) l1[w] = (lg[2 + w] + bop0[w]) * 0.2f;
        float m0 = fmaxf(l0[0], l0[1]);
        float s0 = expf(l0[0] - m0) + expf(l0[1] - m0);
        float lse0 = m0 + logf(s0);
        float e0 = 0.f;
        for (int w = 0; w < 2; ++w){ float lp = l0[w] - lse0; e0 -= lp * expf(lp); }
        float m1 = l1[0]; for (int w = 1; w < 8; ++w) m1 = fmaxf(m1, l1[w]);
        float s1 = 0.f; for (int w = 0; w < 8; ++w) s1 += expf(l1[w] - m1);
        float lse1 = m1 + logf(s1);
        float e1 = 0.f;
        for (int w = 0; w < 8; ++w){ float lp = l1[w] - lse1; e1 -= lp * expf(lp); }
        g_dec0[0] = l0[0]; g_dec0[1] = l0[1];
        for (int w = 0; w < 8; ++w) g_dec0[2 + w] = l1[w];
        g_dec0[10] = lse0; g_dec0[11] = lse1;
        g_dec0[12] = e0;   g_dec0[13] = e1;
    }
}

__global__ void step0_sample(const float* __restrict__ gum, float* __restrict__ out){
    int b = blockIdx.x * 256 + threadIdx.x;
    float l0[2], l1[8];
    l0[0] = g_dec0[0]; l0[1] = g_dec0[1];
    #pragma unroll
    for (int w = 0; w < 8; ++w) l1[w] = g_dec0[2 + w];
    float lse0 = g_dec0[10], lse1 = g_dec0[11];
    float e0 = g_dec0[12], e1 = g_dec0[13];
    const float* g0 = gum + (size_t)b * 8;
    const float* g1 = gum + ((size_t)B_BATCH + b) * 8;
    int a0 = (l0[1] + g0[1] > l0[0] + g0[0]) ? 1 : 0;
    out[b]                         = (float)a0;
    out[(size_t)16 * B_BATCH + b]  = l0[a0] - lse0;
    out[(size_t)32 * B_BATCH + b]  = e0;
    int a1 = 0; float best = l1[0] + g1[0];
    #pragma unroll
    for (int w = 1; w < 8; ++w){ float v = l1[w] + g1[w]; if (v > best){ best = v; a1 = w; } }
    out[(size_t)1 * B_BATCH + b]   = (float)a1;
    out[(size_t)17 * B_BATCH + b]  = l1[a1] - lse1;
    out[(size_t)33 * B_BATCH + b]  = e1;
    g_key[b] = a1;
}

// ---------------- distinct-state steps 1..3 ----------------
__global__ __launch_bounds__(256)
void dstep_gemm(const float* __restrict__ w_hh, const float* __restrict__ Hd, int Kin){
    __shared__ float hs[8][HID];
    __shared__ float ws[256][17];
    int tid = threadIdx.x;
    int j0 = blockIdx.x * 256;
    int kb = blockIdx.y * 8;
    int nk = Kin - kb; if (nk > 8) nk = 8;
    for (int idx = tid; idx < nk * HID; idx += 256)
        hs[idx >> 9][idx & 511] = Hd[(size_t)(kb + (idx >> 9)) * HID + (idx & 511)];
    float acc[8] = {0,0,0,0,0,0,0,0};
    for (int kc = 0; kc < HID; kc += 16){
        __syncthreads();
        #pragma unroll
        for (int i = 0; i < 16; ++i){
            int e = tid + 256 * i;
            ws[e >> 4][e & 15] = w_hh[(size_t)(j0 + (e >> 4)) * HID + kc + (e & 15)];
        }
        __syncthreads();
        #pragma unroll
        for (int kl = 0; kl < 16; ++kl){
            float w = ws[tid][kl];
            #pragma unroll
            for (int q = 0; q < 8; ++q) acc[q] += w * hs[q][kc + kl];
        }
    }
    for (int q = 0; q < nk; ++q) g_G[(size_t)(kb + q) * G4 + j0 + tid] = acc[q];
}

__global__ __launch_bounds__(128)
void dstep_point(int Kin, int kd,
                 const float* __restrict__ wn, const float* __restrict__ bn,
                 const float* __restrict__ wop, const float* __restrict__ bop,
                 float* __restrict__ Hdo, float* __restrict__ Cdo,
                 const float* __restrict__ Cdi){
    __shared__ float sh[HID];
    __shared__ float hd[13];
    int kp = blockIdx.x;
    int k = kp % Kin, t = kp / Kin;
    int tid = threadIdx.x;
    const float* Gr = &g_G[(size_t)k * G4];
    const float* Er = &g_E[(size_t)t * G4];
    const float* Cr = &Cdi[(size_t)k * HID];
    #pragma unroll
    for (int e = 0; e < 4; ++e){
        int col = tid * 4 + e;
        float gi = Gr[col]        + Er[col];
        float gf = Gr[512 + col]  + Er[512 + col];
        float gg = Gr[1024 + col] + Er[1024 + col];
        float go = Gr[1536 + col] + Er[1536 + col];
        float i_ = sigf(gi), f_ = sigf(gf);
        float g_ = tanhfa(gg), o_ = sigf(go);
        float cc = f_ * Cr[col] + i_ * g_;
        float hh = o_ * tanhfa(cc);
        sh[col] = hh;
        Hdo[(size_t)kp * HID + col] = hh;
        Cdo[(size_t)kp * HID + col] = cc;
    }
    __syncthreads();
    int wid = tid >> 5, lane = tid & 31;
    for (int hx = wid; hx < 13; hx += 4){
        if (hx < 5 && hx >= kd) continue;
        const float* wr = (hx < 5) ? wn + hx * HID : wop + (hx - 5) * HID;
        float s = 0.f;
        #pragma unroll
        for (int j = 0; j < 16; ++j){
            int col = lane + (j << 5);
            s += sh[col] * wr[col];
        }
        #pragma unroll
        for (int off = 16; off > 0; off >>= 1) s += __shfl_xor_sync(0xffffffffu, s, off);
        if (lane == 0) hd[hx] = s;
    }
    __syncthreads();
    if (tid == 0){
        float* dl = &g_dlog[kp * 20];
        float ln[5], lo[8];
        for (int w = 0; w < kd; ++w) ln[w] = 2.5f * tanhf((hd[w] + bn[w]) * 0.2f);
        for (int w = 0; w < 8; ++w)  lo[w] = (hd[5 + w] + bop[w]) * 0.2f;
        float m = ln[0]; for (int w = 1; w < kd; ++w) m = fmaxf(m, ln[w]);
        float sum = 0.f; for (int w = 0; w < kd; ++w) sum += expf(ln[w] - m);
        float lse_n = m + logf(sum);
        float ent_n = 0.f;
        for (int w = 0; w < kd; ++w){ float lp = ln[w] - lse_n; ent_n -= lp * expf(lp); }
        m = lo[0]; for (int w = 1; w < 8; ++w) m = fmaxf(m, lo[w]);
        sum = 0.f; for (int w = 0; w < 8; ++w) sum += expf(lo[w] - m);
        float lse_o = m + logf(sum);
        float ent_o = 0.f;
        for (int w = 0; w < 8; ++w){ float lp = lo[w] - lse_o; ent_o -= lp * expf(lp); }
        for (int w = 0; w < kd; ++w) dl[w] = ln[w];
        for (int w = 0; w < 8; ++w)  dl[5 + w] = lo[w];
        dl[13] = lse_n; dl[14] = lse_o; dl[15] = ent_n; dl[16] = ent_o;
    }
}

__global__ void dsample(int s, int K, int kd, const float* __restrict__ gum, float* __restrict__ out){
    int b = blockIdx.x * 256 + threadIdx.x;
    int k = g_key[b];
    const float* dl = &g_dlog[k * 20];
    const float* g0 = gum + ((size_t)(2 * s) * B_BATCH + b) * 8;
    int a = 0; float best = dl[0] + g0[0];
    for (int w = 1; w < kd; ++w){ float v = dl[w] + g0[w]; if (v > best){ best = v; a = w; } }
    int row = 2 * s;
    out[(size_t)row * B_BATCH + b]        = (float)a;
    out[(size_t)(16 + row) * B_BATCH + b] = dl[a] - dl[13];
    out[(size_t)(32 + row) * B_BATCH + b] = dl[15];
    const float* g1 = gum + ((size_t)(2 * s + 1) * B_BATCH + b) * 8;
    a = 0; best = dl[5] + g1[0];
    #pragma unroll
    for (int w = 1; w < 8; ++w){ float v = dl[5 + w] + g1[w]; if (v > best){ best = v; a = w; } }
    row = 2 * s + 1;
    out[(size_t)row * B_BATCH + b]        = (float)a;
    out[(size_t)(16 + row) * B_BATCH + b] = dl[5 + a] - dl[14];
    out[(size_t)(32 + row) * B_BATCH + b] = dl[16];
    g_key[b] = k + K * a;
    g_tok[b] = a;
}

__global__ void materialize(){
    int idx = blockIdx.x * blockDim.x + threadIdx.x;
    int r  = idx >> 7;
    int c4 = (idx & 127) << 2;
    int k = g_key[r] & 511;
    float4 h4 = *(const float4*)&g_Hd[1][(size_t)k * HID + c4];
    float4 cv = *(const float4*)&g_Cd[1][(size_t)k * HID + c4];
    float4 ah, al;
    #pragma unroll
    for (int e = 0; e < 4; ++e){
        float hh = (&h4.x)[e];
        float hi = tf32_rna(hh);
        (&ah.x)[e] = hi;
        (&al.x)[e] = tf32_rna(hh - hi);
    }
    size_t gb = ((size_t)r << 9) + c4;
    *(float4*)&g_c[gb]     = cv;
    *(float4*)&g_Ah[0][gb] = ah;
    *(float4*)&g_Al[0][gb] = al;
}

// ---------------- full per-row step (s=4..7) ----------------
// doFin: warps 4-7 of bx==0 CTAs run finalize for step sPrev (rows R0..R0+127),
// publishing g_tok + flag g_done[y] = sPrev+1; siblings spin before epilogue.
__global__ __launch_bounds__(256, 1)
void lstm_step_tma(int sIn, int kd, int doFin, int kdPrev, int sPrev,
                   const float* __restrict__ wnp, const float* __restrict__ wopp,
                   const float* __restrict__ bnPrev, const float* __restrict__ bopPrev,
                   const float* __restrict__ gum, float* __restrict__ out,
                   const __grid_constant__ CUtensorMap mAh,
                   const __grid_constant__ CUtensorMap mAl,
                   const __grid_constant__ CUtensorMap mBh,
                   const __grid_constant__ CUtensorMap mBl){
    extern __shared__ __align__(1024) char smem[];
    uint32_t sb = smem_u32(smem);
    int tid = threadIdx.x, wid = tid >> 5, lane = tid & 31;
    int bx = blockIdx.x;
    int R0 = blockIdx.y * BM;
    int N0 = bx * BN;
    int c0 = bx * 64;

    float* Es  = (float*)(smem + OFF_ES);
    float* dws = (float*)(smem + OFF_DWS);

    uint32_t fullb  = sb + OFF_MBAR;
    uint32_t emptyb = sb + OFF_MBAR + 16;
    if (tid == 0){
        MBAR_INIT(fullb, 1);
        MBAR_INIT(fullb + 8, 1);
        MBAR_INIT(emptyb, 8);
        MBAR_INIT(emptyb + 8, 8);
    }
    __syncthreads();

    // TMA prologue first: chunks 0 and 1 in flight while we do scalar work below
    if (tid == 0){
        #pragma unroll
        for (int c = 0; c < 2; ++c){
            uint32_t mb = fullb + c * 8;
            uint32_t st = sb + STG(c);
            MBAR_EXPECT_TX(mb, CHUNK_BYTES);
            TMA_2D(st + OFF_AHI, &mAh, c * KC, R0, mb);
            TMA_2D(st + OFF_ALO, &mAl, c * KC, R0, mb);
            TMA_2D(st + OFF_BHI, &mBh, c * KC, N0, mb);
            TMA_2D(st + OFF_BLO, &mBl, c * KC, N0, mb);
        }
    }

    // in-kernel finalize for previous step (bx==0 CTAs, warps 4-7)
    if (doFin && bx == 0 && tid >= 128){
        int b = R0 + tid - 128;
        float dn[5] = {0,0,0,0,0};
        float dq[8] = {0,0,0,0,0,0,0,0};
        #pragma unroll
        for (int bx2 = 0; bx2 < 8; ++bx2){
            const float4* p = (const float4*)&g_part[((size_t)bx2 * B_BATCH + b) * 16];
            float4 p0 = p[0], p1 = p[1], p2 = p[2], p3 = p[3];
            dn[0] += p0.x; dn[1] += p0.y; dn[2] += p0.z; dn[3] += p0.w;
            dn[4] += p1.x;
            dq[0] += p1.y; dq[1] += p1.z; dq[2] += p1.w;
            dq[3] += p2.x; dq[4] += p2.y; dq[5] += p2.z; dq[6] += p2.w;
            dq[7] += p3.x;
        }
        float l[8];
        for (int w = 0; w < kdPrev; ++w) l[w] = 2.5f * tanhf((dn[w] + bnPrev[w]) * 0.2f);
        {
            const float* g0 = gum + ((size_t)(2 * sPrev) * B_BATCH + b) * 8;
            float m = l[0]; for (int w = 1; w < kdPrev; ++w) m = fmaxf(m, l[w]);
            float sum = 0.f; for (int w = 0; w < kdPrev; ++w) sum += expf(l[w] - m);
            float lse = m + logf(sum);
            float ent = 0.f;
            for (int w = 0; w < kdPrev; ++w){ float lp = l[w] - lse; ent -= lp * expf(lp); }
            int a = 0; float best = l[0] + g0[0];
            for (int w = 1; w < kdPrev; ++w){ float v = l[w] + g0[w]; if (v > best){ best = v; a = w; } }
            int row = 2 * sPrev;
            out[(size_t)row * B_BATCH + b]        = (float)a;
            out[(size_t)(16 + row) * B_BATCH + b] = l[a] - lse;
            out[(size_t)(32 + row) * B_BATCH + b] = ent;
        }
        for (int w = 0; w < 8; ++w) l[w] = (dq[w] + bopPrev[w]) * 0.2f;
        {
            const float* g1 = gum + ((size_t)(2 * sPrev + 1) * B_BATCH + b) * 8;
            float m = l[0]; for (int w = 1; w < 8; ++w) m = fmaxf(m, l[w]);
            float sum = 0.f; for (int w = 0; w < 8; ++w) sum += expf(l[w] - m);
            float lse = m + logf(sum);
            float ent = 0.f;
            for (int w = 0; w < 8; ++w){ float lp = l[w] - lse; ent -= lp * expf(lp); }
            int a = 0; float best = l[0] + g1[0];
            for (int w = 1; w < 8; ++w){ float v = l[w] + g1[w]; if (v > best){ best = v; a = w; } }
            int row = 2 * sPrev + 1;
            out[(size_t)row * B_BATCH + b]        = (float)a;
            out[(size_t)(16 + row) * B_BATCH + b] = l[a] - lse;
            out[(size_t)(32 + row) * B_BATCH + b] = ent;
            g_tok[b] = a;
        }
        asm volatile("bar.sync 1, 128;" ::: "memory");
        if (tid == 128){
            __threadfence();
            atomicExch(&g_done[blockIdx.y], sPrev + 1);
        }
    }

    // prologue gathers (overlap with chunk-0/1 TMA flight)
    for (int idx = tid; idx < 9 * 256; idx += 256){
        int t = idx >> 8, n = idx & 255;
        Es[t * ES_PITCH + n] = g_E[t * G4 + (n >> 6) * HID + c0 + (n & 63)];
    }
    for (int idx = tid; idx < 13 * 64; idx += 256){
        int w = idx >> 6, j = idx & 63;
        float v;
        if (w < 5) v = (w < kd) ? wnp[w * HID + c0 + j] : 0.0f;
        else       v = wopp[(w - 5) * HID + c0 + j];
        dws[idx] = v;
    }

    int wm = wid >> 2, wn = wid & 3;
    int mat = lane >> 3, r8 = lane & 7;
    int rowA[4];
    #pragma unroll
    for (int f = 0; f < 4; ++f) rowA[f] = wm * 64 + f * 16 + ((mat & 1) << 3) + r8;
    int usA = mat >> 1;
    int rowB[4];
    #pragma unroll
    for (int p = 0; p < 4; ++p) rowB[p] = wn * 64 + (p * 2 + (mat >> 1)) * 8 + r8;
    int usB = mat & 1;

    float acc[4][8][4];
    #pragma unroll
    for (int f = 0; f < 4; ++f)
        #pragma unroll
        for (int j = 0; j < 8; ++j)
            #pragma unroll
            for (int e = 0; e < 4; ++e) acc[f][j][e] = 0.0f;

    #pragma unroll 1
    for (int c = 0; c < NCHUNK; ++c){
        int stg = c & 1;
        int par = (c >> 1) & 1;
        MBAR_WAIT(fullb + stg * 8, par);

        uint32_t ahi_b = sb + STG(stg) + OFF_AHI;
        uint32_t alo_b = sb + STG(stg) + OFF_ALO;
        uint32_t bhi_b = sb + STG(stg) + OFF_BHI;
        uint32_t blo_b = sb + STG(stg) + OFF_BLO;

        #pragma unroll
        for (int s = 0; s < 4; ++s){
            int ku = s * 2;
            uint32_t ah[4][4], bh[8][2];
            #pragma unroll
            for (int f = 0; f < 4; ++f){
                uint32_t ad = ahi_b + rowA[f] * 128 + (((ku + usA) ^ r8) << 4);
                LDSM4(ah[f][0], ah[f][1], ah[f][2], ah[f][3], ad);
            }
            #pragma unroll
            for (int p = 0; p < 4; ++p){
                uint32_t bd = bhi_b + rowB[p] * 128 + (((ku + usB) ^ r8) << 4);
                LDSM4(bh[2*p][0], bh[2*p][1], bh[2*p+1][0], bh[2*p+1][1], bd);
            }
            #pragma unroll
            for (int f = 0; f < 4; ++f)
                #pragma unroll
                for (int j = 0; j < 8; ++j)
                    MMA_TF32(acc[f][j], ah[f], bh[j]);

            {
                uint32_t al[4][4];
                #pragma unroll
                for (int f = 0; f < 4; ++f){
                    uint32_t ad = alo_b + rowA[f] * 128 + (((ku + usA) ^ r8) << 4);
                    LDSM4(al[f][0], al[f][1], al[f][2], al[f][3], ad);
                }
                #pragma unroll
                for (int f = 0; f < 4; ++f)
                    #pragma unroll
                    for (int j = 0; j < 8; ++j)
                        MMA_TF32(acc[f][j], al[f], bh[j]);
            }
            {
                uint32_t bl[8][2];
                #pragma unroll
                for (int p = 0; p < 4; ++p){
                    uint32_t bd = blo_b + rowB[p] * 128 + (((ku + usB) ^ r8) << 4);
                    LDSM4(bl[2*p][0], bl[2*p][1], bl[2*p+1][0], bl[2*p+1][1], bd);
                }
                #pragma unroll
                for (int f = 0; f < 4; ++f)
                    #pragma unroll
                    for (int j = 0; j < 8; ++j)
                        MMA_TF32(acc[f][j], ah[f], bl[j]);
            }
        }

        if (lane == 0) MBAR_ARRIVE(emptyb + stg * 8);
        if (tid == 0 && c + 2 < NCHUNK){
            MBAR_WAIT(emptyb + stg * 8, par);
            int cn = c + 2;
            uint32_t mb = fullb + stg * 8;
            uint32_t st = sb + STG(stg);
            MBAR_EXPECT_TX(mb, CHUNK_BYTES);
            TMA_2D(st + OFF_AHI, &mAh, cn * KC, R0, mb);
            TMA_2D(st + OFF_ALO, &mAl, cn * KC, R0, mb);
            TMA_2D(st + OFF_BHI, &mBh, cn * KC, N0, mb);
            TMA_2D(st + OFF_BLO, &mBl, cn * KC, N0, mb);
        }
    }

    // wait for previous-step tokens (flag set by bx==0 CTA of this row-block)
    if (doFin && bx != 0 && tid == 0){
        while (atomicAdd(&g_done[blockIdx.y], 0) != sPrev + 1) {}
        __threadfence();
    }
    __syncthreads();
    float* Ds = (float*)smem;
    #pragma unroll
    for (int f = 0; f < 4; ++f){
        int r0 = wm * 64 + f * 16 + (lane >> 2);
        #pragma unroll
        for (int j = 0; j < 8; ++j){
            int cb = wn * 64 + j * 8 + 2 * (lane & 3);
            *(float2*)&Ds[r0 * D_PITCH + cb]       = make_float2(acc[f][j][0], acc[f][j][1]);
            *(float2*)&Ds[(r0 + 8) * D_PITCH + cb] = make_float2(acc[f][j][2], acc[f][j][3]);
        }
    }
    __syncthreads();

    int row  = tid >> 1;
    int j0   = (tid & 1) * 32;
    int t    = g_tok[R0 + row];
    const float* Ep = &Es[t * ES_PITCH];
    const float* Dr = &Ds[row * D_PITCH];
    size_t gb = ((size_t)(R0 + row) << 9) + c0;
    float* Aho = &g_Ah[sIn ^ 1][0];
    float* Alo_o = &g_Al[sIn ^ 1][0];
    float hbuf[32];
    #pragma unroll
    for (int jj = 0; jj < 32; jj += 4){
        int j = j0 + jj;
        float4 iv = *(const float4*)&Dr[j];
        float4 fv = *(const float4*)&Dr[64 + j];
        float4 gv = *(const float4*)&Dr[128 + j];
        float4 ov = *(const float4*)&Dr[192 + j];
        float4 cv = *(const float4*)&g_c[gb + j];
        float4 cn, ah, al;
        #pragma unroll
        for (int e = 0; e < 4; ++e){
            float i_ = sigf((&iv.x)[e] + Ep[j + e]);
            float f_ = sigf((&fv.x)[e] + Ep[64 + j + e]);
            float gg = tanhfa((&gv.x)[e] + Ep[128 + j + e]);
            float o_ = sigf((&ov.x)[e] + Ep[192 + j + e]);
            float cc = f_ * ((&cv.x)[e]) + i_ * gg;
            float hh = o_ * tanhfa(cc);
            float hi = tf32_rna(hh);
            hbuf[jj + e] = hh;
            (&cn.x)[e] = cc;
            (&ah.x)[e] = hi; (&al.x)[e] = tf32_rna(hh - hi);
        }
        *(float4*)&g_c[gb + j]   = cn;
        *(float4*)&Aho[gb + j]   = ah;
        *(float4*)&Alo_o[gb + j] = al;
    }

    float pd[13];
    #pragma unroll
    for (int w = 0; w < 13; ++w) pd[w] = 0.0f;
    #pragma unroll
    for (int jj = 0; jj < 32; ++jj){
        float hv = hbuf[jj];
        const float* dc = &dws[j0 + jj];
        #pragma unroll
        for (int w = 0; w < 13; ++w) pd[w] += hv * dc[w * 64];
    }
    #pragma unroll
    for (int w = 0; w < 13; ++w) pd[w] += __shfl_xor_sync(0xffffffffu, pd[w], 1);
    if ((tid & 1) == 0){
        float4* dst = (float4*)&g_part[((size_t)bx * B_BATCH + R0 + row) * 16];
        dst[0] = make_float4(pd[0], pd[1], pd[2], pd[3]);
        dst[1] = make_float4(pd[4], pd[5], pd[6], pd[7]);
        dst[2] = make_float4(pd[8], pd[9], pd[10], pd[11]);
        dst[3] = make_float4(pd[12], 0.f, 0.f, 0.f);
    }
}

// ---------------- finalize (last step only) ----------------
__global__ __launch_bounds__(256)
void finalize_kernel(const float* __restrict__ bn, int k,
                     const float* __restrict__ bop,
                     const float* __restrict__ gum, int s, float* __restrict__ out){
    int b = blockIdx.x * 256 + threadIdx.x;
    float dn[5] = {0,0,0,0,0};
    float dq[8] = {0,0,0,0,0,0,0,0};
    #pragma unroll
    for (int bx = 0; bx < 8; ++bx){
        const float4* p = (const float4*)&g_part[((size_t)bx * B_BATCH + b) * 16];
        float4 p0 = p[0], p1 = p[1], p2 = p[2], p3 = p[3];
        dn[0] += p0.x; dn[1] += p0.y; dn[2] += p0.z; dn[3] += p0.w;
        dn[4] += p1.x;
        dq[0] += p1.y; dq[1] += p1.z; dq[2] += p1.w;
        dq[3] += p2.x; dq[4] += p2.y; dq[5] += p2.z; dq[6] += p2.w;
        dq[7] += p3.x;
    }
    float l[8];
    for (int w = 0; w < k; ++w) l[w] = 2.5f * tanhf((dn[w] + bn[w]) * 0.2f);
    {
        const float* g0 = gum + ((size_t)(2 * s) * B_BATCH + b) * 8;
        float m = l[0]; for (int w = 1; w < k; ++w) m = fmaxf(m, l[w]);
        float sum = 0.f; for (int w = 0; w < k; ++w) sum += expf(l[w] - m);
        float lse = m + logf(sum);
        float ent = 0.f;
        for (int w = 0; w < k; ++w){ float lp = l[w] - lse; ent -= lp * expf(lp); }
        int a = 0; float best = l[0] + g0[0];
        for (int w = 1; w < k; ++w){ float v = l[w] + g0[w]; if (v > best){ best = v; a = w; } }
        int row = 2 * s;
        out[(size_t)row * B_BATCH + b]        = (float)a;
        out[(size_t)(16 + row) * B_BATCH + b] = l[a] - lse;
        out[(size_t)(32 + row) * B_BATCH + b] = ent;
    }
    for (int w = 0; w < 8; ++w) l[w] = (dq[w] + bop[w]) * 0.2f;
    {
        const float* g1 = gum + ((size_t)(2 * s + 1) * B_BATCH + b) * 8;
        float m = l[0]; for (int w = 1; w < 8; ++w) m = fmaxf(m, l[w]);
        float sum = 0.f; for (int w = 0; w < 8; ++w) sum += expf(l[w] - m);
        float lse = m + logf(sum);
        float ent = 0.f;
        for (int w = 0; w < 8; ++w){ float lp = l[w] - lse; ent -= lp * expf(lp); }
        int a = 0; float best = l[0] + g1[0];
        for (int w = 1; w < 8; ++w){ float v = l[w] + g1[w]; if (v > best){ best = v; a = w; } }
        int row = 2 * s + 1;
        out[(size_t)row * B_BATCH + b]        = (float)a;
        out[(size_t)(16 + row) * B_BATCH + b] = l[a] - lse;
        out[(size_t)(32 + row) * B_BATCH + b] = ent;
        g_tok[b] = a;
    }
}

// ---------------- host: tensormap construction via dlopen(libcuda) ----------------
typedef CUresult (*EncodeTiledFn)(CUtensorMap*, CUtensorMapDataType, cuuint32_t, void*,
                                  const cuuint64_t*, const cuuint64_t*, const cuuint32_t*,
                                  const cuuint32_t*, CUtensorMapInterleave, CUtensorMapSwizzle,
                                  CUtensorMapL2promotion, CUtensorMapFloatOOBfill);

static EncodeTiledFn get_encoder(){
    void* h = dlopen("libcuda.so.1", RTLD_LAZY | RTLD_GLOBAL);
    if (!h) h = dlopen("libcuda.so", RTLD_LAZY | RTLD_GLOBAL);
    if (!h) return nullptr;
    return (EncodeTiledFn)dlsym(h, "cuTensorMapEncodeTiled");
}

static void make_map(EncodeTiledFn enc, CUtensorMap* m, void* base,
                     uint64_t rows, uint32_t box_rows){
    cuuint64_t dims[2]    = {(cuuint64_t)HID, (cuuint64_t)rows};
    cuuint64_t strides[1] = {(cuuint64_t)HID * 4};
    cuuint32_t box[2]     = {KC, box_rows};
    cuuint32_t es[2]      = {1, 1};
    enc(m, CU_TENSOR_MAP_DATA_TYPE_FLOAT32, 2, base, dims, strides, box, es,
        CU_TENSOR_MAP_INTERLEAVE_NONE, CU_TENSOR_MAP_SWIZZLE_128B,
        CU_TENSOR_MAP_L2_PROMOTION_L2_128B, CU_TENSOR_MAP_FLOAT_OOB_FILL_NONE);
}

// ---------------- launch ----------------
extern "C" void kernel_launch(void* const* d_in, const int* in_sizes, int n_in,
                              void* d_out, int out_size){
    const float* emb  = (const float*)d_in[0];
    const float* w_ih = (const float*)d_in[1];
    const float* w_hh = (const float*)d_in[2];
    const float* b_ih = (const float*)d_in[3];
    const float* b_hh = (const float*)d_in[4];
    const float* wn[4] = {(const float*)d_in[5], (const float*)d_in[7],
                          (const float*)d_in[9], (const float*)d_in[11]};
    const float* bn[4] = {(const float*)d_in[6], (const float*)d_in[8],
                          (const float*)d_in[10], (const float*)d_in[12]};
    const float* wop = (const float*)d_in[13];
    const float* bop = (const float*)d_in[14];
    const float* gum = (const float*)d_in[15];
    float* out = (float*)d_out;

    EncodeTiledFn enc = get_encoder();
    void *pAh, *pAl, *pBh, *pBl, *pHd, *pCd;
    cudaGetSymbolAddress(&pAh, g_Ah);
    cudaGetSymbolAddress(&pAl, g_Al);
    cudaGetSymbolAddress(&pBh, g_Bh);
    cudaGetSymbolAddress(&pBl, g_Bl);
    cudaGetSymbolAddress(&pHd, g_Hd);
    cudaGetSymbolAddress(&pCd, g_Cd);
    CUtensorMap mAh[2], mAl[2], mBh, mBl;
    size_t buf = (size_t)B_BATCH * HID * 4;
    make_map(enc, &mAh[0], (char*)pAh,       B_BATCH, BM);
    make_map(enc, &mAh[1], (char*)pAh + buf, B_BATCH, BM);
    make_map(enc, &mAl[0], (char*)pAl,       B_BATCH, BM);
    make_map(enc, &mAl[1], (char*)pAl + buf, B_BATCH, BM);
    make_map(enc, &mBh, pBh, G4, BN);
    make_map(enc, &mBl, pBl, G4, BN);

    float* Hd0 = (float*)pHd;
    float* Hd1 = (float*)pHd + 512 * HID;
    float* Cd0 = (float*)pCd;
    float* Cd1 = (float*)pCd + 512 * HID;

    cudaFuncSetAttribute(lstm_step_tma, cudaFuncAttributeMaxDynamicSharedMemorySize, SMEM_TOTAL);

    precompute_E<<<dim3(G4 / 256, 9), 256>>>(emb, w_ih, b_ih, b_hh);
    split_B<<<G4, 256>>>(w_hh);

    // step 0: rank-1
    step0_compute<<<1, 512>>>(wn[0], bn[0], wop, bop);
    step0_sample<<<B_BATCH / 256, 256>>>(gum, out);

    // steps 1-3: distinct-state pipeline
    dstep_gemm<<<dim3(8, 1), 256>>>(w_hh, Hd0, 1);
    dstep_point<<<8, 128>>>(1, 2, wn[0], bn[0], wop, bop, Hd1, Cd1, Cd0);
    dsample<<<B_BATCH / 256, 256>>>(1, 8, 2, gum, out);

    dstep_gemm<<<dim3(8, 1), 256>>>(w_hh, Hd1, 8);
    dstep_point<<<64, 128>>>(8, 3, wn[1], bn[1], wop + 8 * HID, bop + 8, Hd0, Cd0, Cd1);
    dsample<<<B_BATCH / 256, 256>>>(2, 64, 3, gum, out);

    dstep_gemm<<<dim3(8, 8), 256>>>(w_hh, Hd0, 64);
    dstep_point<<<512, 128>>>(64, 3, wn[1], bn[1], wop + 8 * HID, bop + 8, Hd1, Cd1, Cd0);
    dsample<<<B_BATCH / 256, 256>>>(3, 512, 3, gum, out);

    materialize<<<2048, 256>>>();

    // step 4 (no in-kernel finalize; tokens already valid from dsample(3))
    lstm_step_tma<<<dim3(G4 / BN, B_BATCH / BM), 256, SMEM_TOTAL>>>(
        0, 4, 0, 0, 0, wn[2], wop + (size_t)2 * 8 * HID,
        nullptr, nullptr, gum, out, mAh[0], mAl[0], mBh, mBl);

    // steps 5-7 with fused finalize of the previous step
    for (int s = 5; s < 8; ++s){
        int i = s >> 1;
        int iP = (s - 1) >> 1;
        int ping = s & 1;
        lstm_step_tma<<<dim3(G4 / BN, B_BATCH / BM), 256, SMEM_TOTAL>>>(
            ping, i + 2, 1, iP + 2, s - 1,
            wn[i], wop + (size_t)i * 8 * HID,
            bn[iP], bop + iP * 8, gum, out,
            mAh[ping], mAl[ping], mBh, mBl);
    }
    finalize_kernel<<<B_BATCH / 256, 256>>>(bn[3], 5, bop + 24, gum, 7, out);
}

// round 14
// speedup vs baseline: 2.4421x; 1.1057x over previous
#include <cuda_runtime.h>
#include <cuda.h>
#include <dlfcn.h>
#include <cstdint>
#include <math.h>

#define B_BATCH 4096
#define HID     512
#define G4      2048
#define BM      128
#define BN      256
#define KC      32
#define NCHUNK  16
#define NTILES  1024      // 4 steps x 256 tiles
#define NWORK   148

#define STG_BYTES  98304
#define STG(s)     ((s) * STG_BYTES)
#define OFF_AHI    0
#define OFF_ALO    16384
#define OFF_BHI    32768
#define OFF_BLO    65536
#define OFF_MBAR   196608
#define OFF_ES     196672
#define ES_PITCH   260
#define OFF_DWS    (OFF_ES + 9 * ES_PITCH * 4)
#define SMEM_TOTAL (OFF_DWS + 13 * 64 * 4)
#define D_PITCH    264
#define CHUNK_BYTES 98304u

// ---------------- device scratch ----------------
__device__ __align__(1024) float g_E[9 * G4];
__device__ __align__(1024) float g_c[B_BATCH * HID];
__device__ __align__(1024) float g_Ah[2][B_BATCH * HID];
__device__ __align__(1024) float g_Al[2][B_BATCH * HID];
__device__ __align__(1024) float g_Bh[G4 * HID];
__device__ __align__(1024) float g_Bl[G4 * HID];
__device__ __align__(1024) float g_part[8 * B_BATCH * 16];
__device__ __align__(1024) float g_Hd[2][512 * HID];
__device__ __align__(1024) float g_Cd[2][512 * HID];
__device__ __align__(1024) float g_G[64 * G4];
__device__ float g_dlog[512 * 20];
__device__ float g_dec0[16];
__device__ int g_tok[B_BATCH];
__device__ int g_key[B_BATCH];
__device__ int g_done[32];
__device__ int g_ready[4][32];
__device__ int g_ticket;

// ---------------- helpers ----------------
__device__ __forceinline__ uint32_t smem_u32(const void* p){
    uint32_t a; asm("{ .reg .u64 t; cvta.to.shared.u64 t, %1; cvt.u32.u64 %0, t; }" : "=r"(a) : "l"(p));
    return a;
}
__device__ __forceinline__ float tf32_rna(float x){
    uint32_t t; asm("cvt.rna.tf32.f32 %0, %1;" : "=r"(t) : "f"(x));
    return __uint_as_float(t);
}
__device__ __forceinline__ float sigf(float x){ return __fdividef(1.0f, 1.0f + __expf(-x)); }
__device__ __forceinline__ float tanhfa(float x){ return 2.0f * __fdividef(1.0f, 1.0f + __expf(-2.0f * x)) - 1.0f; }

#define LDSM4(r0, r1, r2, r3, addr) \
    asm volatile("ldmatrix.sync.aligned.m8n8.x4.shared.b16 {%0,%1,%2,%3}, [%4];" \
        : "=r"(r0), "=r"(r1), "=r"(r2), "=r"(r3) : "r"(addr))

#define MMA_TF32(d, a, b) \
    asm volatile("mma.sync.aligned.m16n8k8.row.col.f32.tf32.tf32.f32 " \
        "{%0,%1,%2,%3}, {%4,%5,%6,%7}, {%8,%9}, {%0,%1,%2,%3};" \
        : "+f"((d)[0]), "+f"((d)[1]), "+f"((d)[2]), "+f"((d)[3]) \
        : "r"((a)[0]), "r"((a)[1]), "r"((a)[2]), "r"((a)[3]), "r"((b)[0]), "r"((b)[1]))

#define MBAR_INIT(mb, n) asm volatile("mbarrier.init.shared.b64 [%0], %1;" :: "r"((uint32_t)(mb)), "r"((uint32_t)(n)) : "memory")
#define MBAR_EXPECT_TX(mb, bytes) asm volatile("mbarrier.arrive.expect_tx.shared.b64 _, [%0], %1;" :: "r"((uint32_t)(mb)), "r"((uint32_t)(bytes)) : "memory")
#define MBAR_ARRIVE(mb) asm volatile("mbarrier.arrive.shared.b64 _, [%0];" :: "r"((uint32_t)(mb)) : "memory")
#define MBAR_WAIT(mb, par) do { \
    uint32_t _m = (uint32_t)(mb); uint32_t _p = (uint32_t)(par); uint32_t _d; \
    asm volatile("{\n\t.reg .pred p;\n\tmbarrier.try_wait.parity.acquire.cta.shared::cta.b64 p, [%1], %2;\n\tselp.b32 %0, 1, 0, p;\n\t}" \
        : "=r"(_d) : "r"(_m), "r"(_p) : "memory"); \
    if (!_d) { \
        asm volatile("{\n\t.reg .pred P1;\n\tWL_%=:\n\tmbarrier.try_wait.parity.acquire.cta.shared::cta.b64 P1, [%0], %1, 0x989680;\n\t@P1 bra.uni WD_%=;\n\tbra.uni WL_%=;\n\tWD_%=:\n\t}" \
            :: "r"(_m), "r"(_p) : "memory"); \
    } } while (0)

#define TMA_2D(dst, map, cx, cy, mb) \
    asm volatile("cp.async.bulk.tensor.2d.shared::cta.global.tile.mbarrier::complete_tx::bytes " \
        "[%0], [%1, {%2, %3}], [%4];" \
        :: "r"((uint32_t)(dst)), "l"(map), "r"((int32_t)(cx)), "r"((int32_t)(cy)), "r"((uint32_t)(mb)) : "memory")

// ---------------- E = emb @ w_ih^T + b_ih + b_hh ----------------
__global__ void precompute_E(const float* __restrict__ emb, const float* __restrict__ w_ih,
                             const float* __restrict__ b_ih, const float* __restrict__ b_hh){
    __shared__ float er[HID];
    int t = blockIdx.y;
    int j = blockIdx.x * blockDim.x + threadIdx.x;
    for (int k = threadIdx.x; k < HID; k += blockDim.x) er[k] = emb[t * HID + k];
    __syncthreads();
    const float* w = w_ih + (size_t)j * HID;
    float s = 0.f;
    #pragma unroll 4
    for (int k = 0; k < HID; k += 4){
        float4 wv = *(const float4*)(w + k);
        s += er[k]*wv.x + er[k+1]*wv.y + er[k+2]*wv.z + er[k+3]*wv.w;
    }
    g_E[t * G4 + j] = s + b_ih[j] + b_hh[j];
}

// ---------------- split + permute w_hh ----------------
__global__ void split_B(const float* __restrict__ w_hh){
    int r = blockIdx.x;
    int t = r >> 8, n = r & 255;
    int srow = (n >> 6) * HID + t * 64 + (n & 63);
    const float* s = w_hh + (size_t)srow * HID;
    float* dh = g_Bh + (size_t)r * HID;
    float* dl = g_Bl + (size_t)r * HID;
    for (int k = threadIdx.x; k < HID; k += blockDim.x){
        float w = s[k];
        float hi = tf32_rna(w);
        dh[k] = hi;
        dl[k] = tf32_rna(w - hi);
    }
}

// ---------------- step 0 ----------------
__global__ void step0_compute(const float* __restrict__ wn2, const float* __restrict__ bn2,
                              const float* __restrict__ wop0, const float* __restrict__ bop0){
    __shared__ float sh[HID];
    __shared__ float lg[10];
    int k = threadIdx.x;
    float i_ = sigf(g_E[k]);
    float gg = tanhfa(g_E[1024 + k]);
    float o_ = sigf(g_E[1536 + k]);
    float cc = i_ * gg;
    float hh = o_ * tanhfa(cc);
    sh[k] = hh;
    g_Hd[0][k] = hh;
    g_Cd[0][k] = cc;
    __syncthreads();
    int wid = k >> 5, lane = k & 31;
    if (wid < 10){
        const float* wr = (wid < 2) ? wn2 + wid * HID : wop0 + (wid - 2) * HID;
        float s = 0.f;
        #pragma unroll
        for (int j = 0; j < 16; ++j){
            int col = lane + (j << 5);
            s += sh[col] * wr[col];
        }
        #pragma unroll
        for (int off = 16; off > 0; off >>= 1) s += __shfl_xor_sync(0xffffffffu, s, off);
        if (lane == 0) lg[wid] = s;
    }
    __syncthreads();
    if (k == 0){
        float l0[2], l1[8];
        for (int w = 0; w < 2; ++w) l0[w] = 2.5f * tanhf((lg[w] + bn2[w]) * 0.2f);
        for (int w = 0; w < 8; ++w) l1[w] = (lg[2 + w] + bop0[w]) * 0.2f;
        float m0 = fmaxf(l0[0], l0[1]);
        float s0 = expf(l0[0] - m0) + expf(l0[1] - m0);
        float lse0 = m0 + logf(s0);
        float e0 = 0.f;
        for (int w = 0; w < 2; ++w){ float lp = l0[w] - lse0; e0 -= lp * expf(lp); }
        float m1 = l1[0]; for (int w = 1; w < 8; ++w) m1 = fmaxf(m1, l1[w]);
        float s1 = 0.f; for (int w = 0; w < 8; ++w) s1 += expf(l1[w] - m1);
        float lse1 = m1 + logf(s1);
        float e1 = 0.f;
        for (int w = 0; w < 8; ++w){ float lp = l1[w] - lse1; e1 -= lp * expf(lp); }
        g_dec0[0] = l0[0]; g_dec0[1] = l0[1];
        for (int w = 0; w < 8; ++w) g_dec0[2 + w] = l1[w];
        g_dec0[10] = lse0; g_dec0[11] = lse1;
        g_dec0[12] = e0;   g_dec0[13] = e1;
    }
}

__global__ void step0_sample(const float* __restrict__ gum, float* __restrict__ out){
    int b = blockIdx.x * 256 + threadIdx.x;
    float l0[2], l1[8];
    l0[0] = g_dec0[0]; l0[1] = g_dec0[1];
    #pragma unroll
    for (int w = 0; w < 8; ++w) l1[w] = g_dec0[2 + w];
    float lse0 = g_dec0[10], lse1 = g_dec0[11];
    float e0 = g_dec0[12], e1 = g_dec0[13];
    const float* g0 = gum + (size_t)b * 8;
    const float* g1 = gum + ((size_t)B_BATCH + b) * 8;
    int a0 = (l0[1] + g0[1] > l0[0] + g0[0]) ? 1 : 0;
    out[b]                         = (float)a0;
    out[(size_t)16 * B_BATCH + b]  = l0[a0] - lse0;
    out[(size_t)32 * B_BATCH + b]  = e0;
    int a1 = 0; float best = l1[0] + g1[0];
    #pragma unroll
    for (int w = 1; w < 8; ++w){ float v = l1[w] + g1[w]; if (v > best){ best = v; a1 = w; } }
    out[(size_t)1 * B_BATCH + b]   = (float)a1;
    out[(size_t)17 * B_BATCH + b]  = l1[a1] - lse1;
    out[(size_t)33 * B_BATCH + b]  = e1;
    g_key[b] = a1;
}

// ---------------- distinct-state steps 1..3 ----------------
__global__ __launch_bounds__(256)
void dstep_gemm(const float* __restrict__ w_hh, const float* __restrict__ Hd, int Kin){
    __shared__ float hs[8][HID];
    __shared__ float ws[256][17];
    int tid = threadIdx.x;
    int j0 = blockIdx.x * 256;
    int kb = blockIdx.y * 8;
    int nk = Kin - kb; if (nk > 8) nk = 8;
    for (int idx = tid; idx < nk * HID; idx += 256)
        hs[idx >> 9][idx & 511] = Hd[(size_t)(kb + (idx >> 9)) * HID + (idx & 511)];
    float acc[8] = {0,0,0,0,0,0,0,0};
    for (int kc = 0; kc < HID; kc += 16){
        __syncthreads();
        #pragma unroll
        for (int i = 0; i < 16; ++i){
            int e = tid + 256 * i;
            ws[e >> 4][e & 15] = w_hh[(size_t)(j0 + (e >> 4)) * HID + kc + (e & 15)];
        }
        __syncthreads();
        #pragma unroll
        for (int kl = 0; kl < 16; ++kl){
            float w = ws[tid][kl];
            #pragma unroll
            for (int q = 0; q < 8; ++q) acc[q] += w * hs[q][kc + kl];
        }
    }
    for (int q = 0; q < nk; ++q) g_G[(size_t)(kb + q) * G4 + j0 + tid] = acc[q];
}

__global__ __launch_bounds__(128)
void dstep_point(int Kin, int kd,
                 const float* __restrict__ wn, const float* __restrict__ bn,
                 const float* __restrict__ wop, const float* __restrict__ bop,
                 float* __restrict__ Hdo, float* __restrict__ Cdo,
                 const float* __restrict__ Cdi){
    __shared__ float sh[HID];
    __shared__ float hd[13];
    int kp = blockIdx.x;
    int k = kp % Kin, t = kp / Kin;
    int tid = threadIdx.x;
    const float* Gr = &g_G[(size_t)k * G4];
    const float* Er = &g_E[(size_t)t * G4];
    const float* Cr = &Cdi[(size_t)k * HID];
    #pragma unroll
    for (int e = 0; e < 4; ++e){
        int col = tid * 4 + e;
        float gi = Gr[col]        + Er[col];
        float gf = Gr[512 + col]  + Er[512 + col];
        float gg = Gr[1024 + col] + Er[1024 + col];
        float go = Gr[1536 + col] + Er[1536 + col];
        float i_ = sigf(gi), f_ = sigf(gf);
        float g_ = tanhfa(gg), o_ = sigf(go);
        float cc = f_ * Cr[col] + i_ * g_;
        float hh = o_ * tanhfa(cc);
        sh[col] = hh;
        Hdo[(size_t)kp * HID + col] = hh;
        Cdo[(size_t)kp * HID + col] = cc;
    }
    __syncthreads();
    int wid = tid >> 5, lane = tid & 31;
    for (int hx = wid; hx < 13; hx += 4){
        if (hx < 5 && hx >= kd) continue;
        const float* wr = (hx < 5) ? wn + hx * HID : wop + (hx - 5) * HID;
        float s = 0.f;
        #pragma unroll
        for (int j = 0; j < 16; ++j){
            int col = lane + (j << 5);
            s += sh[col] * wr[col];
        }
        #pragma unroll
        for (int off = 16; off > 0; off >>= 1) s += __shfl_xor_sync(0xffffffffu, s, off);
        if (lane == 0) hd[hx] = s;
    }
    __syncthreads();
    if (tid == 0){
        float* dl = &g_dlog[kp * 20];
        float ln[5], lo[8];
        for (int w = 0; w < kd; ++w) ln[w] = 2.5f * tanhf((hd[w] + bn[w]) * 0.2f);
        for (int w = 0; w < 8; ++w)  lo[w] = (hd[5 + w] + bop[w]) * 0.2f;
        float m = ln[0]; for (int w = 1; w < kd; ++w) m = fmaxf(m, ln[w]);
        float sum = 0.f; for (int w = 0; w < kd; ++w) sum += expf(ln[w] - m);
        float lse_n = m + logf(sum);
        float ent_n = 0.f;
        for (int w = 0; w < kd; ++w){ float lp = ln[w] - lse_n; ent_n -= lp * expf(lp); }
        m = lo[0]; for (int w = 1; w < 8; ++w) m = fmaxf(m, lo[w]);
        sum = 0.f; for (int w = 0; w < 8; ++w) sum += expf(lo[w] - m);
        float lse_o = m + logf(sum);
        float ent_o = 0.f;
        for (int w = 0; w < 8; ++w){ float lp = lo[w] - lse_o; ent_o -= lp * expf(lp); }
        for (int w = 0; w < kd; ++w) dl[w] = ln[w];
        for (int w = 0; w < 8; ++w)  dl[5 + w] = lo[w];
        dl[13] = lse_n; dl[14] = lse_o; dl[15] = ent_n; dl[16] = ent_o;
    }
}

__global__ void dsample(int s, int K, int kd, const float* __restrict__ gum, float* __restrict__ out){
    int b = blockIdx.x * 256 + threadIdx.x;
    int k = g_key[b];
    const float* dl = &g_dlog[k * 20];
    const float* g0 = gum + ((size_t)(2 * s) * B_BATCH + b) * 8;
    int a = 0; float best = dl[0] + g0[0];
    for (int w = 1; w < kd; ++w){ float v = dl[w] + g0[w]; if (v > best){ best = v; a = w; } }
    int row = 2 * s;
    out[(size_t)row * B_BATCH + b]        = (float)a;
    out[(size_t)(16 + row) * B_BATCH + b] = dl[a] - dl[13];
    out[(size_t)(32 + row) * B_BATCH + b] = dl[15];
    const float* g1 = gum + ((size_t)(2 * s + 1) * B_BATCH + b) * 8;
    a = 0; best = dl[5] + g1[0];
    #pragma unroll
    for (int w = 1; w < 8; ++w){ float v = dl[5 + w] + g1[w]; if (v > best){ best = v; a = w; } }
    row = 2 * s + 1;
    out[(size_t)row * B_BATCH + b]        = (float)a;
    out[(size_t)(16 + row) * B_BATCH + b] = dl[5 + a] - dl[14];
    out[(size_t)(32 + row) * B_BATCH + b] = dl[16];
    g_key[b] = k + K * a;
    g_tok[b] = a;
}

__global__ void materialize(){
    int idx = blockIdx.x * blockDim.x + threadIdx.x;
    if (idx == 0) g_ticket = 0;
    if (idx < 128) ((int*)g_ready)[idx] = 0;
    int r  = idx >> 7;
    int c4 = (idx & 127) << 2;
    int k = g_key[r] & 511;
    float4 h4 = *(const float4*)&g_Hd[1][(size_t)k * HID + c4];
    float4 cv = *(const float4*)&g_Cd[1][(size_t)k * HID + c4];
    float4 ah, al;
    #pragma unroll
    for (int e = 0; e < 4; ++e){
        float hh = (&h4.x)[e];
        float hi = tf32_rna(hh);
        (&ah.x)[e] = hi;
        (&al.x)[e] = tf32_rna(hh - hi);
    }
    size_t gb = ((size_t)r << 9) + c4;
    *(float4*)&g_c[gb]     = cv;
    *(float4*)&g_Ah[0][gb] = ah;
    *(float4*)&g_Al[0][gb] = al;
}

// ---------------- persistent mega-kernel: steps 4..7 ----------------
__global__ __launch_bounds__(256, 1)
void mega_step(const float* __restrict__ wn2p, const float* __restrict__ wn3p,
               const float* __restrict__ bn2p, const float* __restrict__ bn3p,
               const float* __restrict__ wop, const float* __restrict__ bop,
               const float* __restrict__ gum, float* __restrict__ out,
               const __grid_constant__ CUtensorMap mAh0,
               const __grid_constant__ CUtensorMap mAh1,
               const __grid_constant__ CUtensorMap mAl0,
               const __grid_constant__ CUtensorMap mAl1,
               const __grid_constant__ CUtensorMap mBh,
               const __grid_constant__ CUtensorMap mBl){
    extern __shared__ __align__(1024) char smem[];
    uint32_t sb = smem_u32(smem);
    int tid = threadIdx.x, wid = tid >> 5, lane = tid & 31;

    float* Es  = (float*)(smem + OFF_ES);
    float* dws = (float*)(smem + OFF_DWS);
    __shared__ int s_tile;

    uint32_t fullb  = sb + OFF_MBAR;
    uint32_t emptyb = sb + OFF_MBAR + 16;
    if (tid == 0){
        MBAR_INIT(fullb, 1);
        MBAR_INIT(fullb + 8, 1);
        MBAR_INIT(emptyb, 8);
        MBAR_INIT(emptyb + 8, 8);
    }
    __syncthreads();

    int pfA = 0, pfB = 0;   // full-barrier parity (all threads)
    int peA = 0, peB = 0;   // empty-barrier parity (tid 0 only)
    int first = 1;

    int wm = wid >> 2, wn = wid & 3;
    int mat = lane >> 3, r8 = lane & 7;
    int rowA[4];
    #pragma unroll
    for (int f = 0; f < 4; ++f) rowA[f] = wm * 64 + f * 16 + ((mat & 1) << 3) + r8;
    int usA = mat >> 1;
    int rowB[4];
    #pragma unroll
    for (int p = 0; p < 4; ++p) rowB[p] = wn * 64 + (p * 2 + (mat >> 1)) * 8 + r8;
    int usB = mat & 1;

    for (;;){
        if (tid == 0) s_tile = atomicAdd(&g_ticket, 1);
        __syncthreads();
        int t = s_tile;
        if (t >= NTILES) break;
        int s  = 4 + (t >> 8);
        int r  = t & 255;
        int bx = r & 7;
        int y  = r >> 3;
        int R0 = y * BM;
        int N0 = bx * BN;
        int c0 = bx * 64;
        int sIn = s & 1;
        int i  = s >> 1;           // 2 or 3
        int kd = i + 2;
        const float* wnp  = (i == 2) ? wn2p : wn3p;
        const float* wopp = wop + (size_t)i * 8 * HID;
        const CUtensorMap* pAh = sIn ? &mAh1 : &mAh0;
        const CUtensorMap* pAl = sIn ? &mAl1 : &mAl0;

        // dep wait: all 8 column tiles of (s-1, y) complete
        if (s > 4 && tid == 0){
            while (atomicAdd(&g_ready[s - 5][y], 0) != 8) {}
            __threadfence();
        }
        __syncthreads();

        // TMA prologue: chunks 0,1 (wait empties from previous tile unless first)
        if (tid == 0){
            if (!first){ MBAR_WAIT(emptyb, peA); peA ^= 1; }
            MBAR_EXPECT_TX(fullb, CHUNK_BYTES);
            TMA_2D(sb + STG(0) + OFF_AHI, pAh, 0, R0, fullb);
            TMA_2D(sb + STG(0) + OFF_ALO, pAl, 0, R0, fullb);
            TMA_2D(sb + STG(0) + OFF_BHI, &mBh, 0, N0, fullb);
            TMA_2D(sb + STG(0) + OFF_BLO, &mBl, 0, N0, fullb);
            if (!first){ MBAR_WAIT(emptyb + 8, peB); peB ^= 1; }
            MBAR_EXPECT_TX(fullb + 8, CHUNK_BYTES);
            TMA_2D(sb + STG(1) + OFF_AHI, pAh, KC, R0, fullb + 8);
            TMA_2D(sb + STG(1) + OFF_ALO, pAl, KC, R0, fullb + 8);
            TMA_2D(sb + STG(1) + OFF_BHI, &mBh, KC, N0, fullb + 8);
            TMA_2D(sb + STG(1) + OFF_BLO, &mBl, KC, N0, fullb + 8);
        }

        // in-kernel finalize for step s-1 (bx==0 tiles, warps 4-7)
        if (s > 4 && bx == 0 && tid >= 128){
            int iP = (s - 1) >> 1;
            int kdPrev = iP + 2;
            const float* bnPrev  = (iP == 2) ? bn2p : bn3p;
            const float* bopPrev = bop + iP * 8;
            int b = R0 + tid - 128;
            float dn[5] = {0,0,0,0,0};
            float dq[8] = {0,0,0,0,0,0,0,0};
            #pragma unroll
            for (int bx2 = 0; bx2 < 8; ++bx2){
                const float4* p = (const float4*)&g_part[((size_t)bx2 * B_BATCH + b) * 16];
                float4 p0 = p[0], p1 = p[1], p2 = p[2], p3 = p[3];
                dn[0] += p0.x; dn[1] += p0.y; dn[2] += p0.z; dn[3] += p0.w;
                dn[4] += p1.x;
                dq[0] += p1.y; dq[1] += p1.z; dq[2] += p1.w;
                dq[3] += p2.x; dq[4] += p2.y; dq[5] += p2.z; dq[6] += p2.w;
                dq[7] += p3.x;
            }
            float l[8];
            for (int w = 0; w < kdPrev; ++w) l[w] = 2.5f * tanhf((dn[w] + bnPrev[w]) * 0.2f);
            {
                const float* g0 = gum + ((size_t)(2 * (s - 1)) * B_BATCH + b) * 8;
                float m = l[0]; for (int w = 1; w < kdPrev; ++w) m = fmaxf(m, l[w]);
                float sum = 0.f; for (int w = 0; w < kdPrev; ++w) sum += expf(l[w] - m);
                float lse = m + logf(sum);
                float ent = 0.f;
                for (int w = 0; w < kdPrev; ++w){ float lp = l[w] - lse; ent -= lp * expf(lp); }
                int a = 0; float best = l[0] + g0[0];
                for (int w = 1; w < kdPrev; ++w){ float v = l[w] + g0[w]; if (v > best){ best = v; a = w; } }
                int rw = 2 * (s - 1);
                out[(size_t)rw * B_BATCH + b]        = (float)a;
                out[(size_t)(16 + rw) * B_BATCH + b] = l[a] - lse;
                out[(size_t)(32 + rw) * B_BATCH + b] = ent;
            }
            for (int w = 0; w < 8; ++w) l[w] = (dq[w] + bopPrev[w]) * 0.2f;
            {
                const float* g1 = gum + ((size_t)(2 * (s - 1) + 1) * B_BATCH + b) * 8;
                float m = l[0]; for (int w = 1; w < 8; ++w) m = fmaxf(m, l[w]);
                float sum = 0.f; for (int w = 0; w < 8; ++w) sum += expf(l[w] - m);
                float lse = m + logf(sum);
                float ent = 0.f;
                for (int w = 0; w < 8; ++w){ float lp = l[w] - lse; ent -= lp * expf(lp); }
                int a = 0; float best = l[0] + g1[0];
                for (int w = 1; w < 8; ++w){ float v = l[w] + g1[w]; if (v > best){ best = v; a = w; } }
                int rw = 2 * (s - 1) + 1;
                out[(size_t)rw * B_BATCH + b]        = (float)a;
                out[(size_t)(16 + rw) * B_BATCH + b] = l[a] - lse;
                out[(size_t)(32 + rw) * B_BATCH + b] = ent;
                g_tok[b] = a;
            }
            asm volatile("bar.sync 1, 128;" ::: "memory");
            if (tid == 128){
                __threadfence();
                atomicExch(&g_done[y], s);
            }
        }

        // prologue gathers (overlap TMA flight)
        for (int idx = tid; idx < 9 * 256; idx += 256){
            int tt = idx >> 8, n = idx & 255;
            Es[tt * ES_PITCH + n] = g_E[tt * G4 + (n >> 6) * HID + c0 + (n & 63)];
        }
        for (int idx = tid; idx < 13 * 64; idx += 256){
            int w = idx >> 6, j = idx & 63;
            float v;
            if (w < 5) v = (w < kd) ? wnp[w * HID + c0 + j] : 0.0f;
            else       v = wopp[(w - 5) * HID + c0 + j];
            dws[idx] = v;
        }

        float acc[4][8][4];
        #pragma unroll
        for (int f = 0; f < 4; ++f)
            #pragma unroll
            for (int j = 0; j < 8; ++j)
                #pragma unroll
                for (int e = 0; e < 4; ++e) acc[f][j][e] = 0.0f;

        #pragma unroll 1
        for (int c = 0; c < NCHUNK; ++c){
            int stg = c & 1;
            if (stg == 0){ MBAR_WAIT(fullb, pfA); pfA ^= 1; }
            else         { MBAR_WAIT(fullb + 8, pfB); pfB ^= 1; }

            uint32_t ahi_b = sb + STG(stg) + OFF_AHI;
            uint32_t alo_b = sb + STG(stg) + OFF_ALO;
            uint32_t bhi_b = sb + STG(stg) + OFF_BHI;
            uint32_t blo_b = sb + STG(stg) + OFF_BLO;

            #pragma unroll
            for (int ss = 0; ss < 4; ++ss){
                int ku = ss * 2;
                uint32_t ah[4][4], bh[8][2];
                #pragma unroll
                for (int f = 0; f < 4; ++f){
                    uint32_t ad = ahi_b + rowA[f] * 128 + (((ku + usA) ^ r8) << 4);
                    LDSM4(ah[f][0], ah[f][1], ah[f][2], ah[f][3], ad);
                }
                #pragma unroll
                for (int p = 0; p < 4; ++p){
                    uint32_t bd = bhi_b + rowB[p] * 128 + (((ku + usB) ^ r8) << 4);
                    LDSM4(bh[2*p][0], bh[2*p][1], bh[2*p+1][0], bh[2*p+1][1], bd);
                }
                #pragma unroll
                for (int f = 0; f < 4; ++f)
                    #pragma unroll
                    for (int j = 0; j < 8; ++j)
                        MMA_TF32(acc[f][j], ah[f], bh[j]);
                {
                    uint32_t al[4][4];
                    #pragma unroll
                    for (int f = 0; f < 4; ++f){
                        uint32_t ad = alo_b + rowA[f] * 128 + (((ku + usA) ^ r8) << 4);
                        LDSM4(al[f][0], al[f][1], al[f][2], al[f][3], ad);
                    }
                    #pragma unroll
                    for (int f = 0; f < 4; ++f)
                        #pragma unroll
                        for (int j = 0; j < 8; ++j)
                            MMA_TF32(acc[f][j], al[f], bh[j]);
                }
                {
                    uint32_t bl[8][2];
                    #pragma unroll
                    for (int p = 0; p < 4; ++p){
                        uint32_t bd = blo_b + rowB[p] * 128 + (((ku + usB) ^ r8) << 4);
                        LDSM4(bl[2*p][0], bl[2*p][1], bl[2*p+1][0], bl[2*p+1][1], bd);
                    }
                    #pragma unroll
                    for (int f = 0; f < 4; ++f)
                        #pragma unroll
                        for (int j = 0; j < 8; ++j)
                            MMA_TF32(acc[f][j], ah[f], bl[j]);
                }
            }

            // warp done with this stage's smem (final two chunks arrive after epilogue)
            if (lane == 0 && c < NCHUNK - 2) MBAR_ARRIVE(emptyb + stg * 8);
            if (tid == 0 && c + 2 < NCHUNK){
                if (stg == 0){ MBAR_WAIT(emptyb, peA); peA ^= 1; }
                else         { MBAR_WAIT(emptyb + 8, peB); peB ^= 1; }
                int cn = c + 2;
                uint32_t mb = fullb + stg * 8;
                uint32_t st = sb + STG(stg);
                MBAR_EXPECT_TX(mb, CHUNK_BYTES);
                TMA_2D(st + OFF_AHI, pAh, cn * KC, R0, mb);
                TMA_2D(st + OFF_ALO, pAl, cn * KC, R0, mb);
                TMA_2D(st + OFF_BHI, &mBh, cn * KC, N0, mb);
                TMA_2D(st + OFF_BLO, &mBl, cn * KC, N0, mb);
            }
        }

        // token wait (sibling tiles of bx==0's finalize)
        if (s > 4 && bx != 0 && tid == 0){
            while (atomicAdd(&g_done[y], 0) != s) {}
            __threadfence();
        }
        __syncthreads();
        float* Ds = (float*)smem;
        #pragma unroll
        for (int f = 0; f < 4; ++f){
            int r0 = wm * 64 + f * 16 + (lane >> 2);
            #pragma unroll
            for (int j = 0; j < 8; ++j){
                int cb = wn * 64 + j * 8 + 2 * (lane & 3);
                *(float2*)&Ds[r0 * D_PITCH + cb]       = make_float2(acc[f][j][0], acc[f][j][1]);
                *(float2*)&Ds[(r0 + 8) * D_PITCH + cb] = make_float2(acc[f][j][2], acc[f][j][3]);
            }
        }
        __syncthreads();

        int row  = tid >> 1;
        int j0   = (tid & 1) * 32;
        int tk   = g_tok[R0 + row];
        const float* Ep = &Es[tk * ES_PITCH];
        const float* Dr = &Ds[row * D_PITCH];
        size_t gb = ((size_t)(R0 + row) << 9) + c0;
        float* Aho = &g_Ah[sIn ^ 1][0];
        float* Alo_o = &g_Al[sIn ^ 1][0];
        float hbuf[32];
        #pragma unroll
        for (int jj = 0; jj < 32; jj += 4){
            int j = j0 + jj;
            float4 iv = *(const float4*)&Dr[j];
            float4 fv = *(const float4*)&Dr[64 + j];
            float4 gv = *(const float4*)&Dr[128 + j];
            float4 ov = *(const float4*)&Dr[192 + j];
            float4 cv = *(const float4*)&g_c[gb + j];
            float4 cn, ah, al;
            #pragma unroll
            for (int e = 0; e < 4; ++e){
                float i_ = sigf((&iv.x)[e] + Ep[j + e]);
                float f_ = sigf((&fv.x)[e] + Ep[64 + j + e]);
                float gg = tanhfa((&gv.x)[e] + Ep[128 + j + e]);
                float o_ = sigf((&ov.x)[e] + Ep[192 + j + e]);
                float cc = f_ * ((&cv.x)[e]) + i_ * gg;
                float hh = o_ * tanhfa(cc);
                float hi = tf32_rna(hh);
                hbuf[jj + e] = hh;
                (&cn.x)[e] = cc;
                (&ah.x)[e] = hi; (&al.x)[e] = tf32_rna(hh - hi);
            }
            *(float4*)&g_c[gb + j]   = cn;
            *(float4*)&Aho[gb + j]   = ah;
            *(float4*)&Alo_o[gb + j] = al;
        }

        float pd[13];
        #pragma unroll
        for (int w = 0; w < 13; ++w) pd[w] = 0.0f;
        #pragma unroll
        for (int jj = 0; jj < 32; ++jj){
            float hv = hbuf[jj];
            const float* dc = &dws[j0 + jj];
            #pragma unroll
            for (int w = 0; w < 13; ++w) pd[w] += hv * dc[w * 64];
        }
        #pragma unroll
        for (int w = 0; w < 13; ++w) pd[w] += __shfl_xor_sync(0xffffffffu, pd[w], 1);
        if ((tid & 1) == 0){
            float4* dst = (float4*)&g_part[((size_t)bx * B_BATCH + R0 + row) * 16];
            dst[0] = make_float4(pd[0], pd[1], pd[2], pd[3]);
            dst[1] = make_float4(pd[4], pd[5], pd[6], pd[7]);
            dst[2] = make_float4(pd[8], pd[9], pd[10], pd[11]);
            dst[3] = make_float4(pd[12], 0.f, 0.f, 0.f);
        }

        // release final stage buffers (epilogue Ds reads complete), publish tile
        __syncthreads();
        if (lane == 0){ MBAR_ARRIVE(emptyb); MBAR_ARRIVE(emptyb + 8); }
        if (tid == 0){
            __threadfence();
            atomicAdd(&g_ready[s - 4][y], 1);
        }
        first = 0;
    }
}

// ---------------- finalize (last step only) ----------------
__global__ __launch_bounds__(256)
void finalize_kernel(const float* __restrict__ bn, int k,
                     const float* __restrict__ bop,
                     const float* __restrict__ gum, int s, float* __restrict__ out){
    int b = blockIdx.x * 256 + threadIdx.x;
    float dn[5] = {0,0,0,0,0};
    float dq[8] = {0,0,0,0,0,0,0,0};
    #pragma unroll
    for (int bx = 0; bx < 8; ++bx){
        const float4* p = (const float4*)&g_part[((size_t)bx * B_BATCH + b) * 16];
        float4 p0 = p[0], p1 = p[1], p2 = p[2], p3 = p[3];
        dn[0] += p0.x; dn[1] += p0.y; dn[2] += p0.z; dn[3] += p0.w;
        dn[4] += p1.x;
        dq[0] += p1.y; dq[1] += p1.z; dq[2] += p1.w;
        dq[3] += p2.x; dq[4] += p2.y; dq[5] += p2.z; dq[6] += p2.w;
        dq[7] += p3.x;
    }
    float l[8];
    for (int w = 0; w < k; ++w) l[w] = 2.5f * tanhf((dn[w] + bn[w]) * 0.2f);
    {
        const float* g0 = gum + ((size_t)(2 * s) * B_BATCH + b) * 8;
        float m = l[0]; for (int w = 1; w < k; ++w) m = fmaxf(m, l[w]);
        float sum = 0.f; for (int w = 0; w < k; ++w) sum += expf(l[w] - m);
        float lse = m + logf(sum);
        float ent = 0.f;
        for (int w = 0; w < k; ++w){ float lp = l[w] - lse; ent -= lp * expf(lp); }
        int a = 0; float best = l[0] + g0[0];
        for (int w = 1; w < k; ++w){ float v = l[w] + g0[w]; if (v > best){ best = v; a = w; } }
        int row = 2 * s;
        out[(size_t)row * B_BATCH + b]        = (float)a;
        out[(size_t)(16 + row) * B_BATCH + b] = l[a] - lse;
        out[(size_t)(32 + row) * B_BATCH + b] = ent;
    }
    for (int w = 0; w < 8; ++w) l[w] = (dq[w] + bop[w]) * 0.2f;
    {
        const float* g1 = gum + ((size_t)(2 * s + 1) * B_BATCH + b) * 8;
        float m = l[0]; for (int w = 1; w < 8; ++w) m = fmaxf(m, l[w]);
        float sum = 0.f; for (int w = 0; w < 8; ++w) sum += expf(l[w] - m);
        float lse = m + logf(sum);
        float ent = 0.f;
        for (int w = 0; w < 8; ++w){ float lp = l[w] - lse; ent -= lp * expf(lp); }
        int a = 0; float best = l[0] + g1[0];
        for (int w = 1; w < 8; ++w){ float v = l[w] + g1[w]; if (v > best){ best = v; a = w; } }
        int row = 2 * s + 1;
        out[(size_t)row * B_BATCH + b]        = (float)a;
        out[(size_t)(16 + row) * B_BATCH + b] = l[a] - lse;
        out[(size_t)(32 + row) * B_BATCH + b] = ent;
        g_tok[b] = a;
    }
}

// ---------------- host: tensormap construction via dlopen(libcuda) ----------------
typedef CUresult (*EncodeTiledFn)(CUtensorMap*, CUtensorMapDataType, cuuint32_t, void*,
                                  const cuuint64_t*, const cuuint64_t*, const cuuint32_t*,
                                  const cuuint32_t*, CUtensorMapInterleave, CUtensorMapSwizzle,
                                  CUtensorMapL2promotion, CUtensorMapFloatOOBfill);

static EncodeTiledFn get_encoder(){
    void* h = dlopen("libcuda.so.1", RTLD_LAZY | RTLD_GLOBAL);
    if (!h) h = dlopen("libcuda.so", RTLD_LAZY | RTLD_GLOBAL);
    if (!h) return nullptr;
    return (EncodeTiledFn)dlsym(h, "cuTensorMapEncodeTiled");
}

static void make_map(EncodeTiledFn enc, CUtensorMap* m, void* base,
                     uint64_t rows, uint32_t box_rows){
    cuuint64_t dims[2]    = {(cuuint64_t)HID, (cuuint64_t)rows};
    cuuint64_t strides[1] = {(cuuint64_t)HID * 4};
    cuuint32_t box[2]     = {KC, box_rows};
    cuuint32_t es[2]      = {1, 1};
    enc(m, CU_TENSOR_MAP_DATA_TYPE_FLOAT32, 2, base, dims, strides, box, es,
        CU_TENSOR_MAP_INTERLEAVE_NONE, CU_TENSOR_MAP_SWIZZLE_128B,
        CU_TENSOR_MAP_L2_PROMOTION_L2_128B, CU_TENSOR_MAP_FLOAT_OOB_FILL_NONE);
}

// ---------------- launch ----------------
extern "C" void kernel_launch(void* const* d_in, const int* in_sizes, int n_in,
                              void* d_out, int out_size){
    const float* emb  = (const float*)d_in[0];
    const float* w_ih = (const float*)d_in[1];
    const float* w_hh = (const float*)d_in[2];
    const float* b_ih = (const float*)d_in[3];
    const float* b_hh = (const float*)d_in[4];
    const float* wn[4] = {(const float*)d_in[5], (const float*)d_in[7],
                          (const float*)d_in[9], (const float*)d_in[11]};
    const float* bn[4] = {(const float*)d_in[6], (const float*)d_in[8],
                          (const float*)d_in[10], (const float*)d_in[12]};
    const float* wop = (const float*)d_in[13];
    const float* bop = (const float*)d_in[14];
    const float* gum = (const float*)d_in[15];
    float* out = (float*)d_out;

    EncodeTiledFn enc = get_encoder();
    void *pAh, *pAl, *pBh, *pBl, *pHd, *pCd;
    cudaGetSymbolAddress(&pAh, g_Ah);
    cudaGetSymbolAddress(&pAl, g_Al);
    cudaGetSymbolAddress(&pBh, g_Bh);
    cudaGetSymbolAddress(&pBl, g_Bl);
    cudaGetSymbolAddress(&pHd, g_Hd);
    cudaGetSymbolAddress(&pCd, g_Cd);
    CUtensorMap mAh[2], mAl[2], mBh, mBl;
    size_t buf = (size_t)B_BATCH * HID * 4;
    make_map(enc, &mAh[0], (char*)pAh,       B_BATCH, BM);
    make_map(enc, &mAh[1], (char*)pAh + buf, B_BATCH, BM);
    make_map(enc, &mAl[0], (char*)pAl,       B_BATCH, BM);
    make_map(enc, &mAl[1], (char*)pAl + buf, B_BATCH, BM);
    make_map(enc, &mBh, pBh, G4, BN);
    make_map(enc, &mBl, pBl, G4, BN);

    float* Hd0 = (float*)pHd;
    float* Hd1 = (float*)pHd + 512 * HID;
    float* Cd0 = (float*)pCd;
    float* Cd1 = (float*)pCd + 512 * HID;

    cudaFuncSetAttribute(mega_step, cudaFuncAttributeMaxDynamicSharedMemorySize, SMEM_TOTAL);

    precompute_E<<<dim3(G4 / 256, 9), 256>>>(emb, w_ih, b_ih, b_hh);
    split_B<<<G4, 256>>>(w_hh);

    step0_compute<<<1, 512>>>(wn[0], bn[0], wop, bop);
    step0_sample<<<B_BATCH / 256, 256>>>(gum, out);

    dstep_gemm<<<dim3(8, 1), 256>>>(w_hh, Hd0, 1);
    dstep_point<<<8, 128>>>(1, 2, wn[0], bn[0], wop, bop, Hd1, Cd1, Cd0);
    dsample<<<B_BATCH / 256, 256>>>(1, 8, 2, gum, out);

    dstep_gemm<<<dim3(8, 1), 256>>>(w_hh, Hd1, 8);
    dstep_point<<<64, 128>>>(8, 3, wn[1], bn[1], wop + 8 * HID, bop + 8, Hd0, Cd0, Cd1);
    dsample<<<B_BATCH / 256, 256>>>(2, 64, 3, gum, out);

    dstep_gemm<<<dim3(8, 8), 256>>>(w_hh, Hd0, 64);
    dstep_point<<<512, 128>>>(64, 3, wn[1], bn[1], wop + 8 * HID, bop + 8, Hd1, Cd1, Cd0);
    dsample<<<B_BATCH / 256, 256>>>(3, 512, 3, gum, out);

    materialize<<<2048, 256>>>();

    mega_step<<<NWORK, 256, SMEM_TOTAL>>>(wn[2], wn[3], bn[2], bn[3], wop, bop, gum, out,
                                          mAh[0], mAh[1], mAl[0], mAl[1], mBh, mBl);

    finalize_kernel<<<B_BATCH / 256, 256>>>(bn[3], 5, bop + 24, gum, 7, out);
}